// round 1
// baseline (speedup 1.0000x reference)
#include <cuda_runtime.h>
#include <math.h>

#define D_MODEL 2048
#define N_HEADS 16
#define N_KV 4
#define HEAD_DIM 128
#define B_SZ 2
#define T_SEQ 2048
#define M_ROWS (B_SZ * T_SEQ)          // 4096
#define QDIM (N_HEADS * HEAD_DIM)      // 2048
#define KVDIM (N_KV * HEAD_DIM)        // 512

// ---------------- scratch (no allocations allowed) ----------------
__device__ float g_q[M_ROWS * QDIM];     // 32 MB
__device__ float g_k[M_ROWS * KVDIM];    // 8 MB
__device__ float g_v[M_ROWS * KVDIM];    // 8 MB
__device__ float g_att[M_ROWS * QDIM];   // 32 MB

// ---------------- tiled SGEMM: C[M,N] = A[M,K] @ B[K,N], row-major ----------------
// BM=BN=64, BK=16, 256 threads, 4x4 register tile per thread.
#define BM 64
#define BN 64
#define BK 16

__global__ void sgemm_kernel(const float* __restrict__ A, const float* __restrict__ B,
                             float* __restrict__ C, int M, int N, int K) {
    __shared__ float As[BK][BM + 1];   // transposed A tile, padded
    __shared__ float Bs[BK][BN];

    const int bm = blockIdx.y * BM;
    const int bn = blockIdx.x * BN;
    const int tid = threadIdx.x;
    const int ty = tid >> 4;          // 0..15
    const int tx = tid & 15;          // 0..15

    // load indices
    const int ar  = tid >> 2;         // 0..63 (A tile row)
    const int ac4 = (tid & 3) * 4;    // 0,4,8,12 (A tile col, float4)
    const int br  = tid >> 4;         // 0..15 (B tile row)
    const int bc4 = (tid & 15) * 4;   // 0..60 (B tile col, float4)

    float acc[4][4];
#pragma unroll
    for (int i = 0; i < 4; i++)
#pragma unroll
        for (int j = 0; j < 4; j++) acc[i][j] = 0.f;

    for (int k0 = 0; k0 < K; k0 += BK) {
        float4 av = *(const float4*)&A[(size_t)(bm + ar) * K + k0 + ac4];
        float4 bv = *(const float4*)&B[(size_t)(k0 + br) * N + bn + bc4];
        __syncthreads();
        As[ac4 + 0][ar] = av.x;
        As[ac4 + 1][ar] = av.y;
        As[ac4 + 2][ar] = av.z;
        As[ac4 + 3][ar] = av.w;
        *(float4*)&Bs[br][bc4] = bv;
        __syncthreads();

#pragma unroll
        for (int k = 0; k < BK; k++) {
            float a0 = As[k][ty * 4 + 0];
            float a1 = As[k][ty * 4 + 1];
            float a2 = As[k][ty * 4 + 2];
            float a3 = As[k][ty * 4 + 3];
            float4 b4 = *(const float4*)&Bs[k][tx * 4];
            acc[0][0] += a0 * b4.x; acc[0][1] += a0 * b4.y; acc[0][2] += a0 * b4.z; acc[0][3] += a0 * b4.w;
            acc[1][0] += a1 * b4.x; acc[1][1] += a1 * b4.y; acc[1][2] += a1 * b4.z; acc[1][3] += a1 * b4.w;
            acc[2][0] += a2 * b4.x; acc[2][1] += a2 * b4.y; acc[2][2] += a2 * b4.z; acc[2][3] += a2 * b4.w;
            acc[3][0] += a3 * b4.x; acc[3][1] += a3 * b4.y; acc[3][2] += a3 * b4.z; acc[3][3] += a3 * b4.w;
        }
    }

#pragma unroll
    for (int i = 0; i < 4; i++) {
        float* crow = &C[(size_t)(bm + ty * 4 + i) * N + bn + tx * 4];
        crow[0] = acc[i][0];
        crow[1] = acc[i][1];
        crow[2] = acc[i][2];
        crow[3] = acc[i][3];
    }
}

// ---------------- RoPE (in place) ----------------
// X layout: [B*T, nh*128]; pair (i, i+64) rotated by angle t * 10000^{-2i/128}
__global__ void rope_kernel(float* __restrict__ X, int nh, int total) {
    int gid = blockIdx.x * blockDim.x + threadIdx.x;
    if (gid >= total) return;
    int i = gid & 63;
    int hh = (gid >> 6) % nh;
    int bt = gid / (64 * nh);          // b*T + t
    int t = bt % T_SEQ;

    float inv = powf(10000.0f, -((float)(2 * i)) / 128.0f);
    float ang = (float)t * inv;
    float s, c;
    sincosf(ang, &s, &c);

    size_t base = (size_t)bt * ((size_t)nh * 128) + (size_t)hh * 128 + i;
    float x1 = X[base];
    float x2 = X[base + 64];
    X[base] = x1 * c - x2 * s;
    X[base + 64] = x2 * c + x1 * s;
}

// ---------------- flash attention (fp32, online softmax) ----------------
// grid: (T/64, H, B), 256 threads.
// Q,att layout: [B*T, 16*128]; K,V layout: [B*T, 4*128]
#define QPAD 132   // 128 + 4 pad (bank spread)
#define SPAD 65

__global__ void attn_kernel(const float* __restrict__ Q, const float* __restrict__ K,
                            const float* __restrict__ V, float* __restrict__ O) {
    const int qt = blockIdx.x;
    const int h = blockIdx.y;
    const int b = blockIdx.z;
    const int kvh = h >> 2;

    extern __shared__ float sm[];
    float* Qs = sm;                    // 64 * 132
    float* Ks = Qs + 64 * QPAD;        // 64 * 132
    float* Vs = Ks + 64 * QPAD;        // 64 * 132
    float* Ss = Vs + 64 * QPAD;        // 64 * 65
    float* mrow = Ss + 64 * SPAD;      // 64
    float* lrow = mrow + 64;           // 64
    float* arow = lrow + 64;           // 64

    const int tid = threadIdx.x;
    const int ty = tid >> 4;
    const int tx = tid & 15;
    const float scale = 0.08838834764831845f;  // 1/sqrt(128)

    const int qrow0 = b * T_SEQ + qt * 64;

    // load Q tile (scaled)
    for (int idx = tid; idx < 64 * 128; idx += 256) {
        int r = idx >> 7, d = idx & 127;
        Qs[r * QPAD + d] = Q[(size_t)(qrow0 + r) * QDIM + h * HEAD_DIM + d] * scale;
    }
    if (tid < 64) {
        mrow[tid] = -INFINITY;
        lrow[tid] = 0.f;
    }

    float o[4][8];
#pragma unroll
    for (int i = 0; i < 4; i++)
#pragma unroll
        for (int j = 0; j < 8; j++) o[i][j] = 0.f;

    for (int kt = 0; kt <= qt; kt++) {
        __syncthreads();   // protect Ks/Vs/Ss reuse from previous iteration
        const int krow0 = b * T_SEQ + kt * 64;
        for (int idx = tid; idx < 64 * 128; idx += 256) {
            int r = idx >> 7, d = idx & 127;
            size_t g = (size_t)(krow0 + r) * KVDIM + kvh * HEAD_DIM + d;
            Ks[r * QPAD + d] = K[g];
            Vs[r * QPAD + d] = V[g];
        }
        __syncthreads();

        // S = Q K^T  (each thread 4x4)
        float sacc[4][4];
#pragma unroll
        for (int i = 0; i < 4; i++)
#pragma unroll
            for (int j = 0; j < 4; j++) sacc[i][j] = 0.f;

        const float* qp = &Qs[(ty * 4) * QPAD];
        const float* kp = &Ks[(tx * 4) * QPAD];
#pragma unroll 4
        for (int d = 0; d < 128; d++) {
            float a0 = qp[d], a1 = qp[QPAD + d], a2 = qp[2 * QPAD + d], a3 = qp[3 * QPAD + d];
            float b0 = kp[d], b1 = kp[QPAD + d], b2 = kp[2 * QPAD + d], b3 = kp[3 * QPAD + d];
            sacc[0][0] += a0 * b0; sacc[0][1] += a0 * b1; sacc[0][2] += a0 * b2; sacc[0][3] += a0 * b3;
            sacc[1][0] += a1 * b0; sacc[1][1] += a1 * b1; sacc[1][2] += a1 * b2; sacc[1][3] += a1 * b3;
            sacc[2][0] += a2 * b0; sacc[2][1] += a2 * b1; sacc[2][2] += a2 * b2; sacc[2][3] += a2 * b3;
            sacc[3][0] += a3 * b0; sacc[3][1] += a3 * b1; sacc[3][2] += a3 * b2; sacc[3][3] += a3 * b3;
        }
#pragma unroll
        for (int i = 0; i < 4; i++)
#pragma unroll
            for (int j = 0; j < 4; j++)
                Ss[(ty * 4 + i) * SPAD + tx * 4 + j] = sacc[i][j];
        __syncthreads();

        // online softmax row pass (one thread per row)
        if (tid < 64) {
            int r = tid;
            int cmax = (kt == qt) ? (r + 1) : 64;   // causal mask inside diagonal tile
            float mo = mrow[r];
            float mn = mo;
            for (int c = 0; c < cmax; c++) mn = fmaxf(mn, Ss[r * SPAD + c]);
            float alpha = (mo == -INFINITY) ? 0.f : __expf(mo - mn);
            float lsum = 0.f;
            for (int c = 0; c < 64; c++) {
                float p = (c < cmax) ? __expf(Ss[r * SPAD + c] - mn) : 0.f;
                Ss[r * SPAD + c] = p;
                lsum += p;
            }
            mrow[r] = mn;
            lrow[r] = lrow[r] * alpha + lsum;
            arow[r] = alpha;
        }
        __syncthreads();

        // O = O*alpha + P @ V   (each thread 4 rows x 8 cols)
        float al[4];
#pragma unroll
        for (int i = 0; i < 4; i++) al[i] = arow[ty * 4 + i];
#pragma unroll
        for (int i = 0; i < 4; i++)
#pragma unroll
            for (int j = 0; j < 8; j++) o[i][j] *= al[i];

        const float* pp = &Ss[(ty * 4) * SPAD];
        const float* vp = &Vs[tx * 8];
#pragma unroll 4
        for (int kk = 0; kk < 64; kk++) {
            float p0 = pp[kk], p1 = pp[SPAD + kk], p2 = pp[2 * SPAD + kk], p3 = pp[3 * SPAD + kk];
#pragma unroll
            for (int j = 0; j < 8; j++) {
                float vv = vp[kk * QPAD + j];
                o[0][j] += p0 * vv;
                o[1][j] += p1 * vv;
                o[2][j] += p2 * vv;
                o[3][j] += p3 * vv;
            }
        }
    }

    // epilogue: normalize and store
    float linv[4];
#pragma unroll
    for (int i = 0; i < 4; i++) linv[i] = 1.f / lrow[ty * 4 + i];
#pragma unroll
    for (int i = 0; i < 4; i++) {
        float* orow = &O[(size_t)(qrow0 + ty * 4 + i) * QDIM + h * HEAD_DIM + tx * 8];
#pragma unroll
        for (int j = 0; j < 8; j++) orow[j] = o[i][j] * linv[i];
    }
}

// ---------------- launch ----------------
extern "C" void kernel_launch(void* const* d_in, const int* in_sizes, int n_in,
                              void* d_out, int out_size) {
    const float* x  = (const float*)d_in[0];
    const float* Wq = (const float*)d_in[1];
    const float* Wk = (const float*)d_in[2];
    const float* Wv = (const float*)d_in[3];
    const float* Wo = (const float*)d_in[4];
    float* out = (float*)d_out;

    float *q, *k, *v, *att;
    cudaGetSymbolAddress((void**)&q, g_q);
    cudaGetSymbolAddress((void**)&k, g_k);
    cudaGetSymbolAddress((void**)&v, g_v);
    cudaGetSymbolAddress((void**)&att, g_att);

    // projections
    sgemm_kernel<<<dim3(QDIM / BN, M_ROWS / BM), 256>>>(x, Wq, q, M_ROWS, QDIM, D_MODEL);
    sgemm_kernel<<<dim3(KVDIM / BN, M_ROWS / BM), 256>>>(x, Wk, k, M_ROWS, KVDIM, D_MODEL);
    sgemm_kernel<<<dim3(KVDIM / BN, M_ROWS / BM), 256>>>(x, Wv, v, M_ROWS, KVDIM, D_MODEL);

    // RoPE
    {
        int totq = B_SZ * T_SEQ * N_HEADS * 64;
        int totk = B_SZ * T_SEQ * N_KV * 64;
        rope_kernel<<<(totq + 255) / 256, 256>>>(q, N_HEADS, totq);
        rope_kernel<<<(totk + 255) / 256, 256>>>(k, N_KV, totk);
    }

    // attention
    {
        size_t smem = (size_t)(3 * 64 * QPAD + 64 * SPAD + 3 * 64) * sizeof(float);  // 118784 B
        cudaFuncSetAttribute(attn_kernel, cudaFuncAttributeMaxDynamicSharedMemorySize, (int)smem);
        attn_kernel<<<dim3(T_SEQ / 64, N_HEADS, B_SZ), 256, smem>>>(q, k, v, att);
    }

    // output projection
    sgemm_kernel<<<dim3(QDIM / BN, M_ROWS / BM), 256>>>(att, Wo, out, M_ROWS, QDIM, D_MODEL);
}

// round 2
// speedup vs baseline: 3.5761x; 3.5761x over previous
#include <cuda_runtime.h>
#include <math.h>
#include <stdint.h>

#define D_MODEL 2048
#define N_HEADS 16
#define N_KV 4
#define HEAD_DIM 128
#define B_SZ 2
#define T_SEQ 2048
#define M_ROWS (B_SZ * T_SEQ)          // 4096
#define QDIM (N_HEADS * HEAD_DIM)      // 2048
#define KVDIM (N_KV * HEAD_DIM)        // 512

// ---------------- scratch ----------------
__device__ float g_q[M_ROWS * QDIM];
__device__ float g_k[M_ROWS * KVDIM];
__device__ float g_v[M_ROWS * KVDIM];
__device__ float g_att[M_ROWS * QDIM];

// ---------------- tf32 helpers ----------------
__device__ __forceinline__ uint32_t ftf(float x) {
    uint32_t u;
    asm("cvt.rna.tf32.f32 %0, %1;" : "=r"(u) : "f"(x));
    return u;
}
__device__ __forceinline__ float tfr(float x) { return __uint_as_float(ftf(x)); }
__device__ __forceinline__ uint32_t fu(float x) { return __float_as_uint(x); }

__device__ __forceinline__ void mma8(float* c, uint32_t a0, uint32_t a1, uint32_t a2, uint32_t a3,
                                     uint32_t b0, uint32_t b1) {
    asm volatile(
        "mma.sync.aligned.m16n8k8.row.col.f32.tf32.tf32.f32 "
        "{%0,%1,%2,%3},{%4,%5,%6,%7},{%8,%9},{%0,%1,%2,%3};"
        : "+f"(c[0]), "+f"(c[1]), "+f"(c[2]), "+f"(c[3])
        : "r"(a0), "r"(a1), "r"(a2), "r"(a3), "r"(b0), "r"(b1));
}

// ---------------- GEMM (tf32 tensor core): C[M,N] = A[M,K] @ B[K,N] ----------------
#define GBM 128
#define GBN 128
#define GBK 32
#define AST 36     // A smem stride [m][k]
#define BST 136    // B smem stride [k][n]

__global__ __launch_bounds__(256) void gemm_tf32(const float* __restrict__ A,
                                                 const float* __restrict__ B,
                                                 float* __restrict__ C,
                                                 int M, int N, int K) {
    __shared__ float As[GBM][AST];
    __shared__ float Bs[GBK][BST];

    const int tid = threadIdx.x;
    const int lane = tid & 31, warp = tid >> 5;
    const int wm = warp >> 2, wn = warp & 3;    // 2 x 4 warp grid
    const int g = lane >> 2, tg = lane & 3;
    const int bm = blockIdx.y * GBM, bn = blockIdx.x * GBN;

    float acc[4][4][4];
#pragma unroll
    for (int mt = 0; mt < 4; mt++)
#pragma unroll
        for (int nt = 0; nt < 4; nt++)
#pragma unroll
            for (int r = 0; r < 4; r++) acc[mt][nt][r] = 0.f;

    float4 pa[4], pb[4];
    const int nk = K / GBK;

    // prefetch tile 0
#pragma unroll
    for (int i = 0; i < 4; i++) {
        int r = (tid >> 3) + i * 32, c4 = (tid & 7) << 2;
        pa[i] = *(const float4*)&A[(size_t)(bm + r) * K + c4];
    }
#pragma unroll
    for (int i = 0; i < 4; i++) {
        int r = (tid >> 5) + i * 8, c4 = (tid & 31) << 2;
        pb[i] = *(const float4*)&B[(size_t)r * N + bn + c4];
    }

    for (int kt = 0; kt < nk; kt++) {
        __syncthreads();
#pragma unroll
        for (int i = 0; i < 4; i++) {
            int r = (tid >> 3) + i * 32, c4 = (tid & 7) << 2;
            *(float4*)&As[r][c4] = make_float4(tfr(pa[i].x), tfr(pa[i].y), tfr(pa[i].z), tfr(pa[i].w));
        }
#pragma unroll
        for (int i = 0; i < 4; i++) {
            int r = (tid >> 5) + i * 8, c4 = (tid & 31) << 2;
            *(float4*)&Bs[r][c4] = make_float4(tfr(pb[i].x), tfr(pb[i].y), tfr(pb[i].z), tfr(pb[i].w));
        }
        __syncthreads();

        if (kt + 1 < nk) {
            int k0 = (kt + 1) * GBK;
#pragma unroll
            for (int i = 0; i < 4; i++) {
                int r = (tid >> 3) + i * 32, c4 = (tid & 7) << 2;
                pa[i] = *(const float4*)&A[(size_t)(bm + r) * K + k0 + c4];
            }
#pragma unroll
            for (int i = 0; i < 4; i++) {
                int r = (tid >> 5) + i * 8, c4 = (tid & 31) << 2;
                pb[i] = *(const float4*)&B[(size_t)(k0 + r) * N + bn + c4];
            }
        }

#pragma unroll
        for (int ks = 0; ks < 4; ks++) {
            const int kk = ks * 8;
            uint32_t af[4][4];
#pragma unroll
            for (int mt = 0; mt < 4; mt++) {
                int r0 = wm * 64 + mt * 16 + g;
                af[mt][0] = fu(As[r0][kk + tg]);
                af[mt][1] = fu(As[r0 + 8][kk + tg]);
                af[mt][2] = fu(As[r0][kk + tg + 4]);
                af[mt][3] = fu(As[r0 + 8][kk + tg + 4]);
            }
            uint32_t bf[4][2];
#pragma unroll
            for (int nt = 0; nt < 4; nt++) {
                int c0 = wn * 32 + nt * 8 + g;
                bf[nt][0] = fu(Bs[kk + tg][c0]);
                bf[nt][1] = fu(Bs[kk + tg + 4][c0]);
            }
#pragma unroll
            for (int mt = 0; mt < 4; mt++)
#pragma unroll
                for (int nt = 0; nt < 4; nt++)
                    mma8(acc[mt][nt], af[mt][0], af[mt][1], af[mt][2], af[mt][3], bf[nt][0], bf[nt][1]);
        }
    }

#pragma unroll
    for (int mt = 0; mt < 4; mt++)
#pragma unroll
        for (int nt = 0; nt < 4; nt++) {
            int r = bm + wm * 64 + mt * 16 + g;
            int c = bn + wn * 32 + nt * 8 + 2 * tg;
            *(float2*)&C[(size_t)r * N + c] = make_float2(acc[mt][nt][0], acc[mt][nt][1]);
            *(float2*)&C[(size_t)(r + 8) * N + c] = make_float2(acc[mt][nt][2], acc[mt][nt][3]);
        }
}

// ---------------- RoPE (in place) ----------------
__global__ void rope_kernel(float* __restrict__ X, int nh, int total) {
    int gid = blockIdx.x * blockDim.x + threadIdx.x;
    if (gid >= total) return;
    int i = gid & 63;
    int hh = (gid >> 6) % nh;
    int bt = gid / (64 * nh);
    int t = bt % T_SEQ;

    float inv = powf(10000.0f, -((float)(2 * i)) / 128.0f);
    float ang = (float)t * inv;
    float s, c;
    sincosf(ang, &s, &c);

    size_t base = (size_t)bt * ((size_t)nh * 128) + (size_t)hh * 128 + i;
    float x1 = X[base];
    float x2 = X[base + 64];
    X[base] = x1 * c - x2 * s;
    X[base + 64] = x2 * c + x1 * s;
}

// ---------------- flash attention with tf32 mma ----------------
#define QST 132
#define KST 72
#define VST 136
#define SST 68

__global__ __launch_bounds__(256) void attn_tf32(const float* __restrict__ Q,
                                                 const float* __restrict__ K,
                                                 const float* __restrict__ V,
                                                 float* __restrict__ O) {
    extern __shared__ float sm[];
    float* Qs = sm;                      // 64*132
    float* Kt = Qs + 64 * QST;           // 128*72 (transposed: [d][n])
    float* Vs = Kt + 128 * KST;          // 64*136
    float* Ss = Vs + 64 * VST;           // 64*68
    float* mrow = Ss + 64 * SST;
    float* lrow = mrow + 64;
    float* arow = lrow + 64;

    const int qt = blockIdx.x, h = blockIdx.y, b = blockIdx.z;
    const int kvh = h >> 2;
    const int tid = threadIdx.x, lane = tid & 31, warp = tid >> 5;
    const int g = lane >> 2, tg = lane & 3;
    const int wm = warp >> 1, wn = warp & 1;    // 4 x 2 warp grid
    const int qrow0 = b * T_SEQ + qt * 64;
    const float scale = 0.08838834764831845f;
    const int r0 = wm * 16 + g;

    // load Q tile (scaled, tf32-rounded)
#pragma unroll
    for (int i = 0; i < 8; i++) {
        int f = tid + i * 256;
        int r = f >> 5, c4 = (f & 31) << 2;
        float4 v = *(const float4*)&Q[(size_t)(qrow0 + r) * QDIM + h * HEAD_DIM + c4];
        *(float4*)&Qs[r * QST + c4] =
            make_float4(tfr(v.x * scale), tfr(v.y * scale), tfr(v.z * scale), tfr(v.w * scale));
    }
    if (tid < 64) { mrow[tid] = -INFINITY; lrow[tid] = 0.f; }

    float o[8][4];
#pragma unroll
    for (int nt = 0; nt < 8; nt++)
#pragma unroll
        for (int r = 0; r < 4; r++) o[nt][r] = 0.f;

    for (int kt = 0; kt <= qt; kt++) {
        __syncthreads();
        const int kr0 = b * T_SEQ + kt * 64;
#pragma unroll
        for (int i = 0; i < 8; i++) {
            int f = tid + i * 256;
            // K transposed scatter
            int n = f & 63, d4 = (f >> 6) << 2;
            float4 kv = *(const float4*)&K[(size_t)(kr0 + n) * KVDIM + kvh * HEAD_DIM + d4];
            Kt[(d4 + 0) * KST + n] = tfr(kv.x);
            Kt[(d4 + 1) * KST + n] = tfr(kv.y);
            Kt[(d4 + 2) * KST + n] = tfr(kv.z);
            Kt[(d4 + 3) * KST + n] = tfr(kv.w);
            // V natural
            int r = f >> 5, c4 = (f & 31) << 2;
            float4 vv = *(const float4*)&V[(size_t)(kr0 + r) * KVDIM + kvh * HEAD_DIM + c4];
            *(float4*)&Vs[r * VST + c4] = make_float4(tfr(vv.x), tfr(vv.y), tfr(vv.z), tfr(vv.w));
        }
        __syncthreads();

        // S = Q K^T  (warp tile 16x32)
        float sc[4][4];
#pragma unroll
        for (int nt = 0; nt < 4; nt++)
#pragma unroll
            for (int r = 0; r < 4; r++) sc[nt][r] = 0.f;
#pragma unroll
        for (int ks = 0; ks < 16; ks++) {
            const int kk = ks * 8;
            uint32_t a0 = fu(Qs[r0 * QST + kk + tg]);
            uint32_t a1 = fu(Qs[(r0 + 8) * QST + kk + tg]);
            uint32_t a2 = fu(Qs[r0 * QST + kk + tg + 4]);
            uint32_t a3 = fu(Qs[(r0 + 8) * QST + kk + tg + 4]);
#pragma unroll
            for (int nt = 0; nt < 4; nt++) {
                int c0 = wn * 32 + nt * 8 + g;
                uint32_t b0 = fu(Kt[(kk + tg) * KST + c0]);
                uint32_t b1 = fu(Kt[(kk + tg + 4) * KST + c0]);
                mma8(sc[nt], a0, a1, a2, a3, b0, b1);
            }
        }
#pragma unroll
        for (int nt = 0; nt < 4; nt++) {
            int c = wn * 32 + nt * 8 + 2 * tg;
            *(float2*)&Ss[r0 * SST + c] = make_float2(sc[nt][0], sc[nt][1]);
            *(float2*)&Ss[(r0 + 8) * SST + c] = make_float2(sc[nt][2], sc[nt][3]);
        }
        __syncthreads();

        // online softmax: 4 threads per row
        {
            int r = tid >> 2, qd = tid & 3;
            int limit = (kt == qt) ? r : 63;
            float* srow = &Ss[r * SST + qd * 16];
            float mloc = -INFINITY;
#pragma unroll
            for (int c = 0; c < 16; c++) {
                int cc = qd * 16 + c;
                if (cc <= limit) mloc = fmaxf(mloc, srow[c]);
            }
            mloc = fmaxf(mloc, __shfl_xor_sync(0xffffffffu, mloc, 1));
            mloc = fmaxf(mloc, __shfl_xor_sync(0xffffffffu, mloc, 2));
            float mold = mrow[r];
            float mn = fmaxf(mold, mloc);
            float lsum = 0.f;
#pragma unroll
            for (int c = 0; c < 16; c++) {
                int cc = qd * 16 + c;
                float p = (cc <= limit) ? __expf(srow[c] - mn) : 0.f;
                srow[c] = p;
                lsum += p;
            }
            lsum += __shfl_xor_sync(0xffffffffu, lsum, 1);
            lsum += __shfl_xor_sync(0xffffffffu, lsum, 2);
            if (qd == 0) {
                float al = __expf(mold - mn);
                arow[r] = al;
                lrow[r] = lrow[r] * al + lsum;
                mrow[r] = mn;
            }
        }
        __syncthreads();

        // rescale O, then O += P @ V  (warp tile 16x64)
        float alo = arow[r0], ahi = arow[r0 + 8];
#pragma unroll
        for (int nt = 0; nt < 8; nt++) {
            o[nt][0] *= alo; o[nt][1] *= alo;
            o[nt][2] *= ahi; o[nt][3] *= ahi;
        }
#pragma unroll
        for (int ks = 0; ks < 8; ks++) {
            const int kk = ks * 8;
            uint32_t a0 = ftf(Ss[r0 * SST + kk + tg]);
            uint32_t a1 = ftf(Ss[(r0 + 8) * SST + kk + tg]);
            uint32_t a2 = ftf(Ss[r0 * SST + kk + tg + 4]);
            uint32_t a3 = ftf(Ss[(r0 + 8) * SST + kk + tg + 4]);
#pragma unroll
            for (int nt = 0; nt < 8; nt++) {
                int c0 = wn * 64 + nt * 8 + g;
                uint32_t b0 = fu(Vs[(kk + tg) * VST + c0]);
                uint32_t b1 = fu(Vs[(kk + tg + 4) * VST + c0]);
                mma8(o[nt], a0, a1, a2, a3, b0, b1);
            }
        }
    }

    // epilogue
    float li = 1.f / lrow[r0], lh2 = 1.f / lrow[r0 + 8];
#pragma unroll
    for (int nt = 0; nt < 8; nt++) {
        int c = h * HEAD_DIM + wn * 64 + nt * 8 + 2 * tg;
        *(float2*)&O[(size_t)(qrow0 + r0) * QDIM + c] = make_float2(o[nt][0] * li, o[nt][1] * li);
        *(float2*)&O[(size_t)(qrow0 + r0 + 8) * QDIM + c] = make_float2(o[nt][2] * lh2, o[nt][3] * lh2);
    }
}

// ---------------- launch ----------------
extern "C" void kernel_launch(void* const* d_in, const int* in_sizes, int n_in,
                              void* d_out, int out_size) {
    const float* x  = (const float*)d_in[0];
    const float* Wq = (const float*)d_in[1];
    const float* Wk = (const float*)d_in[2];
    const float* Wv = (const float*)d_in[3];
    const float* Wo = (const float*)d_in[4];
    float* out = (float*)d_out;

    float *q, *k, *v, *att;
    cudaGetSymbolAddress((void**)&q, g_q);
    cudaGetSymbolAddress((void**)&k, g_k);
    cudaGetSymbolAddress((void**)&v, g_v);
    cudaGetSymbolAddress((void**)&att, g_att);

    gemm_tf32<<<dim3(QDIM / GBN, M_ROWS / GBM), 256>>>(x, Wq, q, M_ROWS, QDIM, D_MODEL);
    gemm_tf32<<<dim3(KVDIM / GBN, M_ROWS / GBM), 256>>>(x, Wk, k, M_ROWS, KVDIM, D_MODEL);
    gemm_tf32<<<dim3(KVDIM / GBN, M_ROWS / GBM), 256>>>(x, Wv, v, M_ROWS, KVDIM, D_MODEL);

    {
        int totq = B_SZ * T_SEQ * N_HEADS * 64;
        int totk = B_SZ * T_SEQ * N_KV * 64;
        rope_kernel<<<(totq + 255) / 256, 256>>>(q, N_HEADS, totq);
        rope_kernel<<<(totk + 255) / 256, 256>>>(k, N_KV, totk);
    }

    {
        size_t smem = (size_t)(64 * QST + 128 * KST + 64 * VST + 64 * SST + 192) * sizeof(float);
        cudaFuncSetAttribute(attn_tf32, cudaFuncAttributeMaxDynamicSharedMemorySize, (int)smem);
        attn_tf32<<<dim3(T_SEQ / 64, N_HEADS, B_SZ), 256, smem>>>(q, k, v, att);
    }

    gemm_tf32<<<dim3(QDIM / GBN, M_ROWS / GBM), 256>>>(att, Wo, out, M_ROWS, QDIM, D_MODEL);
}

// round 5
// speedup vs baseline: 3.8277x; 1.0704x over previous
#include <cuda_runtime.h>
#include <math.h>
#include <stdint.h>

#define D_MODEL 2048
#define N_HEADS 16
#define N_KV 4
#define HEAD_DIM 128
#define B_SZ 2
#define T_SEQ 2048
#define M_ROWS (B_SZ * T_SEQ)          // 4096
#define QDIM (N_HEADS * HEAD_DIM)      // 2048
#define KVDIM (N_KV * HEAD_DIM)        // 512
#define QKVD (QDIM + 2 * KVDIM)        // 3072

// ---------------- scratch ----------------
__device__ float g_qkv[M_ROWS * QKVD];      // fused q|k|v, row stride 3072
__device__ float g_att[M_ROWS * QDIM];
__device__ float g_xr[M_ROWS * D_MODEL];    // rna-rounded x
__device__ float g_wc[D_MODEL * QKVD];      // concat(Wq|Wk|Wv), rounded
__device__ float g_wor[QDIM * D_MODEL];     // rounded Wo

// ---------------- helpers ----------------
__device__ __forceinline__ uint32_t ftf(float x) {
    uint32_t u;
    asm("cvt.rna.tf32.f32 %0, %1;" : "=r"(u) : "f"(x));
    return u;
}
__device__ __forceinline__ float tfr(float x) { return __uint_as_float(ftf(x)); }
__device__ __forceinline__ uint32_t fu(float x) { return __float_as_uint(x); }

__device__ __forceinline__ uint32_t s2u(const void* p) {
    uint32_t a;
    asm("{ .reg .u64 t; cvta.to.shared.u64 t, %1; cvt.u32.u64 %0, t; }" : "=r"(a) : "l"(p));
    return a;
}
__device__ __forceinline__ void cpa16(uint32_t dst, const void* src) {
    asm volatile("cp.async.cg.shared.global [%0], [%1], 16;" :: "r"(dst), "l"(src));
}
__device__ __forceinline__ void cpa_commit() { asm volatile("cp.async.commit_group;" ::: "memory"); }
template <int N> __device__ __forceinline__ void cpa_wait() {
    asm volatile("cp.async.wait_group %0;" :: "n"(N) : "memory");
}

__device__ __forceinline__ void mma8(float* c, uint32_t a0, uint32_t a1, uint32_t a2, uint32_t a3,
                                     uint32_t b0, uint32_t b1) {
    asm volatile(
        "mma.sync.aligned.m16n8k8.row.col.f32.tf32.tf32.f32 "
        "{%0,%1,%2,%3},{%4,%5,%6,%7},{%8,%9},{%0,%1,%2,%3};"
        : "+f"(c[0]), "+f"(c[1]), "+f"(c[2]), "+f"(c[3])
        : "r"(a0), "r"(a1), "r"(a2), "r"(a3), "r"(b0), "r"(b1));
}

// ---------------- GEMM (tf32 mma.sync, cp.async 3-stage): C = A @ B ----------------
#define GBM 128
#define GBN 128
#define GBK 32
#define AST 36
#define BST 136
#define ASTG (128 * AST)
#define BSTG (32 * BST)

__global__ __launch_bounds__(256) void gemm_tf32(const float* __restrict__ A,
                                                 const float* __restrict__ B,
                                                 float* __restrict__ C,
                                                 int M, int N, int K) {
    extern __shared__ float sm[];
    float* As = sm;                // 3 * 128*36
    float* Bs = sm + 3 * ASTG;     // 3 * 32*136
    const uint32_t asb = s2u(As), bsb = s2u(Bs);

    const int tid = threadIdx.x;
    const int lane = tid & 31, warp = tid >> 5;
    const int wm = warp >> 2, wn = warp & 3;    // 2 x 4 warp grid
    const int g = lane >> 2, tg = lane & 3;
    const int bm = blockIdx.y * GBM, bn = blockIdx.x * GBN;
    const int NK = K / GBK;

    float acc[4][4][4];
#pragma unroll
    for (int mt = 0; mt < 4; mt++)
#pragma unroll
        for (int nt = 0; nt < 4; nt++)
#pragma unroll
            for (int r = 0; r < 4; r++) acc[mt][nt][r] = 0.f;

    auto fill = [&](int kt) {
        const int s = kt - (kt / 3) * 3;
        const int k0 = kt * GBK;
#pragma unroll
        for (int i = 0; i < 4; i++) {         // A: 128 rows x 8 chunks = 1024
            int ch = tid + i * 256;
            int r = ch >> 3, j = ch & 7;
            cpa16(asb + (uint32_t)(s * ASTG + r * AST + 4 * j) * 4,
                  A + (size_t)(bm + r) * K + k0 + 4 * j);
        }
#pragma unroll
        for (int i = 0; i < 4; i++) {         // B: 32 rows x 32 chunks = 1024
            int ch = tid + i * 256;
            int r = ch >> 5, j = ch & 31;
            cpa16(bsb + (uint32_t)(s * BSTG + r * BST + 4 * j) * 4,
                  B + (size_t)(k0 + r) * N + bn + 4 * j);
        }
    };

    fill(0); cpa_commit();
    fill(1); cpa_commit();

    for (int kt = 0; kt < NK; kt++) {
        __syncthreads();
        if (kt + 2 < NK) fill(kt + 2);
        cpa_commit();
        cpa_wait<2>();
        __syncthreads();

        const int s = kt - (kt / 3) * 3;
        const float* as = As + s * ASTG;
        const float* bs = Bs + s * BSTG;
#pragma unroll
        for (int ks = 0; ks < 4; ks++) {
            const int kk = ks * 8;
            uint32_t af[4][4];
#pragma unroll
            for (int mt = 0; mt < 4; mt++) {
                int r0 = wm * 64 + mt * 16 + g;
                af[mt][0] = fu(as[r0 * AST + kk + tg]);
                af[mt][1] = fu(as[(r0 + 8) * AST + kk + tg]);
                af[mt][2] = fu(as[r0 * AST + kk + tg + 4]);
                af[mt][3] = fu(as[(r0 + 8) * AST + kk + tg + 4]);
            }
            uint32_t bf[4][2];
#pragma unroll
            for (int nt = 0; nt < 4; nt++) {
                int c0 = wn * 32 + nt * 8 + g;
                bf[nt][0] = fu(bs[(kk + tg) * BST + c0]);
                bf[nt][1] = fu(bs[(kk + tg + 4) * BST + c0]);
            }
#pragma unroll
            for (int mt = 0; mt < 4; mt++)
#pragma unroll
                for (int nt = 0; nt < 4; nt++)
                    mma8(acc[mt][nt], af[mt][0], af[mt][1], af[mt][2], af[mt][3], bf[nt][0], bf[nt][1]);
        }
    }

#pragma unroll
    for (int mt = 0; mt < 4; mt++)
#pragma unroll
        for (int nt = 0; nt < 4; nt++) {
            int r = bm + wm * 64 + mt * 16 + g;
            int c = bn + wn * 32 + nt * 8 + 2 * tg;
            *(float2*)&C[(size_t)r * N + c] = make_float2(acc[mt][nt][0], acc[mt][nt][1]);
            *(float2*)&C[(size_t)(r + 8) * N + c] = make_float2(acc[mt][nt][2], acc[mt][nt][3]);
        }
}

// ---------------- prep kernels ----------------
__global__ void round_rna(const float4* __restrict__ in, float4* __restrict__ out, int n4) {
    int i = blockIdx.x * blockDim.x + threadIdx.x;
    if (i < n4) {
        float4 v = in[i];
        out[i] = make_float4(tfr(v.x), tfr(v.y), tfr(v.z), tfr(v.w));
    }
}

// in-place rna rounding of the V panel (cols 2560..3071 of qkv)
__global__ void round_v(float* __restrict__ qkv) {
    int idx = blockIdx.x * blockDim.x + threadIdx.x;     // per float4, M_ROWS*KVDIM/4 total
    int row = idx >> 7;                                  // 128 float4 per row-panel
    int col = (idx & 127) << 2;
    float* p = qkv + (size_t)row * QKVD + 2560 + col;
    float4 v = *(float4*)p;
    *(float4*)p = make_float4(tfr(v.x), tfr(v.y), tfr(v.z), tfr(v.w));
}

// concat Wq|Wk|Wv along N into [2048][3072], rounded
__global__ void concat_w(const float* __restrict__ Wq, const float* __restrict__ Wk,
                         const float* __restrict__ Wv, float* __restrict__ out) {
    int idx = blockIdx.x * blockDim.x + threadIdx.x;        // per float4
    const int n4row = QKVD / 4;
    int k = idx / n4row;
    int n = (idx - k * n4row) * 4;
    const float* src;
    int c;
    if (n < QDIM)      { src = Wq + (size_t)k * QDIM;  c = n; }
    else if (n < 2560) { src = Wk + (size_t)k * KVDIM; c = n - QDIM; }
    else               { src = Wv + (size_t)k * KVDIM; c = n - 2560; }
    float4 v = *(const float4*)(src + c);
    *(float4*)(out + (size_t)k * QKVD + n) = make_float4(tfr(v.x), tfr(v.y), tfr(v.z), tfr(v.w));
}

// ---------------- RoPE (in place, row stride QKVD, rounded output) ----------------
__global__ void rope_kernel(float* __restrict__ X, int nh, int total) {
    int gid = blockIdx.x * blockDim.x + threadIdx.x;
    if (gid >= total) return;
    int i = gid & 63;
    int hh = (gid >> 6) % nh;
    int bt = gid / (64 * nh);
    int t = bt % T_SEQ;

    float inv = powf(10000.0f, -((float)(2 * i)) / 128.0f);
    float ang = (float)t * inv;
    float s, c;
    sincosf(ang, &s, &c);

    size_t base = (size_t)bt * QKVD + (size_t)hh * 128 + i;
    float x1 = X[base];
    float x2 = X[base + 64];
    X[base] = tfr(x1 * c - x2 * s);
    X[base + 64] = tfr(x2 * c + x1 * s);
}

// ---------------- flash attention, cp.async double-buffered K/V ----------------
#define QST 132
#define KST 132
#define VST 136
#define SST 68
#define KBUF (64 * KST)
#define VBUF (64 * VST)

__global__ __launch_bounds__(256) void attn_tf32(const float* __restrict__ QKV,
                                                 float* __restrict__ O) {
    extern __shared__ float sm[];
    float* Qs = sm;                      // 64*132
    float* Ks = Qs + 64 * QST;           // 2 * 64*132   natural [n][d]
    float* Vs = Ks + 2 * KBUF;           // 2 * 64*136   natural [n][d]
    float* Ss = Vs + 2 * VBUF;           // 64*68
    float* mrow = Ss + 64 * SST;
    float* lrow = mrow + 64;
    float* arow = lrow + 64;
    const uint32_t qsb = s2u(Qs), ksb = s2u(Ks), vsb = s2u(Vs);

    const int qt = blockIdx.x, h = blockIdx.y, b = blockIdx.z;
    const int kvh = h >> 2;
    const int tid = threadIdx.x, lane = tid & 31, warp = tid >> 5;
    const int g = lane >> 2, tg = lane & 3;
    const int wm = warp >> 1, wn = warp & 1;    // 4 x 2 warp grid
    const int qrow0 = b * T_SEQ + qt * 64;
    const float scale = 0.08838834764831845f;   // 1/sqrt(128)
    const int r0 = wm * 16 + g;

    const float* Qg = QKV + (size_t)h * 128;
    const float* Kg = QKV + QDIM + (size_t)kvh * 128;
    const float* Vg = QKV + 2560 + (size_t)kvh * 128;

    // 64 rows x 32 float4-chunks = 2048 chunks per tensor
    auto fill_kv = [&](int kt) {
        const int s = kt & 1;
        const int kr0 = b * T_SEQ + kt * 64;
#pragma unroll
        for (int i = 0; i < 8; i++) {
            int ch = tid + i * 256;
            int r = ch >> 5, j = ch & 31;
            cpa16(ksb + (uint32_t)(s * KBUF + r * KST + 4 * j) * 4,
                  Kg + (size_t)(kr0 + r) * QKVD + 4 * j);
            cpa16(vsb + (uint32_t)(s * VBUF + r * VST + 4 * j) * 4,
                  Vg + (size_t)(kr0 + r) * QKVD + 4 * j);
        }
    };

    // Q tile + first K/V tile
#pragma unroll
    for (int i = 0; i < 8; i++) {
        int ch = tid + i * 256;
        int r = ch >> 5, j = ch & 31;
        cpa16(qsb + (uint32_t)(r * QST + 4 * j) * 4, Qg + (size_t)(qrow0 + r) * QKVD + 4 * j);
    }
    fill_kv(0);
    cpa_commit();

    if (tid < 64) { mrow[tid] = -INFINITY; lrow[tid] = 0.f; }

    float o[8][4];
#pragma unroll
    for (int nt = 0; nt < 8; nt++)
#pragma unroll
        for (int r = 0; r < 4; r++) o[nt][r] = 0.f;

    for (int kt = 0; kt <= qt; kt++) {
        __syncthreads();                 // all warps done with buffer being overwritten
        if (kt < qt) fill_kv(kt + 1);
        cpa_commit();
        cpa_wait<1>();
        __syncthreads();

        const int s = kt & 1;
        const float* ks = Ks + s * KBUF;
        const float* vs = Vs + s * VBUF;

        // S = Q K^T  (warp tile 16x32); K read natural [n][d] as col-major B
        float sc[4][4];
#pragma unroll
        for (int nt = 0; nt < 4; nt++)
#pragma unroll
            for (int r = 0; r < 4; r++) sc[nt][r] = 0.f;
#pragma unroll
        for (int kss = 0; kss < 16; kss++) {
            const int kk = kss * 8;
            uint32_t a0 = fu(Qs[r0 * QST + kk + tg]);
            uint32_t a1 = fu(Qs[(r0 + 8) * QST + kk + tg]);
            uint32_t a2 = fu(Qs[r0 * QST + kk + tg + 4]);
            uint32_t a3 = fu(Qs[(r0 + 8) * QST + kk + tg + 4]);
#pragma unroll
            for (int nt = 0; nt < 4; nt++) {
                int c0 = wn * 32 + nt * 8 + g;
                uint32_t b0 = fu(ks[c0 * KST + kk + tg]);
                uint32_t b1 = fu(ks[c0 * KST + kk + tg + 4]);
                mma8(sc[nt], a0, a1, a2, a3, b0, b1);
            }
        }
#pragma unroll
        for (int nt = 0; nt < 4; nt++) {
            int c = wn * 32 + nt * 8 + 2 * tg;
            *(float2*)&Ss[r0 * SST + c] = make_float2(sc[nt][0], sc[nt][1]);
            *(float2*)&Ss[(r0 + 8) * SST + c] = make_float2(sc[nt][2], sc[nt][3]);
        }
        __syncthreads();

        // online softmax (scale folded into exp), 4 threads per row
        {
            int r = tid >> 2, qd = tid & 3;
            int limit = (kt == qt) ? r : 63;
            float* srow = &Ss[r * SST + qd * 16];
            float mloc = -INFINITY;
#pragma unroll
            for (int c = 0; c < 16; c++) {
                int cc = qd * 16 + c;
                if (cc <= limit) mloc = fmaxf(mloc, srow[c]);
            }
            mloc = fmaxf(mloc, __shfl_xor_sync(0xffffffffu, mloc, 1));
            mloc = fmaxf(mloc, __shfl_xor_sync(0xffffffffu, mloc, 2));
            float mold = mrow[r];
            float mn = fmaxf(mold, mloc);
            float lsum = 0.f;
#pragma unroll
            for (int c = 0; c < 16; c++) {
                int cc = qd * 16 + c;
                float p = (cc <= limit) ? __expf((srow[c] - mn) * scale) : 0.f;
                srow[c] = p;
                lsum += p;
            }
            lsum += __shfl_xor_sync(0xffffffffu, lsum, 1);
            lsum += __shfl_xor_sync(0xffffffffu, lsum, 2);
            if (qd == 0) {
                float al = __expf((mold - mn) * scale);
                arow[r] = al;
                lrow[r] = lrow[r] * al + lsum;
                mrow[r] = mn;
            }
        }
        __syncthreads();

        // O = O*alpha + P @ V  (warp tile 16x64)
        float alo = arow[r0], ahi = arow[r0 + 8];
#pragma unroll
        for (int nt = 0; nt < 8; nt++) {
            o[nt][0] *= alo; o[nt][1] *= alo;
            o[nt][2] *= ahi; o[nt][3] *= ahi;
        }
#pragma unroll
        for (int kss = 0; kss < 8; kss++) {
            const int kk = kss * 8;
            uint32_t a0 = ftf(Ss[r0 * SST + kk + tg]);
            uint32_t a1 = ftf(Ss[(r0 + 8) * SST + kk + tg]);
            uint32_t a2 = ftf(Ss[r0 * SST + kk + tg + 4]);
            uint32_t a3 = ftf(Ss[(r0 + 8) * SST + kk + tg + 4]);
#pragma unroll
            for (int nt = 0; nt < 8; nt++) {
                int c0 = wn * 64 + nt * 8 + g;
                uint32_t b0 = fu(vs[(kk + tg) * VST + c0]);
                uint32_t b1 = fu(vs[(kk + tg + 4) * VST + c0]);
                mma8(o[nt], a0, a1, a2, a3, b0, b1);
            }
        }
    }

    // epilogue (rna-rounded: feeds the Wo GEMM)
    float li = 1.f / lrow[r0], lh2 = 1.f / lrow[r0 + 8];
#pragma unroll
    for (int nt = 0; nt < 8; nt++) {
        int c = h * HEAD_DIM + wn * 64 + nt * 8 + 2 * tg;
        *(float2*)&O[(size_t)(qrow0 + r0) * QDIM + c] =
            make_float2(tfr(o[nt][0] * li), tfr(o[nt][1] * li));
        *(float2*)&O[(size_t)(qrow0 + r0 + 8) * QDIM + c] =
            make_float2(tfr(o[nt][2] * lh2), tfr(o[nt][3] * lh2));
    }
}

// ---------------- launch ----------------
extern "C" void kernel_launch(void* const* d_in, const int* in_sizes, int n_in,
                              void* d_out, int out_size) {
    const float* x  = (const float*)d_in[0];
    const float* Wq = (const float*)d_in[1];
    const float* Wk = (const float*)d_in[2];
    const float* Wv = (const float*)d_in[3];
    const float* Wo = (const float*)d_in[4];
    float* out = (float*)d_out;

    float *qkv, *att, *xr, *wc, *wor;
    cudaGetSymbolAddress((void**)&qkv, g_qkv);
    cudaGetSymbolAddress((void**)&att, g_att);
    cudaGetSymbolAddress((void**)&xr, g_xr);
    cudaGetSymbolAddress((void**)&wc, g_wc);
    cudaGetSymbolAddress((void**)&wor, g_wor);

    // prep: round x / Wo, concat+round Wq|Wk|Wv
    {
        int n4x = M_ROWS * D_MODEL / 4;
        round_rna<<<(n4x + 255) / 256, 256>>>((const float4*)x, (float4*)xr, n4x);
        int n4o = QDIM * D_MODEL / 4;
        round_rna<<<(n4o + 255) / 256, 256>>>((const float4*)Wo, (float4*)wor, n4o);
        int n4c = D_MODEL * QKVD / 4;
        concat_w<<<(n4c + 255) / 256, 256>>>(Wq, Wk, Wv, wc);
    }

    const int GSM = 3 * (ASTG + BSTG) * (int)sizeof(float);   // 107520
    cudaFuncSetAttribute(gemm_tf32, cudaFuncAttributeMaxDynamicSharedMemorySize, GSM);

    // fused QKV projection: [4096,2048] @ [2048,3072]
    gemm_tf32<<<dim3(QKVD / GBN, M_ROWS / GBM), 256, GSM>>>(xr, wc, qkv, M_ROWS, QKVD, D_MODEL);

    // RoPE on q/k + RNA-round v, all in place in qkv
    {
        int totq = B_SZ * T_SEQ * N_HEADS * 64;
        int totk = B_SZ * T_SEQ * N_KV * 64;
        rope_kernel<<<(totq + 255) / 256, 256>>>(qkv, N_HEADS, totq);
        rope_kernel<<<(totk + 255) / 256, 256>>>(qkv + QDIM, N_KV, totk);
        int n4v = M_ROWS * KVDIM / 4;
        round_v<<<(n4v + 255) / 256, 256>>>(qkv);
    }

    // attention
    {
        size_t smem = (size_t)(64 * QST + 2 * KBUF + 2 * VBUF + 64 * SST + 192) * sizeof(float);
        cudaFuncSetAttribute(attn_tf32, cudaFuncAttributeMaxDynamicSharedMemorySize, (int)smem);
        attn_tf32<<<dim3(T_SEQ / 64, N_HEADS, B_SZ), 256, smem>>>(qkv, att);
    }

    // output projection
    gemm_tf32<<<dim3(D_MODEL / GBN, M_ROWS / GBM), 256, GSM>>>(att, wor, out, M_ROWS, D_MODEL, QDIM);
}

// round 6
// speedup vs baseline: 5.0957x; 1.3313x over previous
#include <cuda_runtime.h>
#include <math.h>
#include <stdint.h>

#define D_MODEL 2048
#define N_HEADS 16
#define N_KV 4
#define HEAD_DIM 128
#define B_SZ 2
#define T_SEQ 2048
#define M_ROWS (B_SZ * T_SEQ)          // 4096
#define QDIM (N_HEADS * HEAD_DIM)      // 2048
#define KVDIM (N_KV * HEAD_DIM)        // 512
#define QKVD (QDIM + 2 * KVDIM)        // 3072

// ---------------- scratch ----------------
__device__ float g_qkv[M_ROWS * QKVD];
__device__ float g_att[M_ROWS * QDIM];
__device__ float g_xr[M_ROWS * D_MODEL];
__device__ float g_wc[D_MODEL * QKVD];
__device__ float g_wor[QDIM * D_MODEL];

// ---------------- helpers ----------------
__device__ __forceinline__ uint32_t ftf(float x) {
    uint32_t u;
    asm("cvt.rna.tf32.f32 %0, %1;" : "=r"(u) : "f"(x));
    return u;
}
__device__ __forceinline__ float tfr(float x) { return __uint_as_float(ftf(x)); }
__device__ __forceinline__ uint32_t fu(float x) { return __float_as_uint(x); }

__device__ __forceinline__ uint32_t s2u(const void* p) {
    uint32_t a;
    asm("{ .reg .u64 t; cvta.to.shared.u64 t, %1; cvt.u32.u64 %0, t; }" : "=r"(a) : "l"(p));
    return a;
}
__device__ __forceinline__ void cpa16(uint32_t dst, const void* src) {
    asm volatile("cp.async.cg.shared.global [%0], [%1], 16;" :: "r"(dst), "l"(src));
}
__device__ __forceinline__ void cpa_commit() { asm volatile("cp.async.commit_group;" ::: "memory"); }
template <int N> __device__ __forceinline__ void cpa_wait() {
    asm volatile("cp.async.wait_group %0;" :: "n"(N) : "memory");
}

__device__ __forceinline__ void mma8(float* c, uint32_t a0, uint32_t a1, uint32_t a2, uint32_t a3,
                                     uint32_t b0, uint32_t b1) {
    asm volatile(
        "mma.sync.aligned.m16n8k8.row.col.f32.tf32.tf32.f32 "
        "{%0,%1,%2,%3},{%4,%5,%6,%7},{%8,%9},{%0,%1,%2,%3};"
        : "+f"(c[0]), "+f"(c[1]), "+f"(c[2]), "+f"(c[3])
        : "r"(a0), "r"(a1), "r"(a2), "r"(a3), "r"(b0), "r"(b1));
}

// ---------------- GEMM: 128x256 CTA tile, 64x64 warp tile, 3-stage cp.async ----------------
#define GBM 128
#define GBN 256
#define GBK 32
#define AST 36
#define BST 264
#define ASTG (128 * AST)
#define BSTG (32 * BST)

__global__ __launch_bounds__(256, 1) void gemm_tf32(const float* __restrict__ A,
                                                    const float* __restrict__ B,
                                                    float* __restrict__ C,
                                                    int M, int N, int K) {
    extern __shared__ float sm[];
    float* As = sm;                // 3 * 128*36
    float* Bs = sm + 3 * ASTG;     // 3 * 32*264
    const uint32_t asb = s2u(As), bsb = s2u(Bs);

    const int tid = threadIdx.x;
    const int lane = tid & 31, warp = tid >> 5;
    const int wm = warp >> 2, wn = warp & 3;    // 2 x 4 warp grid, warp tile 64x64
    const int g = lane >> 2, tg = lane & 3;
    const int bm = blockIdx.y * GBM, bn = blockIdx.x * GBN;
    const int NK = K / GBK;

    float acc[4][8][4];
#pragma unroll
    for (int mt = 0; mt < 4; mt++)
#pragma unroll
        for (int nt = 0; nt < 8; nt++)
#pragma unroll
            for (int r = 0; r < 4; r++) acc[mt][nt][r] = 0.f;

    auto fill = [&](int kt) {
        const int s = kt - (kt / 3) * 3;
        const int k0 = kt * GBK;
#pragma unroll
        for (int i = 0; i < 4; i++) {         // A: 128 rows x 8 chunks
            int ch = tid + i * 256;
            int r = ch >> 3, j = ch & 7;
            cpa16(asb + (uint32_t)(s * ASTG + r * AST + 4 * j) * 4,
                  A + (size_t)(bm + r) * K + k0 + 4 * j);
        }
#pragma unroll
        for (int i = 0; i < 8; i++) {         // B: 32 rows x 64 chunks
            int ch = tid + i * 256;
            int r = ch >> 6, j = ch & 63;
            cpa16(bsb + (uint32_t)(s * BSTG + r * BST + 4 * j) * 4,
                  B + (size_t)(k0 + r) * N + bn + 4 * j);
        }
    };

    fill(0); cpa_commit();
    fill(1); cpa_commit();

    for (int kt = 0; kt < NK; kt++) {
        __syncthreads();
        if (kt + 2 < NK) fill(kt + 2);
        cpa_commit();
        cpa_wait<2>();
        __syncthreads();

        const int s = kt - (kt / 3) * 3;
        const float* as = As + s * ASTG;
        const float* bs = Bs + s * BSTG;
#pragma unroll
        for (int ks = 0; ks < 4; ks++) {
            const int kk = ks * 8;
            uint32_t af[4][4];
#pragma unroll
            for (int mt = 0; mt < 4; mt++) {
                int r0 = wm * 64 + mt * 16 + g;
                af[mt][0] = fu(as[r0 * AST + kk + tg]);
                af[mt][1] = fu(as[(r0 + 8) * AST + kk + tg]);
                af[mt][2] = fu(as[r0 * AST + kk + tg + 4]);
                af[mt][3] = fu(as[(r0 + 8) * AST + kk + tg + 4]);
            }
            uint32_t bf[8][2];
#pragma unroll
            for (int nt = 0; nt < 8; nt++) {
                int c0 = wn * 64 + nt * 8 + g;
                bf[nt][0] = fu(bs[(kk + tg) * BST + c0]);
                bf[nt][1] = fu(bs[(kk + tg + 4) * BST + c0]);
            }
#pragma unroll
            for (int mt = 0; mt < 4; mt++)
#pragma unroll
                for (int nt = 0; nt < 8; nt++)
                    mma8(acc[mt][nt], af[mt][0], af[mt][1], af[mt][2], af[mt][3], bf[nt][0], bf[nt][1]);
        }
    }

#pragma unroll
    for (int mt = 0; mt < 4; mt++)
#pragma unroll
        for (int nt = 0; nt < 8; nt++) {
            int r = bm + wm * 64 + mt * 16 + g;
            int c = bn + wn * 64 + nt * 8 + 2 * tg;
            *(float2*)&C[(size_t)r * N + c] = make_float2(acc[mt][nt][0], acc[mt][nt][1]);
            *(float2*)&C[(size_t)(r + 8) * N + c] = make_float2(acc[mt][nt][2], acc[mt][nt][3]);
        }
}

// ---------------- prep kernels ----------------
__global__ void round_rna(const float4* __restrict__ in, float4* __restrict__ out, int n4) {
    int i = blockIdx.x * blockDim.x + threadIdx.x;
    if (i < n4) {
        float4 v = in[i];
        out[i] = make_float4(tfr(v.x), tfr(v.y), tfr(v.z), tfr(v.w));
    }
}

__global__ void round_v(float* __restrict__ qkv) {
    int idx = blockIdx.x * blockDim.x + threadIdx.x;
    int row = idx >> 7;
    int col = (idx & 127) << 2;
    float* p = qkv + (size_t)row * QKVD + 2560 + col;
    float4 v = *(float4*)p;
    *(float4*)p = make_float4(tfr(v.x), tfr(v.y), tfr(v.z), tfr(v.w));
}

__global__ void concat_w(const float* __restrict__ Wq, const float* __restrict__ Wk,
                         const float* __restrict__ Wv, float* __restrict__ out) {
    int idx = blockIdx.x * blockDim.x + threadIdx.x;
    const int n4row = QKVD / 4;
    int k = idx / n4row;
    int n = (idx - k * n4row) * 4;
    const float* src;
    int c;
    if (n < QDIM)      { src = Wq + (size_t)k * QDIM;  c = n; }
    else if (n < 2560) { src = Wk + (size_t)k * KVDIM; c = n - QDIM; }
    else               { src = Wv + (size_t)k * KVDIM; c = n - 2560; }
    float4 v = *(const float4*)(src + c);
    *(float4*)(out + (size_t)k * QKVD + n) = make_float4(tfr(v.x), tfr(v.y), tfr(v.z), tfr(v.w));
}

__global__ void rope_kernel(float* __restrict__ X, int nh, int total) {
    int gid = blockIdx.x * blockDim.x + threadIdx.x;
    if (gid >= total) return;
    int i = gid & 63;
    int hh = (gid >> 6) % nh;
    int bt = gid / (64 * nh);
    int t = bt % T_SEQ;

    float inv = powf(10000.0f, -((float)(2 * i)) / 128.0f);
    float ang = (float)t * inv;
    float s, c;
    sincosf(ang, &s, &c);

    size_t base = (size_t)bt * QKVD + (size_t)hh * 128 + i;
    float x1 = X[base];
    float x2 = X[base + 64];
    X[base] = tfr(x1 * c - x2 * s);
    X[base + 64] = tfr(x2 * c + x1 * s);
}

// ---------------- flash attention: Br=128, register softmax ----------------
#define BQ 128
#define BKV 64
#define QST 132
#define KST 132
#define VST 136
#define PST 68
#define KBUF (BKV * KST)

__global__ __launch_bounds__(256, 1) void attn_tf32(const float* __restrict__ QKV,
                                                    float* __restrict__ O) {
    extern __shared__ float sm[];
    float* Qs = sm;                      // 128*132
    float* Ks = Qs + BQ * QST;           // 2 * 64*132  natural [n][d]
    float* Vs = Ks + 2 * KBUF;           // 64*136      natural [n][d]
    float* Ps = Vs + BKV * VST;          // 128*68
    const uint32_t qsb = s2u(Qs), ksb = s2u(Ks), vsb = s2u(Vs);

    const int qt = blockIdx.x, h = blockIdx.y, b = blockIdx.z;
    const int kvh = h >> 2;
    const int tid = threadIdx.x, lane = tid & 31, warp = tid >> 5;
    const int g = lane >> 2, tg = lane & 3;
    const int wr0 = warp * 16;                  // warp owns rows wr0..wr0+15
    const int qrow0 = b * T_SEQ + qt * BQ;
    const float scale = 0.08838834764831845f;

    const float* Qg = QKV + (size_t)h * 128;
    const float* Kg = QKV + QDIM + (size_t)kvh * 128;
    const float* Vg = QKV + 2560 + (size_t)kvh * 128;

    auto fill_k = [&](int kt) {
        const int s = kt & 1;
        const int kr0 = b * T_SEQ + kt * BKV;
#pragma unroll
        for (int i = 0; i < 8; i++) {
            int ch = tid + i * 256;
            int r = ch >> 5, j = ch & 31;
            cpa16(ksb + (uint32_t)(s * KBUF + r * KST + 4 * j) * 4,
                  Kg + (size_t)(kr0 + r) * QKVD + 4 * j);
        }
    };
    auto fill_v = [&](int kt) {
        const int kr0 = b * T_SEQ + kt * BKV;
#pragma unroll
        for (int i = 0; i < 8; i++) {
            int ch = tid + i * 256;
            int r = ch >> 5, j = ch & 31;
            cpa16(vsb + (uint32_t)(r * VST + 4 * j) * 4,
                  Vg + (size_t)(kr0 + r) * QKVD + 4 * j);
        }
    };

    // preamble: Q (128x32 chunks) + K(0), one group
#pragma unroll
    for (int i = 0; i < 16; i++) {
        int ch = tid + i * 256;
        int r = ch >> 5, j = ch & 31;
        cpa16(qsb + (uint32_t)(r * QST + 4 * j) * 4, Qg + (size_t)(qrow0 + r) * QKVD + 4 * j);
    }
    fill_k(0);
    cpa_commit();

    float m_lo = -INFINITY, m_hi = -INFINITY, l_lo = 0.f, l_hi = 0.f;
    float o[16][4];
#pragma unroll
    for (int nt = 0; nt < 16; nt++)
#pragma unroll
        for (int r = 0; r < 4; r++) o[nt][r] = 0.f;

    const int kmax = 2 * qt + 1;
    for (int kt = 0; kt <= kmax; kt++) {
        cpa_wait<0>();                   // K(kt) (and Q on kt=0) resident
        __syncthreads();                 // all warps done with V(kt-1); K(kt) visible
        fill_v(kt); cpa_commit();        // group V
        if (kt < kmax) { fill_k(kt + 1); cpa_commit(); }   // group K

        const float* ks = Ks + (kt & 1) * KBUF;

        // S = Q K^T : warp tile 16x64, full rows
        float sc[8][4];
#pragma unroll
        for (int nt = 0; nt < 8; nt++)
#pragma unroll
            for (int r = 0; r < 4; r++) sc[nt][r] = 0.f;
#pragma unroll
        for (int kss = 0; kss < 16; kss++) {
            const int kk = kss * 8;
            uint32_t a0 = fu(Qs[(wr0 + g) * QST + kk + tg]);
            uint32_t a1 = fu(Qs[(wr0 + 8 + g) * QST + kk + tg]);
            uint32_t a2 = fu(Qs[(wr0 + g) * QST + kk + tg + 4]);
            uint32_t a3 = fu(Qs[(wr0 + 8 + g) * QST + kk + tg + 4]);
#pragma unroll
            for (int nt = 0; nt < 8; nt++) {
                int c0 = nt * 8 + g;
                uint32_t b0 = fu(ks[c0 * KST + kk + tg]);
                uint32_t b1 = fu(ks[c0 * KST + kk + tg + 4]);
                mma8(sc[nt], a0, a1, a2, a3, b0, b1);
            }
        }

        // causal mask (only last two tiles are partial)
        if (kt >= 2 * qt) {
            int lim_lo = qt * BQ + wr0 + g - kt * BKV;
            int lim_hi = lim_lo + 8;
#pragma unroll
            for (int nt = 0; nt < 8; nt++) {
                int cc = nt * 8 + 2 * tg;
                if (cc     > lim_lo) sc[nt][0] = -INFINITY;
                if (cc + 1 > lim_lo) sc[nt][1] = -INFINITY;
                if (cc     > lim_hi) sc[nt][2] = -INFINITY;
                if (cc + 1 > lim_hi) sc[nt][3] = -INFINITY;
            }
        }

        // register softmax
        float mx_lo = -INFINITY, mx_hi = -INFINITY;
#pragma unroll
        for (int nt = 0; nt < 8; nt++) {
            mx_lo = fmaxf(mx_lo, fmaxf(sc[nt][0], sc[nt][1]));
            mx_hi = fmaxf(mx_hi, fmaxf(sc[nt][2], sc[nt][3]));
        }
        mx_lo = fmaxf(mx_lo, __shfl_xor_sync(0xffffffffu, mx_lo, 1));
        mx_lo = fmaxf(mx_lo, __shfl_xor_sync(0xffffffffu, mx_lo, 2));
        mx_hi = fmaxf(mx_hi, __shfl_xor_sync(0xffffffffu, mx_hi, 1));
        mx_hi = fmaxf(mx_hi, __shfl_xor_sync(0xffffffffu, mx_hi, 2));

        float mn_lo = fmaxf(m_lo, mx_lo), mn_hi = fmaxf(m_hi, mx_hi);
        float al_lo = __expf((m_lo - mn_lo) * scale);
        float al_hi = __expf((m_hi - mn_hi) * scale);
        float ls_lo = 0.f, ls_hi = 0.f;
#pragma unroll
        for (int nt = 0; nt < 8; nt++) {
            float p0 = __expf((sc[nt][0] - mn_lo) * scale);
            float p1 = __expf((sc[nt][1] - mn_lo) * scale);
            float p2 = __expf((sc[nt][2] - mn_hi) * scale);
            float p3 = __expf((sc[nt][3] - mn_hi) * scale);
            ls_lo += p0 + p1;
            ls_hi += p2 + p3;
            int cc = nt * 8 + 2 * tg;
            *(float2*)&Ps[(wr0 + g) * PST + cc]     = make_float2(tfr(p0), tfr(p1));
            *(float2*)&Ps[(wr0 + 8 + g) * PST + cc] = make_float2(tfr(p2), tfr(p3));
        }
        ls_lo += __shfl_xor_sync(0xffffffffu, ls_lo, 1);
        ls_lo += __shfl_xor_sync(0xffffffffu, ls_lo, 2);
        ls_hi += __shfl_xor_sync(0xffffffffu, ls_hi, 1);
        ls_hi += __shfl_xor_sync(0xffffffffu, ls_hi, 2);
        l_lo = l_lo * al_lo + ls_lo;
        l_hi = l_hi * al_hi + ls_hi;
        m_lo = mn_lo; m_hi = mn_hi;
        __syncwarp();                    // P visible warp-locally

        // wait V(kt); K(kt+1) may remain in flight
        if (kt < kmax) cpa_wait<1>(); else cpa_wait<0>();
        __syncthreads();                 // V visible CTA-wide

        // O = O*alpha + P @ V : warp tile 16x128
#pragma unroll
        for (int nt = 0; nt < 16; nt++) {
            o[nt][0] *= al_lo; o[nt][1] *= al_lo;
            o[nt][2] *= al_hi; o[nt][3] *= al_hi;
        }
#pragma unroll
        for (int kss = 0; kss < 8; kss++) {
            const int kk = kss * 8;
            uint32_t a0 = fu(Ps[(wr0 + g) * PST + kk + tg]);
            uint32_t a1 = fu(Ps[(wr0 + 8 + g) * PST + kk + tg]);
            uint32_t a2 = fu(Ps[(wr0 + g) * PST + kk + tg + 4]);
            uint32_t a3 = fu(Ps[(wr0 + 8 + g) * PST + kk + tg + 4]);
#pragma unroll
            for (int nt = 0; nt < 16; nt++) {
                int c0 = nt * 8 + g;
                uint32_t b0 = fu(Vs[(kk + tg) * VST + c0]);
                uint32_t b1 = fu(Vs[(kk + tg + 4) * VST + c0]);
                mma8(o[nt], a0, a1, a2, a3, b0, b1);
            }
        }
    }

    // epilogue (rna-rounded for the Wo GEMM)
    float li = 1.f / l_lo, lh = 1.f / l_hi;
#pragma unroll
    for (int nt = 0; nt < 16; nt++) {
        int c = h * HEAD_DIM + nt * 8 + 2 * tg;
        *(float2*)&O[(size_t)(qrow0 + wr0 + g) * QDIM + c] =
            make_float2(tfr(o[nt][0] * li), tfr(o[nt][1] * li));
        *(float2*)&O[(size_t)(qrow0 + wr0 + 8 + g) * QDIM + c] =
            make_float2(tfr(o[nt][2] * lh), tfr(o[nt][3] * lh));
    }
}

// ---------------- launch ----------------
extern "C" void kernel_launch(void* const* d_in, const int* in_sizes, int n_in,
                              void* d_out, int out_size) {
    const float* x  = (const float*)d_in[0];
    const float* Wq = (const float*)d_in[1];
    const float* Wk = (const float*)d_in[2];
    const float* Wv = (const float*)d_in[3];
    const float* Wo = (const float*)d_in[4];
    float* out = (float*)d_out;

    float *qkv, *att, *xr, *wc, *wor;
    cudaGetSymbolAddress((void**)&qkv, g_qkv);
    cudaGetSymbolAddress((void**)&att, g_att);
    cudaGetSymbolAddress((void**)&xr, g_xr);
    cudaGetSymbolAddress((void**)&wc, g_wc);
    cudaGetSymbolAddress((void**)&wor, g_wor);

    {
        int n4x = M_ROWS * D_MODEL / 4;
        round_rna<<<(n4x + 255) / 256, 256>>>((const float4*)x, (float4*)xr, n4x);
        int n4o = QDIM * D_MODEL / 4;
        round_rna<<<(n4o + 255) / 256, 256>>>((const float4*)Wo, (float4*)wor, n4o);
        int n4c = D_MODEL * QKVD / 4;
        concat_w<<<(n4c + 255) / 256, 256>>>(Wq, Wk, Wv, wc);
    }

    const int GSM = 3 * (ASTG + BSTG) * (int)sizeof(float);   // 156672
    cudaFuncSetAttribute(gemm_tf32, cudaFuncAttributeMaxDynamicSharedMemorySize, GSM);

    gemm_tf32<<<dim3(QKVD / GBN, M_ROWS / GBM), 256, GSM>>>(xr, wc, qkv, M_ROWS, QKVD, D_MODEL);

    {
        int totq = B_SZ * T_SEQ * N_HEADS * 64;
        int totk = B_SZ * T_SEQ * N_KV * 64;
        rope_kernel<<<(totq + 255) / 256, 256>>>(qkv, N_HEADS, totq);
        rope_kernel<<<(totk + 255) / 256, 256>>>(qkv + QDIM, N_KV, totk);
        int n4v = M_ROWS * KVDIM / 4;
        round_v<<<(n4v + 255) / 256, 256>>>(qkv);
    }

    {
        const int ASM_ = (BQ * QST + 2 * KBUF + BKV * VST + BQ * PST) * (int)sizeof(float); // 204800
        cudaFuncSetAttribute(attn_tf32, cudaFuncAttributeMaxDynamicSharedMemorySize, ASM_);
        attn_tf32<<<dim3(T_SEQ / BQ, N_HEADS, B_SZ), 256, ASM_>>>(qkv, att);
    }

    gemm_tf32<<<dim3(D_MODEL / GBN, M_ROWS / GBM), 256, GSM>>>(att, wor, out, M_ROWS, D_MODEL, QDIM);
}

// round 7
// speedup vs baseline: 5.1861x; 1.0177x over previous
#include <cuda_runtime.h>
#include <math.h>
#include <stdint.h>

#define D_MODEL 2048
#define N_HEADS 16
#define N_KV 4
#define HEAD_DIM 128
#define B_SZ 2
#define T_SEQ 2048
#define M_ROWS (B_SZ * T_SEQ)          // 4096
#define QDIM (N_HEADS * HEAD_DIM)      // 2048
#define KVDIM (N_KV * HEAD_DIM)        // 512
#define QKVD (QDIM + 2 * KVDIM)        // 3072

// ---------------- scratch ----------------
__device__ float g_qkv[M_ROWS * QKVD];
__device__ float g_att[M_ROWS * QDIM];
__device__ float g_xr[M_ROWS * D_MODEL];
__device__ float g_wct[QKVD * D_MODEL];   // concat weights, transposed [n][k], rounded
__device__ float g_wot[D_MODEL * QDIM];   // Wo transposed [n][k], rounded

// ---------------- helpers ----------------
__device__ __forceinline__ uint32_t ftf(float x) {
    uint32_t u;
    asm("cvt.rna.tf32.f32 %0, %1;" : "=r"(u) : "f"(x));
    return u;
}
__device__ __forceinline__ float tfr(float x) { return __uint_as_float(ftf(x)); }
__device__ __forceinline__ uint32_t fu(float x) { return __float_as_uint(x); }

__device__ __forceinline__ uint32_t s2u(const void* p) {
    uint32_t a;
    asm("{ .reg .u64 t; cvta.to.shared.u64 t, %1; cvt.u32.u64 %0, t; }" : "=r"(a) : "l"(p));
    return a;
}
__device__ __forceinline__ void cpa16(uint32_t dst, const void* src) {
    asm volatile("cp.async.cg.shared.global [%0], [%1], 16;" :: "r"(dst), "l"(src));
}
__device__ __forceinline__ void cpa_commit() { asm volatile("cp.async.commit_group;" ::: "memory"); }
template <int N> __device__ __forceinline__ void cpa_wait() {
    asm volatile("cp.async.wait_group %0;" :: "n"(N) : "memory");
}
__device__ __forceinline__ void ldsm4(uint32_t& r0, uint32_t& r1, uint32_t& r2, uint32_t& r3,
                                      uint32_t addr) {
    asm volatile("ldmatrix.sync.aligned.m8n8.x4.shared.b16 {%0,%1,%2,%3}, [%4];"
                 : "=r"(r0), "=r"(r1), "=r"(r2), "=r"(r3) : "r"(addr));
}
__device__ __forceinline__ void mma8(float* c, uint32_t a0, uint32_t a1, uint32_t a2, uint32_t a3,
                                     uint32_t b0, uint32_t b1) {
    asm volatile(
        "mma.sync.aligned.m16n8k8.row.col.f32.tf32.tf32.f32 "
        "{%0,%1,%2,%3},{%4,%5,%6,%7},{%8,%9},{%0,%1,%2,%3};"
        : "+f"(c[0]), "+f"(c[1]), "+f"(c[2]), "+f"(c[3])
        : "r"(a0), "r"(a1), "r"(a2), "r"(a3), "r"(b0), "r"(b1));
}

// ---------------- GEMM: C[M,N] = A[M,K] @ Bt[N,K]^T, both K-major, ldmatrix frags ----------------
#define GBM 128
#define GBN 256
#define GBK 32
#define GST 36                         // K-major smem stride (floats)
#define ASTG (128 * GST)               // floats per A stage
#define BSTG (256 * GST)               // floats per B stage

__global__ __launch_bounds__(256, 1) void gemm_tf32(const float* __restrict__ A,
                                                    const float* __restrict__ Bt,
                                                    float* __restrict__ C,
                                                    int M, int N, int K) {
    extern __shared__ float sm[];
    float* As = sm;                    // 3 * 128*36
    float* Bs = sm + 3 * ASTG;         // 3 * 256*36
    const uint32_t asb = s2u(As), bsb = s2u(Bs);

    const int tid = threadIdx.x;
    const int lane = tid & 31, warp = tid >> 5;
    const int wm = warp >> 2, wn = warp & 3;    // 2 x 4 warp grid, warp tile 64x64
    const int g = lane >> 2, tg = lane & 3;
    const int bm = blockIdx.y * GBM, bn = blockIdx.x * GBN;
    const int NK = K / GBK;

    // ldmatrix lane offsets (bytes, within a stage)
    uint32_t aoff[4], boff[4];
#pragma unroll
    for (int mt = 0; mt < 4; mt++)
        aoff[mt] = (uint32_t)(((wm * 64 + mt * 16 + (lane & 15)) * GST + ((lane >> 4) << 2)) * 4);
#pragma unroll
    for (int ntp = 0; ntp < 4; ntp++)
        boff[ntp] = (uint32_t)(((wn * 64 + ntp * 16 + (lane & 7) + ((lane >> 4) << 3)) * GST +
                                (((lane >> 3) & 1) << 2)) * 4);

    float acc[4][8][4];
#pragma unroll
    for (int mt = 0; mt < 4; mt++)
#pragma unroll
        for (int nt = 0; nt < 8; nt++)
#pragma unroll
            for (int r = 0; r < 4; r++) acc[mt][nt][r] = 0.f;

    auto fill = [&](int kt) {
        const int s = kt - (kt / 3) * 3;
        const int k0 = kt * GBK;
#pragma unroll
        for (int i = 0; i < 4; i++) {         // A: 128 rows x 8 chunks
            int ch = tid + i * 256;
            int r = ch >> 3, j = ch & 7;
            cpa16(asb + (uint32_t)((s * ASTG + r * GST + 4 * j) * 4),
                  A + (size_t)(bm + r) * K + k0 + 4 * j);
        }
#pragma unroll
        for (int i = 0; i < 8; i++) {         // B: 256 rows x 8 chunks
            int ch = tid + i * 256;
            int r = ch >> 3, j = ch & 7;
            cpa16(bsb + (uint32_t)((s * BSTG + r * GST + 4 * j) * 4),
                  Bt + (size_t)(bn + r) * K + k0 + 4 * j);
        }
    };

    fill(0); cpa_commit();
    fill(1); cpa_commit();

    for (int kt = 0; kt < NK; kt++) {
        cpa_wait<1>();
        __syncthreads();
        if (kt + 2 < NK) fill(kt + 2);
        cpa_commit();

        const int s = kt - (kt / 3) * 3;
        const uint32_t ab = asb + (uint32_t)(s * ASTG * 4);
        const uint32_t bb = bsb + (uint32_t)(s * BSTG * 4);
#pragma unroll
        for (int ks = 0; ks < 4; ks++) {
            uint32_t af[4][4], bf[8][2];
#pragma unroll
            for (int mt = 0; mt < 4; mt++)
                ldsm4(af[mt][0], af[mt][1], af[mt][2], af[mt][3], ab + aoff[mt] + ks * 32);
#pragma unroll
            for (int ntp = 0; ntp < 4; ntp++)
                ldsm4(bf[2 * ntp][0], bf[2 * ntp][1], bf[2 * ntp + 1][0], bf[2 * ntp + 1][1],
                      bb + boff[ntp] + ks * 32);
#pragma unroll
            for (int mt = 0; mt < 4; mt++)
#pragma unroll
                for (int nt = 0; nt < 8; nt++)
                    mma8(acc[mt][nt], af[mt][0], af[mt][1], af[mt][2], af[mt][3], bf[nt][0], bf[nt][1]);
        }
    }

#pragma unroll
    for (int mt = 0; mt < 4; mt++)
#pragma unroll
        for (int nt = 0; nt < 8; nt++) {
            int r = bm + wm * 64 + mt * 16 + g;
            int c = bn + wn * 64 + nt * 8 + 2 * tg;
            *(float2*)&C[(size_t)r * N + c] = make_float2(acc[mt][nt][0], acc[mt][nt][1]);
            *(float2*)&C[(size_t)(r + 8) * N + c] = make_float2(acc[mt][nt][2], acc[mt][nt][3]);
        }
}

// ---------------- prep kernels ----------------
__global__ void round_rna(const float4* __restrict__ in, float4* __restrict__ out, int n4) {
    int i = blockIdx.x * blockDim.x + threadIdx.x;
    if (i < n4) {
        float4 v = in[i];
        out[i] = make_float4(tfr(v.x), tfr(v.y), tfr(v.z), tfr(v.w));
    }
}

__global__ void round_v(float* __restrict__ qkv) {
    int idx = blockIdx.x * blockDim.x + threadIdx.x;
    int row = idx >> 7;
    int col = (idx & 127) << 2;
    float* p = qkv + (size_t)row * QKVD + 2560 + col;
    float4 v = *(float4*)p;
    *(float4*)p = make_float4(tfr(v.x), tfr(v.y), tfr(v.z), tfr(v.w));
}

// Wt[n][k] = rna(W[k][n]); W is [K][N]
__global__ void transpose_rna(const float* __restrict__ W, float* __restrict__ Wt, int K, int N) {
    __shared__ float t[32][33];
    int kb = blockIdx.x * 32, nb = blockIdx.y * 32;
    int tx = threadIdx.x, ty = threadIdx.y;
#pragma unroll
    for (int i = 0; i < 32; i += 8)
        t[ty + i][tx] = W[(size_t)(kb + ty + i) * N + nb + tx];
    __syncthreads();
#pragma unroll
    for (int i = 0; i < 32; i += 8)
        Wt[(size_t)(nb + ty + i) * K + kb + tx] = tfr(t[tx][ty + i]);
}

__global__ void rope_kernel(float* __restrict__ X, int nh, int total) {
    int gid = blockIdx.x * blockDim.x + threadIdx.x;
    if (gid >= total) return;
    int i = gid & 63;
    int hh = (gid >> 6) % nh;
    int bt = gid / (64 * nh);
    int t = bt % T_SEQ;

    float inv = powf(10000.0f, -((float)(2 * i)) / 128.0f);
    float ang = (float)t * inv;
    float s, c;
    sincosf(ang, &s, &c);

    size_t base = (size_t)bt * QKVD + (size_t)hh * 128 + i;
    float x1 = X[base];
    float x2 = X[base + 64];
    X[base] = tfr(x1 * c - x2 * s);
    X[base + 64] = tfr(x2 * c + x1 * s);
}

// ---------------- flash attention: Br=128, register softmax, ldmatrix frags ----------------
#define BQ 128
#define BKV 64
#define QST 132
#define KST 132
#define VST 136
#define PST 68
#define KBUF (BKV * KST)

__global__ __launch_bounds__(256, 1) void attn_tf32(const float* __restrict__ QKV,
                                                    float* __restrict__ O) {
    extern __shared__ float sm[];
    float* Qs = sm;                      // 128*132
    float* Ks = Qs + BQ * QST;           // 2 * 64*132  natural [n][d]
    float* Vs = Ks + 2 * KBUF;           // 64*136      natural [n][d]
    float* Ps = Vs + BKV * VST;          // 128*68
    const uint32_t qsb = s2u(Qs), ksb = s2u(Ks), vsb = s2u(Vs), psb = s2u(Ps);

    const int qt = blockIdx.x, h = blockIdx.y, b = blockIdx.z;
    const int kvh = h >> 2;
    const int tid = threadIdx.x, lane = tid & 31, warp = tid >> 5;
    const int g = lane >> 2, tg = lane & 3;
    const int wr0 = warp * 16;
    const int qrow0 = b * T_SEQ + qt * BQ;
    const float scale = 0.08838834764831845f;

    const float* Qg = QKV + (size_t)h * 128;
    const float* Kg = QKV + QDIM + (size_t)kvh * 128;
    const float* Vg = QKV + 2560 + (size_t)kvh * 128;

    // ldmatrix lane offsets (bytes)
    const uint32_t q_lo = (uint32_t)(((wr0 + (lane & 15)) * QST + ((lane >> 4) << 2)) * 4);
    const uint32_t p_lo = (uint32_t)(((wr0 + (lane & 15)) * PST + ((lane >> 4) << 2)) * 4);
    uint32_t k_lo[4];
#pragma unroll
    for (int ntp = 0; ntp < 4; ntp++)
        k_lo[ntp] = (uint32_t)(((ntp * 16 + (lane & 7) + ((lane >> 4) << 3)) * KST +
                                (((lane >> 3) & 1) << 2)) * 4);

    auto fill_k = [&](int kt) {
        const int s = kt & 1;
        const int kr0 = b * T_SEQ + kt * BKV;
#pragma unroll
        for (int i = 0; i < 8; i++) {
            int ch = tid + i * 256;
            int r = ch >> 5, j = ch & 31;
            cpa16(ksb + (uint32_t)((s * KBUF + r * KST + 4 * j) * 4),
                  Kg + (size_t)(kr0 + r) * QKVD + 4 * j);
        }
    };
    auto fill_v = [&](int kt) {
        const int kr0 = b * T_SEQ + kt * BKV;
#pragma unroll
        for (int i = 0; i < 8; i++) {
            int ch = tid + i * 256;
            int r = ch >> 5, j = ch & 31;
            cpa16(vsb + (uint32_t)((r * VST + 4 * j) * 4),
                  Vg + (size_t)(kr0 + r) * QKVD + 4 * j);
        }
    };

#pragma unroll
    for (int i = 0; i < 16; i++) {
        int ch = tid + i * 256;
        int r = ch >> 5, j = ch & 31;
        cpa16(qsb + (uint32_t)((r * QST + 4 * j) * 4), Qg + (size_t)(qrow0 + r) * QKVD + 4 * j);
    }
    fill_k(0);
    cpa_commit();

    float m_lo = -INFINITY, m_hi = -INFINITY, l_lo = 0.f, l_hi = 0.f;
    float o[16][4];
#pragma unroll
    for (int nt = 0; nt < 16; nt++)
#pragma unroll
        for (int r = 0; r < 4; r++) o[nt][r] = 0.f;

    const int kmax = 2 * qt + 1;
    for (int kt = 0; kt <= kmax; kt++) {
        cpa_wait<0>();
        __syncthreads();
        fill_v(kt); cpa_commit();
        if (kt < kmax) { fill_k(kt + 1); cpa_commit(); }

        const uint32_t kb = ksb + (uint32_t)((kt & 1) * KBUF * 4);

        // S = Q K^T : warp tile 16x64 (ldmatrix both sides)
        float sc[8][4];
#pragma unroll
        for (int nt = 0; nt < 8; nt++)
#pragma unroll
            for (int r = 0; r < 4; r++) sc[nt][r] = 0.f;
#pragma unroll
        for (int kss = 0; kss < 16; kss++) {
            uint32_t a0, a1, a2, a3, bf[8][2];
            ldsm4(a0, a1, a2, a3, qsb + q_lo + kss * 32);
#pragma unroll
            for (int ntp = 0; ntp < 4; ntp++)
                ldsm4(bf[2 * ntp][0], bf[2 * ntp][1], bf[2 * ntp + 1][0], bf[2 * ntp + 1][1],
                      kb + k_lo[ntp] + kss * 32);
#pragma unroll
            for (int nt = 0; nt < 8; nt++)
                mma8(sc[nt], a0, a1, a2, a3, bf[nt][0], bf[nt][1]);
        }

        // causal mask (only last two tiles are partial)
        if (kt >= 2 * qt) {
            int lim_lo = qt * BQ + wr0 + g - kt * BKV;
            int lim_hi = lim_lo + 8;
#pragma unroll
            for (int nt = 0; nt < 8; nt++) {
                int cc = nt * 8 + 2 * tg;
                if (cc     > lim_lo) sc[nt][0] = -INFINITY;
                if (cc + 1 > lim_lo) sc[nt][1] = -INFINITY;
                if (cc     > lim_hi) sc[nt][2] = -INFINITY;
                if (cc + 1 > lim_hi) sc[nt][3] = -INFINITY;
            }
        }

        // register softmax
        float mx_lo = -INFINITY, mx_hi = -INFINITY;
#pragma unroll
        for (int nt = 0; nt < 8; nt++) {
            mx_lo = fmaxf(mx_lo, fmaxf(sc[nt][0], sc[nt][1]));
            mx_hi = fmaxf(mx_hi, fmaxf(sc[nt][2], sc[nt][3]));
        }
        mx_lo = fmaxf(mx_lo, __shfl_xor_sync(0xffffffffu, mx_lo, 1));
        mx_lo = fmaxf(mx_lo, __shfl_xor_sync(0xffffffffu, mx_lo, 2));
        mx_hi = fmaxf(mx_hi, __shfl_xor_sync(0xffffffffu, mx_hi, 1));
        mx_hi = fmaxf(mx_hi, __shfl_xor_sync(0xffffffffu, mx_hi, 2));

        float mn_lo = fmaxf(m_lo, mx_lo), mn_hi = fmaxf(m_hi, mx_hi);
        float al_lo = __expf((m_lo - mn_lo) * scale);
        float al_hi = __expf((m_hi - mn_hi) * scale);
        float ls_lo = 0.f, ls_hi = 0.f;
#pragma unroll
        for (int nt = 0; nt < 8; nt++) {
            float p0 = __expf((sc[nt][0] - mn_lo) * scale);
            float p1 = __expf((sc[nt][1] - mn_lo) * scale);
            float p2 = __expf((sc[nt][2] - mn_hi) * scale);
            float p3 = __expf((sc[nt][3] - mn_hi) * scale);
            ls_lo += p0 + p1;
            ls_hi += p2 + p3;
            int cc = nt * 8 + 2 * tg;
            *(float2*)&Ps[(wr0 + g) * PST + cc]     = make_float2(tfr(p0), tfr(p1));
            *(float2*)&Ps[(wr0 + 8 + g) * PST + cc] = make_float2(tfr(p2), tfr(p3));
        }
        ls_lo += __shfl_xor_sync(0xffffffffu, ls_lo, 1);
        ls_lo += __shfl_xor_sync(0xffffffffu, ls_lo, 2);
        ls_hi += __shfl_xor_sync(0xffffffffu, ls_hi, 1);
        ls_hi += __shfl_xor_sync(0xffffffffu, ls_hi, 2);
        l_lo = l_lo * al_lo + ls_lo;
        l_hi = l_hi * al_hi + ls_hi;
        m_lo = mn_lo; m_hi = mn_hi;
        __syncwarp();

        if (kt < kmax) cpa_wait<1>(); else cpa_wait<0>();
        __syncthreads();

        // O = O*alpha + P @ V : warp tile 16x128 (P via ldmatrix, V scalar)
#pragma unroll
        for (int nt = 0; nt < 16; nt++) {
            o[nt][0] *= al_lo; o[nt][1] *= al_lo;
            o[nt][2] *= al_hi; o[nt][3] *= al_hi;
        }
#pragma unroll
        for (int kss = 0; kss < 8; kss++) {
            const int kk = kss * 8;
            uint32_t a0, a1, a2, a3;
            ldsm4(a0, a1, a2, a3, psb + p_lo + kss * 32);
#pragma unroll
            for (int nt = 0; nt < 16; nt++) {
                int c0 = nt * 8 + g;
                uint32_t b0 = fu(Vs[(kk + tg) * VST + c0]);
                uint32_t b1 = fu(Vs[(kk + tg + 4) * VST + c0]);
                mma8(o[nt], a0, a1, a2, a3, b0, b1);
            }
        }
    }

    // epilogue (rna-rounded for the Wo GEMM)
    float li = 1.f / l_lo, lh = 1.f / l_hi;
#pragma unroll
    for (int nt = 0; nt < 16; nt++) {
        int c = h * HEAD_DIM + nt * 8 + 2 * tg;
        *(float2*)&O[(size_t)(qrow0 + wr0 + g) * QDIM + c] =
            make_float2(tfr(o[nt][0] * li), tfr(o[nt][1] * li));
        *(float2*)&O[(size_t)(qrow0 + wr0 + 8 + g) * QDIM + c] =
            make_float2(tfr(o[nt][2] * lh), tfr(o[nt][3] * lh));
    }
}

// ---------------- launch ----------------
extern "C" void kernel_launch(void* const* d_in, const int* in_sizes, int n_in,
                              void* d_out, int out_size) {
    const float* x  = (const float*)d_in[0];
    const float* Wq = (const float*)d_in[1];
    const float* Wk = (const float*)d_in[2];
    const float* Wv = (const float*)d_in[3];
    const float* Wo = (const float*)d_in[4];
    float* out = (float*)d_out;

    float *qkv, *att, *xr, *wct, *wot;
    cudaGetSymbolAddress((void**)&qkv, g_qkv);
    cudaGetSymbolAddress((void**)&att, g_att);
    cudaGetSymbolAddress((void**)&xr, g_xr);
    cudaGetSymbolAddress((void**)&wct, g_wct);
    cudaGetSymbolAddress((void**)&wot, g_wot);

    // prep: round x; transpose+round weights to [n][k]
    {
        int n4x = M_ROWS * D_MODEL / 4;
        round_rna<<<(n4x + 255) / 256, 256>>>((const float4*)x, (float4*)xr, n4x);
        dim3 blk(32, 8);
        transpose_rna<<<dim3(D_MODEL / 32, QDIM / 32), blk>>>(Wq, wct, D_MODEL, QDIM);
        transpose_rna<<<dim3(D_MODEL / 32, KVDIM / 32), blk>>>(Wk, wct + (size_t)QDIM * D_MODEL,
                                                               D_MODEL, KVDIM);
        transpose_rna<<<dim3(D_MODEL / 32, KVDIM / 32), blk>>>(Wv, wct + (size_t)2560 * D_MODEL,
                                                               D_MODEL, KVDIM);
        transpose_rna<<<dim3(QDIM / 32, D_MODEL / 32), blk>>>(Wo, wot, QDIM, D_MODEL);
    }

    const int GSM = 3 * (ASTG + BSTG) * (int)sizeof(float);   // 165888
    cudaFuncSetAttribute(gemm_tf32, cudaFuncAttributeMaxDynamicSharedMemorySize, GSM);

    // fused QKV projection
    gemm_tf32<<<dim3(QKVD / GBN, M_ROWS / GBM), 256, GSM>>>(xr, wct, qkv, M_ROWS, QKVD, D_MODEL);

    // RoPE q/k + round v
    {
        int totq = B_SZ * T_SEQ * N_HEADS * 64;
        int totk = B_SZ * T_SEQ * N_KV * 64;
        rope_kernel<<<(totq + 255) / 256, 256>>>(qkv, N_HEADS, totq);
        rope_kernel<<<(totk + 255) / 256, 256>>>(qkv + QDIM, N_KV, totk);
        int n4v = M_ROWS * KVDIM / 4;
        round_v<<<(n4v + 255) / 256, 256>>>(qkv);
    }

    // attention
    {
        const int ASM_ = (BQ * QST + 2 * KBUF + BKV * VST + BQ * PST) * (int)sizeof(float); // 204800
        cudaFuncSetAttribute(attn_tf32, cudaFuncAttributeMaxDynamicSharedMemorySize, ASM_);
        attn_tf32<<<dim3(T_SEQ / BQ, N_HEADS, B_SZ), 256, ASM_>>>(qkv, att);
    }

    // output projection
    gemm_tf32<<<dim3(D_MODEL / GBN, M_ROWS / GBM), 256, GSM>>>(att, wot, out, M_ROWS, D_MODEL, QDIM);
}

// round 8
// speedup vs baseline: 9.1627x; 1.7668x over previous
#include <cuda_runtime.h>
#include <cuda_fp16.h>
#include <math.h>
#include <stdint.h>

#define D_MODEL 2048
#define N_HEADS 16
#define N_KV 4
#define HEAD_DIM 128
#define B_SZ 2
#define T_SEQ 2048
#define M_ROWS (B_SZ * T_SEQ)          // 4096
#define QDIM (N_HEADS * HEAD_DIM)      // 2048
#define KVDIM (N_KV * HEAD_DIM)        // 512
#define QKVD (QDIM + 2 * KVDIM)        // 3072

// ---------------- scratch ----------------
__device__ __half g_qkv[M_ROWS * QKVD];
__device__ __half g_att[M_ROWS * QDIM];
__device__ __half g_xh[M_ROWS * D_MODEL];
__device__ __half g_wct[(size_t)QKVD * D_MODEL];   // concat weights [n][k], fp16
__device__ __half g_wot[(size_t)D_MODEL * QDIM];   // Wo [n][k], fp16

// ---------------- helpers ----------------
__device__ __forceinline__ uint32_t s2u(const void* p) {
    uint32_t a;
    asm("{ .reg .u64 t; cvta.to.shared.u64 t, %1; cvt.u32.u64 %0, t; }" : "=r"(a) : "l"(p));
    return a;
}
__device__ __forceinline__ void cpa16(uint32_t dst, const void* src) {
    asm volatile("cp.async.cg.shared.global [%0], [%1], 16;" :: "r"(dst), "l"(src));
}
__device__ __forceinline__ void cpa_commit() { asm volatile("cp.async.commit_group;" ::: "memory"); }
template <int N> __device__ __forceinline__ void cpa_wait() {
    asm volatile("cp.async.wait_group %0;" :: "n"(N) : "memory");
}
__device__ __forceinline__ void ldsm4(uint32_t& r0, uint32_t& r1, uint32_t& r2, uint32_t& r3,
                                      uint32_t addr) {
    asm volatile("ldmatrix.sync.aligned.m8n8.x4.shared.b16 {%0,%1,%2,%3}, [%4];"
                 : "=r"(r0), "=r"(r1), "=r"(r2), "=r"(r3) : "r"(addr));
}
__device__ __forceinline__ void ldsm4t(uint32_t& r0, uint32_t& r1, uint32_t& r2, uint32_t& r3,
                                       uint32_t addr) {
    asm volatile("ldmatrix.sync.aligned.m8n8.x4.trans.shared.b16 {%0,%1,%2,%3}, [%4];"
                 : "=r"(r0), "=r"(r1), "=r"(r2), "=r"(r3) : "r"(addr));
}
// m16n8k16 fp16 -> fp32
__device__ __forceinline__ void mma16(float* c, uint32_t a0, uint32_t a1, uint32_t a2, uint32_t a3,
                                      uint32_t b0, uint32_t b1) {
    asm volatile(
        "mma.sync.aligned.m16n8k16.row.col.f32.f16.f16.f32 "
        "{%0,%1,%2,%3},{%4,%5,%6,%7},{%8,%9},{%0,%1,%2,%3};"
        : "+f"(c[0]), "+f"(c[1]), "+f"(c[2]), "+f"(c[3])
        : "r"(a0), "r"(a1), "r"(a2), "r"(a3), "r"(b0), "r"(b1));
}

// ---------------- GEMM: C[M,N] = A[M,K]h @ Bt[N,K]h^T, K-major, ldmatrix ----------------
#define GBM 128
#define GBN 256
#define GBK 64                         // halves per k-tile (4 mma k-steps)
#define GSTH 72                        // smem stride in halves (64 + 8 pad)
#define ASTGH (128 * GSTH)
#define BSTGH (256 * GSTH)

template <typename TO>
__global__ __launch_bounds__(256, 1) void gemm_h(const __half* __restrict__ A,
                                                 const __half* __restrict__ Bt,
                                                 TO* __restrict__ C,
                                                 int M, int N, int K) {
    extern __shared__ __half smh[];
    const uint32_t asb = s2u(smh);
    const uint32_t bsb = asb + 3 * ASTGH * 2;

    const int tid = threadIdx.x;
    const int lane = tid & 31, warp = tid >> 5;
    const int wm = warp >> 2, wn = warp & 3;    // 2 x 4 warps, 64x64 warp tile
    const int g = lane >> 2, tg = lane & 3;
    const int bm = blockIdx.y * GBM, bn = blockIdx.x * GBN;
    const int NK = K / GBK;

    uint32_t aoff[4], boff[4];
#pragma unroll
    for (int mt = 0; mt < 4; mt++)
        aoff[mt] = (uint32_t)(((wm * 64 + mt * 16 + (lane & 15)) * GSTH + ((lane >> 4) << 3)) * 2);
#pragma unroll
    for (int ntp = 0; ntp < 4; ntp++)
        boff[ntp] = (uint32_t)(((wn * 64 + ntp * 16 + (lane & 7) + ((lane >> 4) << 3)) * GSTH +
                                (((lane >> 3) & 1) << 3)) * 2);

    float acc[4][8][4];
#pragma unroll
    for (int mt = 0; mt < 4; mt++)
#pragma unroll
        for (int nt = 0; nt < 8; nt++)
#pragma unroll
            for (int r = 0; r < 4; r++) acc[mt][nt][r] = 0.f;

    auto fill = [&](int kt) {
        const int s = kt - (kt / 3) * 3;
        const int k0 = kt * GBK;
#pragma unroll
        for (int i = 0; i < 4; i++) {         // A: 128 rows x 8 chunks (16B = 8 halves)
            int ch = tid + i * 256;
            int r = ch >> 3, j = ch & 7;
            cpa16(asb + (uint32_t)((s * ASTGH + r * GSTH) * 2 + j * 16),
                  A + (size_t)(bm + r) * K + k0 + 8 * j);
        }
#pragma unroll
        for (int i = 0; i < 8; i++) {         // B: 256 rows x 8 chunks
            int ch = tid + i * 256;
            int r = ch >> 3, j = ch & 7;
            cpa16(bsb + (uint32_t)((s * BSTGH + r * GSTH) * 2 + j * 16),
                  Bt + (size_t)(bn + r) * K + k0 + 8 * j);
        }
    };

    fill(0); cpa_commit();
    fill(1); cpa_commit();

    for (int kt = 0; kt < NK; kt++) {
        cpa_wait<1>();
        __syncthreads();
        if (kt + 2 < NK) fill(kt + 2);
        cpa_commit();

        const int s = kt - (kt / 3) * 3;
        const uint32_t ab = asb + (uint32_t)(s * ASTGH * 2);
        const uint32_t bb = bsb + (uint32_t)(s * BSTGH * 2);
#pragma unroll
        for (int ks = 0; ks < 4; ks++) {      // 16 halves per step = 32 bytes
            uint32_t af[4][4], bf[8][2];
#pragma unroll
            for (int mt = 0; mt < 4; mt++)
                ldsm4(af[mt][0], af[mt][1], af[mt][2], af[mt][3], ab + aoff[mt] + ks * 32);
#pragma unroll
            for (int ntp = 0; ntp < 4; ntp++)
                ldsm4(bf[2 * ntp][0], bf[2 * ntp][1], bf[2 * ntp + 1][0], bf[2 * ntp + 1][1],
                      bb + boff[ntp] + ks * 32);
#pragma unroll
            for (int mt = 0; mt < 4; mt++)
#pragma unroll
                for (int nt = 0; nt < 8; nt++)
                    mma16(acc[mt][nt], af[mt][0], af[mt][1], af[mt][2], af[mt][3], bf[nt][0], bf[nt][1]);
        }
    }

#pragma unroll
    for (int mt = 0; mt < 4; mt++)
#pragma unroll
        for (int nt = 0; nt < 8; nt++) {
            int r = bm + wm * 64 + mt * 16 + g;
            int c = bn + wn * 64 + nt * 8 + 2 * tg;
            if constexpr (sizeof(TO) == 2) {
                *(__half2*)&C[(size_t)r * N + c] =
                    __floats2half2_rn(acc[mt][nt][0], acc[mt][nt][1]);
                *(__half2*)&C[(size_t)(r + 8) * N + c] =
                    __floats2half2_rn(acc[mt][nt][2], acc[mt][nt][3]);
            } else {
                *(float2*)&C[(size_t)r * N + c] = make_float2(acc[mt][nt][0], acc[mt][nt][1]);
                *(float2*)&C[(size_t)(r + 8) * N + c] = make_float2(acc[mt][nt][2], acc[mt][nt][3]);
            }
        }
}

// ---------------- prep kernels ----------------
__global__ void round_h(const float4* __restrict__ in, __half* __restrict__ out, int n4) {
    int i = blockIdx.x * blockDim.x + threadIdx.x;
    if (i < n4) {
        float4 v = in[i];
        __half2 lo = __floats2half2_rn(v.x, v.y);
        __half2 hi = __floats2half2_rn(v.z, v.w);
        *(uint2*)&out[i * 4] = make_uint2(*(uint32_t*)&lo, *(uint32_t*)&hi);
    }
}

// Wt[n][k] = half(W[k][n]); W is [K][N] f32
__global__ void transpose_h(const float* __restrict__ W, __half* __restrict__ Wt, int K, int N) {
    __shared__ float t[32][33];
    int kb = blockIdx.x * 32, nb = blockIdx.y * 32;
    int tx = threadIdx.x, ty = threadIdx.y;
#pragma unroll
    for (int i = 0; i < 32; i += 8)
        t[ty + i][tx] = W[(size_t)(kb + ty + i) * N + nb + tx];
    __syncthreads();
#pragma unroll
    for (int i = 0; i < 32; i += 8)
        Wt[(size_t)(nb + ty + i) * K + kb + tx] = __float2half_rn(t[tx][ty + i]);
}

// ---------------- RoPE (in place on halves, row stride QKVD) ----------------
__global__ void rope_h(__half* __restrict__ X, int nh, int total) {
    int gid = blockIdx.x * blockDim.x + threadIdx.x;
    if (gid >= total) return;
    int i = gid & 63;
    int hh = (gid >> 6) % nh;
    int bt = gid / (64 * nh);
    int t = bt % T_SEQ;

    float inv = powf(10000.0f, -((float)(2 * i)) / 128.0f);
    float ang = (float)t * inv;
    float s, c;
    sincosf(ang, &s, &c);

    size_t base = (size_t)bt * QKVD + (size_t)hh * 128 + i;
    float x1 = __half2float(X[base]);
    float x2 = __half2float(X[base + 64]);
    X[base] = __float2half_rn(x1 * c - x2 * s);
    X[base + 64] = __float2half_rn(x2 * c + x1 * s);
}

// ---------------- flash attention fp16: Br=128, register softmax ----------------
#define BQ 128
#define BKV 64
#define QSTH 136                       // 128 + 8 halves pad
#define KSTH 136
#define VSTH 136
#define PSTH 72                        // 64 + 8
#define KBUFH (BKV * KSTH)

__global__ __launch_bounds__(256, 1) void attn_h(const __half* __restrict__ QKV,
                                                 __half* __restrict__ O) {
    extern __shared__ __half smh[];
    __half* Qs = smh;                    // 128*136
    __half* Ks = Qs + BQ * QSTH;         // 2 * 64*136
    __half* Vs = Ks + 2 * KBUFH;         // 64*136
    __half* Ps = Vs + BKV * VSTH;        // 128*72
    const uint32_t qsb = s2u(Qs), ksb = s2u(Ks), vsb = s2u(Vs), psb = s2u(Ps);

    const int qt = blockIdx.x, h = blockIdx.y, b = blockIdx.z;
    const int kvh = h >> 2;
    const int tid = threadIdx.x, lane = tid & 31, warp = tid >> 5;
    const int g = lane >> 2, tg = lane & 3;
    const int wr0 = warp * 16;
    const int qrow0 = b * T_SEQ + qt * BQ;
    const float scale = 0.08838834764831845f;

    const __half* Qg = QKV + (size_t)h * 128;
    const __half* Kg = QKV + QDIM + (size_t)kvh * 128;
    const __half* Vg = QKV + 2560 + (size_t)kvh * 128;

    const uint32_t q_lo = (uint32_t)(((wr0 + (lane & 15)) * QSTH + ((lane >> 4) << 3)) * 2);
    const uint32_t p_lo = (uint32_t)(((wr0 + (lane & 15)) * PSTH + ((lane >> 4) << 3)) * 2);
    uint32_t k_lo[4];
#pragma unroll
    for (int ntp = 0; ntp < 4; ntp++)
        k_lo[ntp] = (uint32_t)(((ntp * 16 + (lane & 7) + ((lane >> 4) << 3)) * KSTH +
                                (((lane >> 3) & 1) << 3)) * 2);
    // V trans-ldmatrix lane offset (within a 16-row k-slab, per ntp pair)
    const uint32_t v_lo = (uint32_t)(((((lane >> 3) & 1) * 8 + (lane & 7)) * VSTH +
                                      ((lane >> 4) << 3)) * 2);

    auto fill_k = [&](int kt) {
        const int s = kt & 1;
        const int kr0 = b * T_SEQ + kt * BKV;
#pragma unroll
        for (int i = 0; i < 4; i++) {        // 64 rows x 16 chunks
            int ch = tid + i * 256;
            int r = ch >> 4, j = ch & 15;
            cpa16(ksb + (uint32_t)((s * KBUFH + r * KSTH) * 2 + j * 16),
                  Kg + (size_t)(kr0 + r) * QKVD + 8 * j);
        }
    };
    auto fill_v = [&](int kt) {
        const int kr0 = b * T_SEQ + kt * BKV;
#pragma unroll
        for (int i = 0; i < 4; i++) {
            int ch = tid + i * 256;
            int r = ch >> 4, j = ch & 15;
            cpa16(vsb + (uint32_t)((r * VSTH) * 2 + j * 16),
                  Vg + (size_t)(kr0 + r) * QKVD + 8 * j);
        }
    };

#pragma unroll
    for (int i = 0; i < 8; i++) {            // Q: 128 rows x 16 chunks
        int ch = tid + i * 256;
        int r = ch >> 4, j = ch & 15;
        cpa16(qsb + (uint32_t)((r * QSTH) * 2 + j * 16), Qg + (size_t)(qrow0 + r) * QKVD + 8 * j);
    }
    fill_k(0);
    cpa_commit();

    float m_lo = -INFINITY, m_hi = -INFINITY, l_lo = 0.f, l_hi = 0.f;
    float o[16][4];
#pragma unroll
    for (int nt = 0; nt < 16; nt++)
#pragma unroll
        for (int r = 0; r < 4; r++) o[nt][r] = 0.f;

    const int kmax = 2 * qt + 1;
    for (int kt = 0; kt <= kmax; kt++) {
        cpa_wait<0>();
        __syncthreads();
        fill_v(kt); cpa_commit();
        if (kt < kmax) { fill_k(kt + 1); cpa_commit(); }

        const uint32_t kb = ksb + (uint32_t)((kt & 1) * KBUFH * 2);

        // S = Q K^T : warp tile 16x64
        float sc[8][4];
#pragma unroll
        for (int nt = 0; nt < 8; nt++)
#pragma unroll
            for (int r = 0; r < 4; r++) sc[nt][r] = 0.f;
#pragma unroll
        for (int kss = 0; kss < 8; kss++) {   // 8 x 16 halves = 128
            uint32_t a0, a1, a2, a3, bf[8][2];
            ldsm4(a0, a1, a2, a3, qsb + q_lo + kss * 32);
#pragma unroll
            for (int ntp = 0; ntp < 4; ntp++)
                ldsm4(bf[2 * ntp][0], bf[2 * ntp][1], bf[2 * ntp + 1][0], bf[2 * ntp + 1][1],
                      kb + k_lo[ntp] + kss * 32);
#pragma unroll
            for (int nt = 0; nt < 8; nt++)
                mma16(sc[nt], a0, a1, a2, a3, bf[nt][0], bf[nt][1]);
        }

        // causal mask (only last two tiles are partial)
        if (kt >= 2 * qt) {
            int lim_lo = qt * BQ + wr0 + g - kt * BKV;
            int lim_hi = lim_lo + 8;
#pragma unroll
            for (int nt = 0; nt < 8; nt++) {
                int cc = nt * 8 + 2 * tg;
                if (cc     > lim_lo) sc[nt][0] = -INFINITY;
                if (cc + 1 > lim_lo) sc[nt][1] = -INFINITY;
                if (cc     > lim_hi) sc[nt][2] = -INFINITY;
                if (cc + 1 > lim_hi) sc[nt][3] = -INFINITY;
            }
        }

        // register softmax
        float mx_lo = -INFINITY, mx_hi = -INFINITY;
#pragma unroll
        for (int nt = 0; nt < 8; nt++) {
            mx_lo = fmaxf(mx_lo, fmaxf(sc[nt][0], sc[nt][1]));
            mx_hi = fmaxf(mx_hi, fmaxf(sc[nt][2], sc[nt][3]));
        }
        mx_lo = fmaxf(mx_lo, __shfl_xor_sync(0xffffffffu, mx_lo, 1));
        mx_lo = fmaxf(mx_lo, __shfl_xor_sync(0xffffffffu, mx_lo, 2));
        mx_hi = fmaxf(mx_hi, __shfl_xor_sync(0xffffffffu, mx_hi, 1));
        mx_hi = fmaxf(mx_hi, __shfl_xor_sync(0xffffffffu, mx_hi, 2));

        float mn_lo = fmaxf(m_lo, mx_lo), mn_hi = fmaxf(m_hi, mx_hi);
        float al_lo = __expf((m_lo - mn_lo) * scale);
        float al_hi = __expf((m_hi - mn_hi) * scale);
        float ls_lo = 0.f, ls_hi = 0.f;
#pragma unroll
        for (int nt = 0; nt < 8; nt++) {
            float p0 = __expf((sc[nt][0] - mn_lo) * scale);
            float p1 = __expf((sc[nt][1] - mn_lo) * scale);
            float p2 = __expf((sc[nt][2] - mn_hi) * scale);
            float p3 = __expf((sc[nt][3] - mn_hi) * scale);
            ls_lo += p0 + p1;
            ls_hi += p2 + p3;
            int cc = nt * 8 + 2 * tg;
            *(__half2*)&Ps[(wr0 + g) * PSTH + cc]     = __floats2half2_rn(p0, p1);
            *(__half2*)&Ps[(wr0 + 8 + g) * PSTH + cc] = __floats2half2_rn(p2, p3);
        }
        ls_lo += __shfl_xor_sync(0xffffffffu, ls_lo, 1);
        ls_lo += __shfl_xor_sync(0xffffffffu, ls_lo, 2);
        ls_hi += __shfl_xor_sync(0xffffffffu, ls_hi, 1);
        ls_hi += __shfl_xor_sync(0xffffffffu, ls_hi, 2);
        l_lo = l_lo * al_lo + ls_lo;
        l_hi = l_hi * al_hi + ls_hi;
        m_lo = mn_lo; m_hi = mn_hi;
        __syncwarp();

        if (kt < kmax) cpa_wait<1>(); else cpa_wait<0>();
        __syncthreads();

        // O = O*alpha + P @ V : warp tile 16x128, V via ldmatrix.trans
#pragma unroll
        for (int nt = 0; nt < 16; nt++) {
            o[nt][0] *= al_lo; o[nt][1] *= al_lo;
            o[nt][2] *= al_hi; o[nt][3] *= al_hi;
        }
#pragma unroll
        for (int kss = 0; kss < 4; kss++) {    // 4 x 16 k-rows = 64
            uint32_t a0, a1, a2, a3;
            ldsm4(a0, a1, a2, a3, psb + p_lo + kss * 32);
            const uint32_t vslab = vsb + v_lo + (uint32_t)(kss * 16 * VSTH * 2);
#pragma unroll
            for (int ntp = 0; ntp < 8; ntp++) {
                uint32_t b0, b1, b2, b3;
                ldsm4t(b0, b1, b2, b3, vslab + ntp * 32);   // 16 halves of n per pair
                mma16(o[2 * ntp],     a0, a1, a2, a3, b0, b1);
                mma16(o[2 * ntp + 1], a0, a1, a2, a3, b2, b3);
            }
        }
    }

    // epilogue (fp16 store feeds Wo GEMM)
    float li = 1.f / l_lo, lh = 1.f / l_hi;
#pragma unroll
    for (int nt = 0; nt < 16; nt++) {
        int c = h * HEAD_DIM + nt * 8 + 2 * tg;
        *(__half2*)&O[(size_t)(qrow0 + wr0 + g) * QDIM + c] =
            __floats2half2_rn(o[nt][0] * li, o[nt][1] * li);
        *(__half2*)&O[(size_t)(qrow0 + wr0 + 8 + g) * QDIM + c] =
            __floats2half2_rn(o[nt][2] * lh, o[nt][3] * lh);
    }
}

// ---------------- launch ----------------
extern "C" void kernel_launch(void* const* d_in, const int* in_sizes, int n_in,
                              void* d_out, int out_size) {
    const float* x  = (const float*)d_in[0];
    const float* Wq = (const float*)d_in[1];
    const float* Wk = (const float*)d_in[2];
    const float* Wv = (const float*)d_in[3];
    const float* Wo = (const float*)d_in[4];
    float* out = (float*)d_out;

    __half *qkv, *att, *xh, *wct, *wot;
    cudaGetSymbolAddress((void**)&qkv, g_qkv);
    cudaGetSymbolAddress((void**)&att, g_att);
    cudaGetSymbolAddress((void**)&xh, g_xh);
    cudaGetSymbolAddress((void**)&wct, g_wct);
    cudaGetSymbolAddress((void**)&wot, g_wot);

    // prep: x -> fp16; weights -> [n][k] fp16
    {
        int n4x = M_ROWS * D_MODEL / 4;
        round_h<<<(n4x + 255) / 256, 256>>>((const float4*)x, xh, n4x);
        dim3 blk(32, 8);
        transpose_h<<<dim3(D_MODEL / 32, QDIM / 32), blk>>>(Wq, wct, D_MODEL, QDIM);
        transpose_h<<<dim3(D_MODEL / 32, KVDIM / 32), blk>>>(Wk, wct + (size_t)QDIM * D_MODEL,
                                                             D_MODEL, KVDIM);
        transpose_h<<<dim3(D_MODEL / 32, KVDIM / 32), blk>>>(Wv, wct + (size_t)2560 * D_MODEL,
                                                             D_MODEL, KVDIM);
        transpose_h<<<dim3(QDIM / 32, D_MODEL / 32), blk>>>(Wo, wot, QDIM, D_MODEL);
    }

    const int GSM = 3 * (ASTGH + BSTGH) * 2;   // 165888
    cudaFuncSetAttribute(gemm_h<__half>, cudaFuncAttributeMaxDynamicSharedMemorySize, GSM);
    cudaFuncSetAttribute(gemm_h<float>, cudaFuncAttributeMaxDynamicSharedMemorySize, GSM);

    // fused QKV projection (fp16 out)
    gemm_h<__half><<<dim3(QKVD / GBN, M_ROWS / GBM), 256, GSM>>>(xh, wct, qkv, M_ROWS, QKVD, D_MODEL);

    // RoPE q/k in place
    {
        int totq = B_SZ * T_SEQ * N_HEADS * 64;
        int totk = B_SZ * T_SEQ * N_KV * 64;
        rope_h<<<(totq + 255) / 256, 256>>>(qkv, N_HEADS, totq);
        rope_h<<<(totk + 255) / 256, 256>>>(qkv + QDIM, N_KV, totk);
    }

    // attention (fp16 in/out)
    {
        const int ASM_ = (BQ * QSTH + 2 * KBUFH + BKV * VSTH + BQ * PSTH) * 2;   // 105472
        cudaFuncSetAttribute(attn_h, cudaFuncAttributeMaxDynamicSharedMemorySize, ASM_);
        attn_h<<<dim3(T_SEQ / BQ, N_HEADS, B_SZ), 256, ASM_>>>(qkv, att);
    }

    // output projection (fp32 out)
    gemm_h<float><<<dim3(D_MODEL / GBN, M_ROWS / GBM), 256, GSM>>>(att, wot, out, M_ROWS, D_MODEL, QDIM);
}

// round 9
// speedup vs baseline: 9.5760x; 1.0451x over previous
#include <cuda_runtime.h>
#include <cuda_fp16.h>
#include <math.h>
#include <stdint.h>

#define D_MODEL 2048
#define N_HEADS 16
#define N_KV 4
#define HEAD_DIM 128
#define B_SZ 2
#define T_SEQ 2048
#define M_ROWS (B_SZ * T_SEQ)          // 4096
#define QDIM (N_HEADS * HEAD_DIM)      // 2048
#define KVDIM (N_KV * HEAD_DIM)        // 512
#define QKVD (QDIM + 2 * KVDIM)        // 3072

// ---------------- scratch ----------------
__device__ __half g_qkv[M_ROWS * QKVD];
__device__ __half g_att[M_ROWS * QDIM];
__device__ __half g_xh[M_ROWS * D_MODEL];
__device__ __half g_wct[(size_t)QKVD * D_MODEL];   // concat weights [n][k], fp16
__device__ __half g_wot[(size_t)D_MODEL * QDIM];   // Wo [n][k], fp16

// ---------------- helpers ----------------
__device__ __forceinline__ uint32_t s2u(const void* p) {
    uint32_t a;
    asm("{ .reg .u64 t; cvta.to.shared.u64 t, %1; cvt.u32.u64 %0, t; }" : "=r"(a) : "l"(p));
    return a;
}
__device__ __forceinline__ void cpa16(uint32_t dst, const void* src) {
    asm volatile("cp.async.cg.shared.global [%0], [%1], 16;" :: "r"(dst), "l"(src));
}
__device__ __forceinline__ void cpa_commit() { asm volatile("cp.async.commit_group;" ::: "memory"); }
template <int N> __device__ __forceinline__ void cpa_wait() {
    asm volatile("cp.async.wait_group %0;" :: "n"(N) : "memory");
}
__device__ __forceinline__ void ldsm4(uint32_t& r0, uint32_t& r1, uint32_t& r2, uint32_t& r3,
                                      uint32_t addr) {
    asm volatile("ldmatrix.sync.aligned.m8n8.x4.shared.b16 {%0,%1,%2,%3}, [%4];"
                 : "=r"(r0), "=r"(r1), "=r"(r2), "=r"(r3) : "r"(addr));
}
__device__ __forceinline__ void ldsm4t(uint32_t& r0, uint32_t& r1, uint32_t& r2, uint32_t& r3,
                                       uint32_t addr) {
    asm volatile("ldmatrix.sync.aligned.m8n8.x4.trans.shared.b16 {%0,%1,%2,%3}, [%4];"
                 : "=r"(r0), "=r"(r1), "=r"(r2), "=r"(r3) : "r"(addr));
}
__device__ __forceinline__ void mma16(float* c, uint32_t a0, uint32_t a1, uint32_t a2, uint32_t a3,
                                      uint32_t b0, uint32_t b1) {
    asm volatile(
        "mma.sync.aligned.m16n8k16.row.col.f32.f16.f16.f32 "
        "{%0,%1,%2,%3},{%4,%5,%6,%7},{%8,%9},{%0,%1,%2,%3};"
        : "+f"(c[0]), "+f"(c[1]), "+f"(c[2]), "+f"(c[3])
        : "r"(a0), "r"(a1), "r"(a2), "r"(a3), "r"(b0), "r"(b1));
}
// two exps in one MUFU op; result is packed half2
__device__ __forceinline__ uint32_t ex2h2(float a, float b) {
    __half2 h = __floats2half2_rn(a, b);
    uint32_t r;
    asm("ex2.approx.f16x2 %0, %1;" : "=r"(r) : "r"(*(uint32_t*)&h));
    return r;
}

// ---------------- GEMM: C[M,N] = A[M,K]h @ Bt[N,K]h^T, 4-stage cp.async ----------------
#define GBM 128
#define GBN 256
#define GBK 64
#define GSTH 72
#define ASTGH (128 * GSTH)
#define BSTGH (256 * GSTH)

template <typename TO>
__global__ __launch_bounds__(256, 1) void gemm_h(const __half* __restrict__ A,
                                                 const __half* __restrict__ Bt,
                                                 TO* __restrict__ C,
                                                 int M, int N, int K) {
    extern __shared__ __half smh[];
    const uint32_t asb = s2u(smh);
    const uint32_t bsb = asb + 4 * ASTGH * 2;

    const int tid = threadIdx.x;
    const int lane = tid & 31, warp = tid >> 5;
    const int wm = warp >> 2, wn = warp & 3;
    const int g = lane >> 2, tg = lane & 3;
    const int bm = blockIdx.y * GBM, bn = blockIdx.x * GBN;
    const int NK = K / GBK;

    uint32_t aoff[4], boff[4];
#pragma unroll
    for (int mt = 0; mt < 4; mt++)
        aoff[mt] = (uint32_t)(((wm * 64 + mt * 16 + (lane & 15)) * GSTH + ((lane >> 4) << 3)) * 2);
#pragma unroll
    for (int ntp = 0; ntp < 4; ntp++)
        boff[ntp] = (uint32_t)(((wn * 64 + ntp * 16 + (lane & 7) + ((lane >> 4) << 3)) * GSTH +
                                (((lane >> 3) & 1) << 3)) * 2);

    float acc[4][8][4];
#pragma unroll
    for (int mt = 0; mt < 4; mt++)
#pragma unroll
        for (int nt = 0; nt < 8; nt++)
#pragma unroll
            for (int r = 0; r < 4; r++) acc[mt][nt][r] = 0.f;

    auto fill = [&](int kt) {
        const int s = kt & 3;
        const int k0 = kt * GBK;
#pragma unroll
        for (int i = 0; i < 4; i++) {
            int ch = tid + i * 256;
            int r = ch >> 3, j = ch & 7;
            cpa16(asb + (uint32_t)((s * ASTGH + r * GSTH) * 2 + j * 16),
                  A + (size_t)(bm + r) * K + k0 + 8 * j);
        }
#pragma unroll
        for (int i = 0; i < 8; i++) {
            int ch = tid + i * 256;
            int r = ch >> 3, j = ch & 7;
            cpa16(bsb + (uint32_t)((s * BSTGH + r * GSTH) * 2 + j * 16),
                  Bt + (size_t)(bn + r) * K + k0 + 8 * j);
        }
    };

    fill(0); cpa_commit();
    fill(1); cpa_commit();
    fill(2); cpa_commit();

    for (int kt = 0; kt < NK; kt++) {
        cpa_wait<2>();
        __syncthreads();
        if (kt + 3 < NK) fill(kt + 3);
        cpa_commit();

        const int s = kt & 3;
        const uint32_t ab = asb + (uint32_t)(s * ASTGH * 2);
        const uint32_t bb = bsb + (uint32_t)(s * BSTGH * 2);
#pragma unroll
        for (int ks = 0; ks < 4; ks++) {
            uint32_t af[4][4], bf[8][2];
#pragma unroll
            for (int mt = 0; mt < 4; mt++)
                ldsm4(af[mt][0], af[mt][1], af[mt][2], af[mt][3], ab + aoff[mt] + ks * 32);
#pragma unroll
            for (int ntp = 0; ntp < 4; ntp++)
                ldsm4(bf[2 * ntp][0], bf[2 * ntp][1], bf[2 * ntp + 1][0], bf[2 * ntp + 1][1],
                      bb + boff[ntp] + ks * 32);
#pragma unroll
            for (int mt = 0; mt < 4; mt++)
#pragma unroll
                for (int nt = 0; nt < 8; nt++)
                    mma16(acc[mt][nt], af[mt][0], af[mt][1], af[mt][2], af[mt][3], bf[nt][0], bf[nt][1]);
        }
    }

#pragma unroll
    for (int mt = 0; mt < 4; mt++)
#pragma unroll
        for (int nt = 0; nt < 8; nt++) {
            int r = bm + wm * 64 + mt * 16 + g;
            int c = bn + wn * 64 + nt * 8 + 2 * tg;
            if constexpr (sizeof(TO) == 2) {
                *(__half2*)&C[(size_t)r * N + c] =
                    __floats2half2_rn(acc[mt][nt][0], acc[mt][nt][1]);
                *(__half2*)&C[(size_t)(r + 8) * N + c] =
                    __floats2half2_rn(acc[mt][nt][2], acc[mt][nt][3]);
            } else {
                *(float2*)&C[(size_t)r * N + c] = make_float2(acc[mt][nt][0], acc[mt][nt][1]);
                *(float2*)&C[(size_t)(r + 8) * N + c] = make_float2(acc[mt][nt][2], acc[mt][nt][3]);
            }
        }
}

// ---------------- prep kernels ----------------
__global__ void round_h(const float4* __restrict__ in, __half* __restrict__ out, int n4) {
    int i = blockIdx.x * blockDim.x + threadIdx.x;
    if (i < n4) {
        float4 v = in[i];
        __half2 lo = __floats2half2_rn(v.x, v.y);
        __half2 hi = __floats2half2_rn(v.z, v.w);
        *(uint2*)&out[i * 4] = make_uint2(*(uint32_t*)&lo, *(uint32_t*)&hi);
    }
}

__global__ void transpose_h(const float* __restrict__ W, __half* __restrict__ Wt, int K, int N) {
    __shared__ float t[32][33];
    int kb = blockIdx.x * 32, nb = blockIdx.y * 32;
    int tx = threadIdx.x, ty = threadIdx.y;
#pragma unroll
    for (int i = 0; i < 32; i += 8)
        t[ty + i][tx] = W[(size_t)(kb + ty + i) * N + nb + tx];
    __syncthreads();
#pragma unroll
    for (int i = 0; i < 32; i += 8)
        Wt[(size_t)(nb + ty + i) * K + kb + tx] = __float2half_rn(t[tx][ty + i]);
}

// ---------------- RoPE: one launch covers q heads 0-15 and k heads 16-19 ----------------
__global__ void rope_h(__half* __restrict__ X, int total) {
    int gid = blockIdx.x * blockDim.x + threadIdx.x;
    if (gid >= total) return;
    int i = gid & 63;
    int hh = (gid >> 6) % 20;            // 0..15 = q heads, 16..19 = kv heads (cols contiguous)
    int bt = gid / (64 * 20);
    int t = bt % T_SEQ;

    float inv = powf(10000.0f, -((float)(2 * i)) / 128.0f);
    float ang = (float)t * inv;
    float s, c;
    sincosf(ang, &s, &c);

    size_t base = (size_t)bt * QKVD + (size_t)hh * 128 + i;
    float x1 = __half2float(X[base]);
    float x2 = __half2float(X[base + 64]);
    X[base] = __float2half_rn(x1 * c - x2 * s);
    X[base + 64] = __float2half_rn(x2 * c + x1 * s);
}

// ---------------- flash attention fp16: Br=128, Bc=128, f16x2 softmax ----------------
#define BQ 128
#define BKV 128
#define QSTH 136
#define KSTH 136
#define VSTH 136
#define PSTH 136
#define KBUFH (BKV * KSTH)

__global__ __launch_bounds__(256, 1) void attn_h(const __half* __restrict__ QKV,
                                                 __half* __restrict__ O) {
    extern __shared__ __half smh[];
    __half* Qs = smh;                    // 128*136
    __half* Ks = Qs + BQ * QSTH;         // 2 * 128*136
    __half* Vs = Ks + 2 * KBUFH;         // 128*136
    __half* Ps = Vs + BKV * VSTH;        // 128*136
    const uint32_t qsb = s2u(Qs), ksb = s2u(Ks), vsb = s2u(Vs), psb = s2u(Ps);

    const int qt = blockIdx.x, h = blockIdx.y, b = blockIdx.z;
    const int kvh = h >> 2;
    const int tid = threadIdx.x, lane = tid & 31, warp = tid >> 5;
    const int g = lane >> 2, tg = lane & 3;
    const int wr0 = warp * 16;
    const int qrow0 = b * T_SEQ + qt * BQ;
    const float scale = 0.08838834764831845f;            // 1/sqrt(128)
    const float c2 = scale * 1.4426950408889634f;        // scale * log2(e)

    const __half* Qg = QKV + (size_t)h * 128;
    const __half* Kg = QKV + QDIM + (size_t)kvh * 128;
    const __half* Vg = QKV + 2560 + (size_t)kvh * 128;

    const uint32_t q_lo = (uint32_t)(((wr0 + (lane & 15)) * QSTH + ((lane >> 4) << 3)) * 2);
    const uint32_t p_lo = (uint32_t)(((wr0 + (lane & 15)) * PSTH + ((lane >> 4) << 3)) * 2);
    const uint32_t k_lo = (uint32_t)((((lane & 7) + ((lane >> 4) << 3)) * KSTH +
                                      (((lane >> 3) & 1) << 3)) * 2);
    const uint32_t v_lo = (uint32_t)(((((lane >> 3) & 1) * 8 + (lane & 7)) * VSTH +
                                      ((lane >> 4) << 3)) * 2);

    auto fill_k = [&](int kt) {
        const int s = kt & 1;
        const int kr0 = b * T_SEQ + kt * BKV;
#pragma unroll
        for (int i = 0; i < 8; i++) {        // 128 rows x 16 chunks
            int ch = tid + i * 256;
            int r = ch >> 4, j = ch & 15;
            cpa16(ksb + (uint32_t)((s * KBUFH + r * KSTH) * 2 + j * 16),
                  Kg + (size_t)(kr0 + r) * QKVD + 8 * j);
        }
    };
    auto fill_v = [&](int kt) {
        const int kr0 = b * T_SEQ + kt * BKV;
#pragma unroll
        for (int i = 0; i < 8; i++) {
            int ch = tid + i * 256;
            int r = ch >> 4, j = ch & 15;
            cpa16(vsb + (uint32_t)((r * VSTH) * 2 + j * 16),
                  Vg + (size_t)(kr0 + r) * QKVD + 8 * j);
        }
    };

#pragma unroll
    for (int i = 0; i < 8; i++) {            // Q: 128 rows x 16 chunks
        int ch = tid + i * 256;
        int r = ch >> 4, j = ch & 15;
        cpa16(qsb + (uint32_t)((r * QSTH) * 2 + j * 16), Qg + (size_t)(qrow0 + r) * QKVD + 8 * j);
    }
    fill_k(0);
    cpa_commit();

    float m_lo = -INFINITY, m_hi = -INFINITY, l_lo = 0.f, l_hi = 0.f;
    float o[16][4];
#pragma unroll
    for (int nt = 0; nt < 16; nt++)
#pragma unroll
        for (int r = 0; r < 4; r++) o[nt][r] = 0.f;

    for (int kt = 0; kt <= qt; kt++) {
        cpa_wait<0>();
        __syncthreads();
        fill_v(kt); cpa_commit();
        if (kt < qt) { fill_k(kt + 1); cpa_commit(); }

        const uint32_t kb = ksb + (uint32_t)((kt & 1) * KBUFH * 2);

        // S = Q K^T : warp tile 16x128
        float sc[16][4];
#pragma unroll
        for (int nt = 0; nt < 16; nt++)
#pragma unroll
            for (int r = 0; r < 4; r++) sc[nt][r] = 0.f;
#pragma unroll
        for (int kss = 0; kss < 8; kss++) {
            uint32_t a0, a1, a2, a3;
            ldsm4(a0, a1, a2, a3, qsb + q_lo + kss * 32);
#pragma unroll
            for (int ntp = 0; ntp < 8; ntp++) {
                uint32_t b0, b1, b2, b3;
                ldsm4(b0, b1, b2, b3,
                      kb + k_lo + (uint32_t)(ntp * 16 * KSTH * 2) + kss * 32);
                mma16(sc[2 * ntp],     a0, a1, a2, a3, b0, b1);
                mma16(sc[2 * ntp + 1], a0, a1, a2, a3, b2, b3);
            }
        }

        // causal mask on the diagonal tile
        if (kt == qt) {
            int lim_lo = wr0 + g;
            int lim_hi = lim_lo + 8;
#pragma unroll
            for (int nt = 0; nt < 16; nt++) {
                int cc = nt * 8 + 2 * tg;
                if (cc     > lim_lo) sc[nt][0] = -INFINITY;
                if (cc + 1 > lim_lo) sc[nt][1] = -INFINITY;
                if (cc     > lim_hi) sc[nt][2] = -INFINITY;
                if (cc + 1 > lim_hi) sc[nt][3] = -INFINITY;
            }
        }

        // register softmax (f16x2 exp)
        float mx_lo = -INFINITY, mx_hi = -INFINITY;
#pragma unroll
        for (int nt = 0; nt < 16; nt++) {
            mx_lo = fmaxf(mx_lo, fmaxf(sc[nt][0], sc[nt][1]));
            mx_hi = fmaxf(mx_hi, fmaxf(sc[nt][2], sc[nt][3]));
        }
        mx_lo = fmaxf(mx_lo, __shfl_xor_sync(0xffffffffu, mx_lo, 1));
        mx_lo = fmaxf(mx_lo, __shfl_xor_sync(0xffffffffu, mx_lo, 2));
        mx_hi = fmaxf(mx_hi, __shfl_xor_sync(0xffffffffu, mx_hi, 1));
        mx_hi = fmaxf(mx_hi, __shfl_xor_sync(0xffffffffu, mx_hi, 2));

        float mn_lo = fmaxf(m_lo, mx_lo), mn_hi = fmaxf(m_hi, mx_hi);
        float al_lo = __expf((m_lo - mn_lo) * scale);
        float al_hi = __expf((m_hi - mn_hi) * scale);
        float ls_lo = 0.f, ls_hi = 0.f;
#pragma unroll
        for (int nt = 0; nt < 16; nt++) {
            uint32_t plo = ex2h2((sc[nt][0] - mn_lo) * c2, (sc[nt][1] - mn_lo) * c2);
            uint32_t phi = ex2h2((sc[nt][2] - mn_hi) * c2, (sc[nt][3] - mn_hi) * c2);
            float2 flo = __half22float2(*(__half2*)&plo);
            float2 fhi = __half22float2(*(__half2*)&phi);
            ls_lo += flo.x + flo.y;
            ls_hi += fhi.x + fhi.y;
            int cc = nt * 8 + 2 * tg;
            *(uint32_t*)&Ps[(wr0 + g) * PSTH + cc]     = plo;
            *(uint32_t*)&Ps[(wr0 + 8 + g) * PSTH + cc] = phi;
        }
        ls_lo += __shfl_xor_sync(0xffffffffu, ls_lo, 1);
        ls_lo += __shfl_xor_sync(0xffffffffu, ls_lo, 2);
        ls_hi += __shfl_xor_sync(0xffffffffu, ls_hi, 1);
        ls_hi += __shfl_xor_sync(0xffffffffu, ls_hi, 2);
        l_lo = l_lo * al_lo + ls_lo;
        l_hi = l_hi * al_hi + ls_hi;
        m_lo = mn_lo; m_hi = mn_hi;
        __syncwarp();

        if (kt < qt) cpa_wait<1>(); else cpa_wait<0>();
        __syncthreads();

        // O = O*alpha + P @ V : warp tile 16x128, V via ldmatrix.trans
#pragma unroll
        for (int nt = 0; nt < 16; nt++) {
            o[nt][0] *= al_lo; o[nt][1] *= al_lo;
            o[nt][2] *= al_hi; o[nt][3] *= al_hi;
        }
#pragma unroll
        for (int kss = 0; kss < 8; kss++) {
            uint32_t a0, a1, a2, a3;
            ldsm4(a0, a1, a2, a3, psb + p_lo + kss * 32);
            const uint32_t vslab = vsb + v_lo + (uint32_t)(kss * 16 * VSTH * 2);
#pragma unroll
            for (int ntp = 0; ntp < 8; ntp++) {
                uint32_t b0, b1, b2, b3;
                ldsm4t(b0, b1, b2, b3, vslab + ntp * 32);
                mma16(o[2 * ntp],     a0, a1, a2, a3, b0, b1);
                mma16(o[2 * ntp + 1], a0, a1, a2, a3, b2, b3);
            }
        }
    }

    // epilogue
    float li = 1.f / l_lo, lh = 1.f / l_hi;
#pragma unroll
    for (int nt = 0; nt < 16; nt++) {
        int c = h * HEAD_DIM + nt * 8 + 2 * tg;
        *(__half2*)&O[(size_t)(qrow0 + wr0 + g) * QDIM + c] =
            __floats2half2_rn(o[nt][0] * li, o[nt][1] * li);
        *(__half2*)&O[(size_t)(qrow0 + wr0 + 8 + g) * QDIM + c] =
            __floats2half2_rn(o[nt][2] * lh, o[nt][3] * lh);
    }
}

// ---------------- launch ----------------
extern "C" void kernel_launch(void* const* d_in, const int* in_sizes, int n_in,
                              void* d_out, int out_size) {
    const float* x  = (const float*)d_in[0];
    const float* Wq = (const float*)d_in[1];
    const float* Wk = (const float*)d_in[2];
    const float* Wv = (const float*)d_in[3];
    const float* Wo = (const float*)d_in[4];
    float* out = (float*)d_out;

    __half *qkv, *att, *xh, *wct, *wot;
    cudaGetSymbolAddress((void**)&qkv, g_qkv);
    cudaGetSymbolAddress((void**)&att, g_att);
    cudaGetSymbolAddress((void**)&xh, g_xh);
    cudaGetSymbolAddress((void**)&wct, g_wct);
    cudaGetSymbolAddress((void**)&wot, g_wot);

    {
        int n4x = M_ROWS * D_MODEL / 4;
        round_h<<<(n4x + 255) / 256, 256>>>((const float4*)x, xh, n4x);
        dim3 blk(32, 8);
        transpose_h<<<dim3(D_MODEL / 32, QDIM / 32), blk>>>(Wq, wct, D_MODEL, QDIM);
        transpose_h<<<dim3(D_MODEL / 32, KVDIM / 32), blk>>>(Wk, wct + (size_t)QDIM * D_MODEL,
                                                             D_MODEL, KVDIM);
        transpose_h<<<dim3(D_MODEL / 32, KVDIM / 32), blk>>>(Wv, wct + (size_t)2560 * D_MODEL,
                                                             D_MODEL, KVDIM);
        transpose_h<<<dim3(QDIM / 32, D_MODEL / 32), blk>>>(Wo, wot, QDIM, D_MODEL);
    }

    const int GSM = 4 * (ASTGH + BSTGH) * 2;   // 221184
    cudaFuncSetAttribute(gemm_h<__half>, cudaFuncAttributeMaxDynamicSharedMemorySize, GSM);
    cudaFuncSetAttribute(gemm_h<float>, cudaFuncAttributeMaxDynamicSharedMemorySize, GSM);

    gemm_h<__half><<<dim3(QKVD / GBN, M_ROWS / GBM), 256, GSM>>>(xh, wct, qkv, M_ROWS, QKVD, D_MODEL);

    {
        int tot = B_SZ * T_SEQ * 20 * 64;      // q heads + kv heads in one launch
        rope_h<<<(tot + 255) / 256, 256>>>(qkv, tot);
    }

    {
        const int ASM_ = (BQ * QSTH + 2 * KBUFH + BKV * VSTH + BQ * PSTH) * 2;   // 174080
        cudaFuncSetAttribute(attn_h, cudaFuncAttributeMaxDynamicSharedMemorySize, ASM_);
        attn_h<<<dim3(T_SEQ / BQ, N_HEADS, B_SZ), 256, ASM_>>>(qkv, att);
    }

    gemm_h<float><<<dim3(D_MODEL / GBN, M_ROWS / GBM), 256, GSM>>>(att, wot, out, M_ROWS, D_MODEL, QDIM);
}

// round 10
// speedup vs baseline: 9.9274x; 1.0367x over previous
#include <cuda_runtime.h>
#include <cuda_fp16.h>
#include <math.h>
#include <stdint.h>

#define D_MODEL 2048
#define N_HEADS 16
#define N_KV 4
#define HEAD_DIM 128
#define B_SZ 2
#define T_SEQ 2048
#define M_ROWS (B_SZ * T_SEQ)          // 4096
#define QDIM (N_HEADS * HEAD_DIM)      // 2048
#define KVDIM (N_KV * HEAD_DIM)        // 512
#define QKVD (QDIM + 2 * KVDIM)        // 3072

// ---------------- scratch ----------------
__device__ __half g_qkv[M_ROWS * QKVD];
__device__ __half g_att[M_ROWS * QDIM];
__device__ __half g_xh[M_ROWS * D_MODEL];
__device__ __half g_wct[(size_t)QKVD * D_MODEL];   // concat weights [n][k], fp16
__device__ __half g_wot[(size_t)D_MODEL * QDIM];   // Wo [n][k], fp16
__device__ float2 g_tab[T_SEQ * 64];               // rope cos/sin table

// ---------------- helpers ----------------
__device__ __forceinline__ uint32_t s2u(const void* p) {
    uint32_t a;
    asm("{ .reg .u64 t; cvta.to.shared.u64 t, %1; cvt.u32.u64 %0, t; }" : "=r"(a) : "l"(p));
    return a;
}
__device__ __forceinline__ void cpa16(uint32_t dst, const void* src) {
    asm volatile("cp.async.cg.shared.global [%0], [%1], 16;" :: "r"(dst), "l"(src));
}
__device__ __forceinline__ void cpa_commit() { asm volatile("cp.async.commit_group;" ::: "memory"); }
template <int N> __device__ __forceinline__ void cpa_wait() {
    asm volatile("cp.async.wait_group %0;" :: "n"(N) : "memory");
}
__device__ __forceinline__ void ldsm4(uint32_t& r0, uint32_t& r1, uint32_t& r2, uint32_t& r3,
                                      uint32_t addr) {
    asm volatile("ldmatrix.sync.aligned.m8n8.x4.shared.b16 {%0,%1,%2,%3}, [%4];"
                 : "=r"(r0), "=r"(r1), "=r"(r2), "=r"(r3) : "r"(addr));
}
__device__ __forceinline__ void ldsm4t(uint32_t& r0, uint32_t& r1, uint32_t& r2, uint32_t& r3,
                                       uint32_t addr) {
    asm volatile("ldmatrix.sync.aligned.m8n8.x4.trans.shared.b16 {%0,%1,%2,%3}, [%4];"
                 : "=r"(r0), "=r"(r1), "=r"(r2), "=r"(r3) : "r"(addr));
}
__device__ __forceinline__ void mma16(float* c, uint32_t a0, uint32_t a1, uint32_t a2, uint32_t a3,
                                      uint32_t b0, uint32_t b1) {
    asm volatile(
        "mma.sync.aligned.m16n8k16.row.col.f32.f16.f16.f32 "
        "{%0,%1,%2,%3},{%4,%5,%6,%7},{%8,%9},{%0,%1,%2,%3};"
        : "+f"(c[0]), "+f"(c[1]), "+f"(c[2]), "+f"(c[3])
        : "r"(a0), "r"(a1), "r"(a2), "r"(a3), "r"(b0), "r"(b1));
}
__device__ __forceinline__ uint32_t ex2h2(float a, float b) {
    __half2 h = __floats2half2_rn(a, b);
    uint32_t r;
    asm("ex2.approx.f16x2 %0, %1;" : "=r"(r) : "r"(*(uint32_t*)&h));
    return r;
}

// ---------------- GEMM: 128x128 CTA tile, 64x32 warp tile, 3-stage, 2 CTAs/SM ----------------
#define GBM 128
#define GBN 128
#define GBK 64
#define GSTH 72
#define ASTGH (128 * GSTH)
#define BSTGH (128 * GSTH)

template <typename TO>
__global__ __launch_bounds__(256, 2) void gemm_h(const __half* __restrict__ A,
                                                 const __half* __restrict__ Bt,
                                                 TO* __restrict__ C,
                                                 int M, int N, int K) {
    extern __shared__ __half smh[];
    const uint32_t asb = s2u(smh);
    const uint32_t bsb = asb + 3 * ASTGH * 2;

    const int tid = threadIdx.x;
    const int lane = tid & 31, warp = tid >> 5;
    const int wm = warp >> 2, wn = warp & 3;    // 2 x 4 warps, warp tile 64x32
    const int g = lane >> 2, tg = lane & 3;
    const int bm = blockIdx.y * GBM, bn = blockIdx.x * GBN;
    const int NK = K / GBK;

    uint32_t aoff[4], boff[2];
#pragma unroll
    for (int mt = 0; mt < 4; mt++)
        aoff[mt] = (uint32_t)(((wm * 64 + mt * 16 + (lane & 15)) * GSTH + ((lane >> 4) << 3)) * 2);
#pragma unroll
    for (int ntp = 0; ntp < 2; ntp++)
        boff[ntp] = (uint32_t)(((wn * 32 + ntp * 16 + (lane & 7) + ((lane >> 4) << 3)) * GSTH +
                                (((lane >> 3) & 1) << 3)) * 2);

    float acc[4][4][4];
#pragma unroll
    for (int mt = 0; mt < 4; mt++)
#pragma unroll
        for (int nt = 0; nt < 4; nt++)
#pragma unroll
            for (int r = 0; r < 4; r++) acc[mt][nt][r] = 0.f;

    auto fill = [&](int kt) {
        const int s = kt - (kt / 3) * 3;
        const int k0 = kt * GBK;
#pragma unroll
        for (int i = 0; i < 4; i++) {           // A: 128 rows x 8 chunks
            int ch = tid + i * 256;
            int r = ch >> 3, j = ch & 7;
            cpa16(asb + (uint32_t)((s * ASTGH + r * GSTH) * 2 + j * 16),
                  A + (size_t)(bm + r) * K + k0 + 8 * j);
        }
#pragma unroll
        for (int i = 0; i < 4; i++) {           // B: 128 rows x 8 chunks
            int ch = tid + i * 256;
            int r = ch >> 3, j = ch & 7;
            cpa16(bsb + (uint32_t)((s * BSTGH + r * GSTH) * 2 + j * 16),
                  Bt + (size_t)(bn + r) * K + k0 + 8 * j);
        }
    };

    fill(0); cpa_commit();
    fill(1); cpa_commit();

    for (int kt = 0; kt < NK; kt++) {
        cpa_wait<1>();
        __syncthreads();
        if (kt + 2 < NK) fill(kt + 2);
        cpa_commit();

        const int s = kt - (kt / 3) * 3;
        const uint32_t ab = asb + (uint32_t)(s * ASTGH * 2);
        const uint32_t bb = bsb + (uint32_t)(s * BSTGH * 2);
#pragma unroll
        for (int ks = 0; ks < 4; ks++) {
            uint32_t af[4][4], bf[4][2];
#pragma unroll
            for (int mt = 0; mt < 4; mt++)
                ldsm4(af[mt][0], af[mt][1], af[mt][2], af[mt][3], ab + aoff[mt] + ks * 32);
#pragma unroll
            for (int ntp = 0; ntp < 2; ntp++)
                ldsm4(bf[2 * ntp][0], bf[2 * ntp][1], bf[2 * ntp + 1][0], bf[2 * ntp + 1][1],
                      bb + boff[ntp] + ks * 32);
#pragma unroll
            for (int mt = 0; mt < 4; mt++)
#pragma unroll
                for (int nt = 0; nt < 4; nt++)
                    mma16(acc[mt][nt], af[mt][0], af[mt][1], af[mt][2], af[mt][3], bf[nt][0], bf[nt][1]);
        }
    }

#pragma unroll
    for (int mt = 0; mt < 4; mt++)
#pragma unroll
        for (int nt = 0; nt < 4; nt++) {
            int r = bm + wm * 64 + mt * 16 + g;
            int c = bn + wn * 32 + nt * 8 + 2 * tg;
            if constexpr (sizeof(TO) == 2) {
                *(__half2*)&C[(size_t)r * N + c] =
                    __floats2half2_rn(acc[mt][nt][0], acc[mt][nt][1]);
                *(__half2*)&C[(size_t)(r + 8) * N + c] =
                    __floats2half2_rn(acc[mt][nt][2], acc[mt][nt][3]);
            } else {
                *(float2*)&C[(size_t)r * N + c] = make_float2(acc[mt][nt][0], acc[mt][nt][1]);
                *(float2*)&C[(size_t)(r + 8) * N + c] = make_float2(acc[mt][nt][2], acc[mt][nt][3]);
            }
        }
}

// ---------------- prep kernels ----------------
__global__ void round_h(const float4* __restrict__ in, __half* __restrict__ out, int n4) {
    int i = blockIdx.x * blockDim.x + threadIdx.x;
    if (i < n4) {
        float4 v = in[i];
        __half2 lo = __floats2half2_rn(v.x, v.y);
        __half2 hi = __floats2half2_rn(v.z, v.w);
        *(uint2*)&out[i * 4] = make_uint2(*(uint32_t*)&lo, *(uint32_t*)&hi);
    }
}

__global__ void transpose_h(const float* __restrict__ W, __half* __restrict__ Wt, int K, int N) {
    __shared__ float t[32][33];
    int kb = blockIdx.x * 32, nb = blockIdx.y * 32;
    int tx = threadIdx.x, ty = threadIdx.y;
#pragma unroll
    for (int i = 0; i < 32; i += 8)
        t[ty + i][tx] = W[(size_t)(kb + ty + i) * N + nb + tx];
    __syncthreads();
#pragma unroll
    for (int i = 0; i < 32; i += 8)
        Wt[(size_t)(nb + ty + i) * K + kb + tx] = __float2half_rn(t[tx][ty + i]);
}

// rope table: cos/sin(t * 10000^{-2i/128}), identical math to the old rope kernel
__global__ void build_tab() {
    int gid = blockIdx.x * blockDim.x + threadIdx.x;
    if (gid >= T_SEQ * 64) return;
    int i = gid & 63;
    int t = gid >> 6;
    float inv = powf(10000.0f, -((float)(2 * i)) / 128.0f);
    float ang = (float)t * inv;
    float s, c;
    sincosf(ang, &s, &c);
    g_tab[gid] = make_float2(c, s);
}

// ---------------- RoPE via table: q heads 0-15 and k heads 16-19 in one launch ----------------
__global__ void rope_h(__half* __restrict__ X, int total) {
    int gid = blockIdx.x * blockDim.x + threadIdx.x;
    if (gid >= total) return;
    int i = gid & 63;
    int hh = (gid >> 6) % 20;
    int bt = gid / (64 * 20);
    int t = bt % T_SEQ;

    float2 cs = g_tab[t * 64 + i];

    size_t base = (size_t)bt * QKVD + (size_t)hh * 128 + i;
    float x1 = __half2float(X[base]);
    float x2 = __half2float(X[base + 64]);
    X[base] = __float2half_rn(x1 * cs.x - x2 * cs.y);
    X[base + 64] = __float2half_rn(x2 * cs.x + x1 * cs.y);
}

// ---------------- flash attention fp16: Br=128, Bc=128, f16x2 softmax ----------------
#define BQ 128
#define BKV 128
#define QSTH 136
#define KSTH 136
#define VSTH 136
#define PSTH 136
#define KBUFH (BKV * KSTH)

__global__ __launch_bounds__(256, 1) void attn_h(const __half* __restrict__ QKV,
                                                 __half* __restrict__ O) {
    extern __shared__ __half smh[];
    __half* Qs = smh;                    // 128*136
    __half* Ks = Qs + BQ * QSTH;         // 2 * 128*136
    __half* Vs = Ks + 2 * KBUFH;         // 128*136
    __half* Ps = Vs + BKV * VSTH;        // 128*136
    const uint32_t qsb = s2u(Qs), ksb = s2u(Ks), vsb = s2u(Vs), psb = s2u(Ps);

    const int qt = blockIdx.x, h = blockIdx.y, b = blockIdx.z;
    const int kvh = h >> 2;
    const int tid = threadIdx.x, lane = tid & 31, warp = tid >> 5;
    const int g = lane >> 2, tg = lane & 3;
    const int wr0 = warp * 16;
    const int qrow0 = b * T_SEQ + qt * BQ;
    const float scale = 0.08838834764831845f;
    const float c2 = scale * 1.4426950408889634f;

    const __half* Qg = QKV + (size_t)h * 128;
    const __half* Kg = QKV + QDIM + (size_t)kvh * 128;
    const __half* Vg = QKV + 2560 + (size_t)kvh * 128;

    const uint32_t q_lo = (uint32_t)(((wr0 + (lane & 15)) * QSTH + ((lane >> 4) << 3)) * 2);
    const uint32_t p_lo = (uint32_t)(((wr0 + (lane & 15)) * PSTH + ((lane >> 4) << 3)) * 2);
    const uint32_t k_lo = (uint32_t)((((lane & 7) + ((lane >> 4) << 3)) * KSTH +
                                      (((lane >> 3) & 1) << 3)) * 2);
    const uint32_t v_lo = (uint32_t)(((((lane >> 3) & 1) * 8 + (lane & 7)) * VSTH +
                                      ((lane >> 4) << 3)) * 2);

    auto fill_k = [&](int kt) {
        const int s = kt & 1;
        const int kr0 = b * T_SEQ + kt * BKV;
#pragma unroll
        for (int i = 0; i < 8; i++) {
            int ch = tid + i * 256;
            int r = ch >> 4, j = ch & 15;
            cpa16(ksb + (uint32_t)((s * KBUFH + r * KSTH) * 2 + j * 16),
                  Kg + (size_t)(kr0 + r) * QKVD + 8 * j);
        }
    };
    auto fill_v = [&](int kt) {
        const int kr0 = b * T_SEQ + kt * BKV;
#pragma unroll
        for (int i = 0; i < 8; i++) {
            int ch = tid + i * 256;
            int r = ch >> 4, j = ch & 15;
            cpa16(vsb + (uint32_t)((r * VSTH) * 2 + j * 16),
                  Vg + (size_t)(kr0 + r) * QKVD + 8 * j);
        }
    };

#pragma unroll
    for (int i = 0; i < 8; i++) {
        int ch = tid + i * 256;
        int r = ch >> 4, j = ch & 15;
        cpa16(qsb + (uint32_t)((r * QSTH) * 2 + j * 16), Qg + (size_t)(qrow0 + r) * QKVD + 8 * j);
    }
    fill_k(0);
    cpa_commit();

    float m_lo = -INFINITY, m_hi = -INFINITY, l_lo = 0.f, l_hi = 0.f;
    float o[16][4];
#pragma unroll
    for (int nt = 0; nt < 16; nt++)
#pragma unroll
        for (int r = 0; r < 4; r++) o[nt][r] = 0.f;

    for (int kt = 0; kt <= qt; kt++) {
        cpa_wait<0>();
        __syncthreads();
        fill_v(kt); cpa_commit();
        if (kt < qt) { fill_k(kt + 1); cpa_commit(); }

        const uint32_t kb = ksb + (uint32_t)((kt & 1) * KBUFH * 2);

        float sc[16][4];
#pragma unroll
        for (int nt = 0; nt < 16; nt++)
#pragma unroll
            for (int r = 0; r < 4; r++) sc[nt][r] = 0.f;
#pragma unroll
        for (int kss = 0; kss < 8; kss++) {
            uint32_t a0, a1, a2, a3;
            ldsm4(a0, a1, a2, a3, qsb + q_lo + kss * 32);
#pragma unroll
            for (int ntp = 0; ntp < 8; ntp++) {
                uint32_t b0, b1, b2, b3;
                ldsm4(b0, b1, b2, b3,
                      kb + k_lo + (uint32_t)(ntp * 16 * KSTH * 2) + kss * 32);
                mma16(sc[2 * ntp],     a0, a1, a2, a3, b0, b1);
                mma16(sc[2 * ntp + 1], a0, a1, a2, a3, b2, b3);
            }
        }

        if (kt == qt) {
            int lim_lo = wr0 + g;
            int lim_hi = lim_lo + 8;
#pragma unroll
            for (int nt = 0; nt < 16; nt++) {
                int cc = nt * 8 + 2 * tg;
                if (cc     > lim_lo) sc[nt][0] = -INFINITY;
                if (cc + 1 > lim_lo) sc[nt][1] = -INFINITY;
                if (cc     > lim_hi) sc[nt][2] = -INFINITY;
                if (cc + 1 > lim_hi) sc[nt][3] = -INFINITY;
            }
        }

        float mx_lo = -INFINITY, mx_hi = -INFINITY;
#pragma unroll
        for (int nt = 0; nt < 16; nt++) {
            mx_lo = fmaxf(mx_lo, fmaxf(sc[nt][0], sc[nt][1]));
            mx_hi = fmaxf(mx_hi, fmaxf(sc[nt][2], sc[nt][3]));
        }
        mx_lo = fmaxf(mx_lo, __shfl_xor_sync(0xffffffffu, mx_lo, 1));
        mx_lo = fmaxf(mx_lo, __shfl_xor_sync(0xffffffffu, mx_lo, 2));
        mx_hi = fmaxf(mx_hi, __shfl_xor_sync(0xffffffffu, mx_hi, 1));
        mx_hi = fmaxf(mx_hi, __shfl_xor_sync(0xffffffffu, mx_hi, 2));

        float mn_lo = fmaxf(m_lo, mx_lo), mn_hi = fmaxf(m_hi, mx_hi);
        float al_lo = __expf((m_lo - mn_lo) * scale);
        float al_hi = __expf((m_hi - mn_hi) * scale);
        float ls_lo = 0.f, ls_hi = 0.f;
#pragma unroll
        for (int nt = 0; nt < 16; nt++) {
            uint32_t plo = ex2h2((sc[nt][0] - mn_lo) * c2, (sc[nt][1] - mn_lo) * c2);
            uint32_t phi = ex2h2((sc[nt][2] - mn_hi) * c2, (sc[nt][3] - mn_hi) * c2);
            float2 flo = __half22float2(*(__half2*)&plo);
            float2 fhi = __half22float2(*(__half2*)&phi);
            ls_lo += flo.x + flo.y;
            ls_hi += fhi.x + fhi.y;
            int cc = nt * 8 + 2 * tg;
            *(uint32_t*)&Ps[(wr0 + g) * PSTH + cc]     = plo;
            *(uint32_t*)&Ps[(wr0 + 8 + g) * PSTH + cc] = phi;
        }
        ls_lo += __shfl_xor_sync(0xffffffffu, ls_lo, 1);
        ls_lo += __shfl_xor_sync(0xffffffffu, ls_lo, 2);
        ls_hi += __shfl_xor_sync(0xffffffffu, ls_hi, 1);
        ls_hi += __shfl_xor_sync(0xffffffffu, ls_hi, 2);
        l_lo = l_lo * al_lo + ls_lo;
        l_hi = l_hi * al_hi + ls_hi;
        m_lo = mn_lo; m_hi = mn_hi;
        __syncwarp();

        if (kt < qt) cpa_wait<1>(); else cpa_wait<0>();
        __syncthreads();

#pragma unroll
        for (int nt = 0; nt < 16; nt++) {
            o[nt][0] *= al_lo; o[nt][1] *= al_lo;
            o[nt][2] *= al_hi; o[nt][3] *= al_hi;
        }
#pragma unroll
        for (int kss = 0; kss < 8; kss++) {
            uint32_t a0, a1, a2, a3;
            ldsm4(a0, a1, a2, a3, psb + p_lo + kss * 32);
            const uint32_t vslab = vsb + v_lo + (uint32_t)(kss * 16 * VSTH * 2);
#pragma unroll
            for (int ntp = 0; ntp < 8; ntp++) {
                uint32_t b0, b1, b2, b3;
                ldsm4t(b0, b1, b2, b3, vslab + ntp * 32);
                mma16(o[2 * ntp],     a0, a1, a2, a3, b0, b1);
                mma16(o[2 * ntp + 1], a0, a1, a2, a3, b2, b3);
            }
        }
    }

    float li = 1.f / l_lo, lh = 1.f / l_hi;
#pragma unroll
    for (int nt = 0; nt < 16; nt++) {
        int c = h * HEAD_DIM + nt * 8 + 2 * tg;
        *(__half2*)&O[(size_t)(qrow0 + wr0 + g) * QDIM + c] =
            __floats2half2_rn(o[nt][0] * li, o[nt][1] * li);
        *(__half2*)&O[(size_t)(qrow0 + wr0 + 8 + g) * QDIM + c] =
            __floats2half2_rn(o[nt][2] * lh, o[nt][3] * lh);
    }
}

// ---------------- launch ----------------
extern "C" void kernel_launch(void* const* d_in, const int* in_sizes, int n_in,
                              void* d_out, int out_size) {
    const float* x  = (const float*)d_in[0];
    const float* Wq = (const float*)d_in[1];
    const float* Wk = (const float*)d_in[2];
    const float* Wv = (const float*)d_in[3];
    const float* Wo = (const float*)d_in[4];
    float* out = (float*)d_out;

    __half *qkv, *att, *xh, *wct, *wot;
    cudaGetSymbolAddress((void**)&qkv, g_qkv);
    cudaGetSymbolAddress((void**)&att, g_att);
    cudaGetSymbolAddress((void**)&xh, g_xh);
    cudaGetSymbolAddress((void**)&wct, g_wct);
    cudaGetSymbolAddress((void**)&wot, g_wot);

    {
        int n4x = M_ROWS * D_MODEL / 4;
        round_h<<<(n4x + 255) / 256, 256>>>((const float4*)x, xh, n4x);
        build_tab<<<(T_SEQ * 64 + 255) / 256, 256>>>();
        dim3 blk(32, 8);
        transpose_h<<<dim3(D_MODEL / 32, QDIM / 32), blk>>>(Wq, wct, D_MODEL, QDIM);
        transpose_h<<<dim3(D_MODEL / 32, KVDIM / 32), blk>>>(Wk, wct + (size_t)QDIM * D_MODEL,
                                                             D_MODEL, KVDIM);
        transpose_h<<<dim3(D_MODEL / 32, KVDIM / 32), blk>>>(Wv, wct + (size_t)2560 * D_MODEL,
                                                             D_MODEL, KVDIM);
        transpose_h<<<dim3(QDIM / 32, D_MODEL / 32), blk>>>(Wo, wot, QDIM, D_MODEL);
    }

    const int GSM = 3 * (ASTGH + BSTGH) * 2;   // 110592
    cudaFuncSetAttribute(gemm_h<__half>, cudaFuncAttributeMaxDynamicSharedMemorySize, GSM);
    cudaFuncSetAttribute(gemm_h<float>, cudaFuncAttributeMaxDynamicSharedMemorySize, GSM);

    gemm_h<__half><<<dim3(QKVD / GBN, M_ROWS / GBM), 256, GSM>>>(xh, wct, qkv, M_ROWS, QKVD, D_MODEL);

    {
        int tot = B_SZ * T_SEQ * 20 * 64;
        rope_h<<<(tot + 255) / 256, 256>>>(qkv, tot);
    }

    {
        const int ASM_ = (BQ * QSTH + 2 * KBUFH + BKV * VSTH + BQ * PSTH) * 2;   // 174080
        cudaFuncSetAttribute(attn_h, cudaFuncAttributeMaxDynamicSharedMemorySize, ASM_);
        attn_h<<<dim3(T_SEQ / BQ, N_HEADS, B_SZ), 256, ASM_>>>(qkv, att);
    }

    gemm_h<float><<<dim3(D_MODEL / GBN, M_ROWS / GBM), 256, GSM>>>(att, wot, out, M_ROWS, D_MODEL, QDIM);
}

// round 11
// speedup vs baseline: 10.0615x; 1.0135x over previous
#include <cuda_runtime.h>
#include <cuda_fp16.h>
#include <math.h>
#include <stdint.h>

#define D_MODEL 2048
#define N_HEADS 16
#define N_KV 4
#define HEAD_DIM 128
#define B_SZ 2
#define T_SEQ 2048
#define M_ROWS (B_SZ * T_SEQ)          // 4096
#define QDIM (N_HEADS * HEAD_DIM)      // 2048
#define KVDIM (N_KV * HEAD_DIM)        // 512
#define QKVD (QDIM + 2 * KVDIM)        // 3072

// ---------------- scratch ----------------
__device__ __half g_qkv[M_ROWS * QKVD];
__device__ __half g_att[M_ROWS * QDIM];
__device__ __half g_xh[M_ROWS * D_MODEL];
__device__ __half g_wct[(size_t)QKVD * D_MODEL];   // concat weights [n][k], fp16
__device__ __half g_wot[(size_t)D_MODEL * QDIM];   // Wo [n][k], fp16
__device__ float2 g_tab[T_SEQ * 64];               // rope cos/sin table

// ---------------- helpers ----------------
__device__ __forceinline__ uint32_t s2u(const void* p) {
    uint32_t a;
    asm("{ .reg .u64 t; cvta.to.shared.u64 t, %1; cvt.u32.u64 %0, t; }" : "=r"(a) : "l"(p));
    return a;
}
__device__ __forceinline__ void cpa16(uint32_t dst, const void* src) {
    asm volatile("cp.async.cg.shared.global [%0], [%1], 16;" :: "r"(dst), "l"(src));
}
__device__ __forceinline__ void cpa_commit() { asm volatile("cp.async.commit_group;" ::: "memory"); }
template <int N> __device__ __forceinline__ void cpa_wait() {
    asm volatile("cp.async.wait_group %0;" :: "n"(N) : "memory");
}
__device__ __forceinline__ void ldsm4(uint32_t& r0, uint32_t& r1, uint32_t& r2, uint32_t& r3,
                                      uint32_t addr) {
    asm volatile("ldmatrix.sync.aligned.m8n8.x4.shared.b16 {%0,%1,%2,%3}, [%4];"
                 : "=r"(r0), "=r"(r1), "=r"(r2), "=r"(r3) : "r"(addr));
}
__device__ __forceinline__ void ldsm4t(uint32_t& r0, uint32_t& r1, uint32_t& r2, uint32_t& r3,
                                       uint32_t addr) {
    asm volatile("ldmatrix.sync.aligned.m8n8.x4.trans.shared.b16 {%0,%1,%2,%3}, [%4];"
                 : "=r"(r0), "=r"(r1), "=r"(r2), "=r"(r3) : "r"(addr));
}
__device__ __forceinline__ void mma16(float* c, uint32_t a0, uint32_t a1, uint32_t a2, uint32_t a3,
                                      uint32_t b0, uint32_t b1) {
    asm volatile(
        "mma.sync.aligned.m16n8k16.row.col.f32.f16.f16.f32 "
        "{%0,%1,%2,%3},{%4,%5,%6,%7},{%8,%9},{%0,%1,%2,%3};"
        : "+f"(c[0]), "+f"(c[1]), "+f"(c[2]), "+f"(c[3])
        : "r"(a0), "r"(a1), "r"(a2), "r"(a3), "r"(b0), "r"(b1));
}
__device__ __forceinline__ uint32_t ex2h2(float a, float b) {
    __half2 h = __floats2half2_rn(a, b);
    uint32_t r;
    asm("ex2.approx.f16x2 %0, %1;" : "=r"(r) : "r"(*(uint32_t*)&h));
    return r;
}

// ---------------- GEMM: 128x128 CTA tile, 64x32 warp tile, 3-stage, 2 CTAs/SM ----------------
#define GBM 128
#define GBN 128
#define GBK 64
#define GSTH 72
#define ASTGH (128 * GSTH)
#define BSTGH (128 * GSTH)

template <typename TO>
__global__ __launch_bounds__(256, 2) void gemm_h(const __half* __restrict__ A,
                                                 const __half* __restrict__ Bt,
                                                 TO* __restrict__ C,
                                                 int M, int N, int K) {
    extern __shared__ __half smh[];
    const uint32_t asb = s2u(smh);
    const uint32_t bsb = asb + 3 * ASTGH * 2;

    const int tid = threadIdx.x;
    const int lane = tid & 31, warp = tid >> 5;
    const int wm = warp >> 2, wn = warp & 3;
    const int g = lane >> 2, tg = lane & 3;
    const int bm = blockIdx.y * GBM, bn = blockIdx.x * GBN;
    const int NK = K / GBK;

    uint32_t aoff[4], boff[2];
#pragma unroll
    for (int mt = 0; mt < 4; mt++)
        aoff[mt] = (uint32_t)(((wm * 64 + mt * 16 + (lane & 15)) * GSTH + ((lane >> 4) << 3)) * 2);
#pragma unroll
    for (int ntp = 0; ntp < 2; ntp++)
        boff[ntp] = (uint32_t)(((wn * 32 + ntp * 16 + (lane & 7) + ((lane >> 4) << 3)) * GSTH +
                                (((lane >> 3) & 1) << 3)) * 2);

    float acc[4][4][4];
#pragma unroll
    for (int mt = 0; mt < 4; mt++)
#pragma unroll
        for (int nt = 0; nt < 4; nt++)
#pragma unroll
            for (int r = 0; r < 4; r++) acc[mt][nt][r] = 0.f;

    auto fill = [&](int kt) {
        const int s = kt - (kt / 3) * 3;
        const int k0 = kt * GBK;
#pragma unroll
        for (int i = 0; i < 4; i++) {
            int ch = tid + i * 256;
            int r = ch >> 3, j = ch & 7;
            cpa16(asb + (uint32_t)((s * ASTGH + r * GSTH) * 2 + j * 16),
                  A + (size_t)(bm + r) * K + k0 + 8 * j);
        }
#pragma unroll
        for (int i = 0; i < 4; i++) {
            int ch = tid + i * 256;
            int r = ch >> 3, j = ch & 7;
            cpa16(bsb + (uint32_t)((s * BSTGH + r * GSTH) * 2 + j * 16),
                  Bt + (size_t)(bn + r) * K + k0 + 8 * j);
        }
    };

    fill(0); cpa_commit();
    fill(1); cpa_commit();

    for (int kt = 0; kt < NK; kt++) {
        cpa_wait<1>();
        __syncthreads();
        if (kt + 2 < NK) fill(kt + 2);
        cpa_commit();

        const int s = kt - (kt / 3) * 3;
        const uint32_t ab = asb + (uint32_t)(s * ASTGH * 2);
        const uint32_t bb = bsb + (uint32_t)(s * BSTGH * 2);
#pragma unroll
        for (int ks = 0; ks < 4; ks++) {
            uint32_t af[4][4], bf[4][2];
#pragma unroll
            for (int mt = 0; mt < 4; mt++)
                ldsm4(af[mt][0], af[mt][1], af[mt][2], af[mt][3], ab + aoff[mt] + ks * 32);
#pragma unroll
            for (int ntp = 0; ntp < 2; ntp++)
                ldsm4(bf[2 * ntp][0], bf[2 * ntp][1], bf[2 * ntp + 1][0], bf[2 * ntp + 1][1],
                      bb + boff[ntp] + ks * 32);
#pragma unroll
            for (int mt = 0; mt < 4; mt++)
#pragma unroll
                for (int nt = 0; nt < 4; nt++)
                    mma16(acc[mt][nt], af[mt][0], af[mt][1], af[mt][2], af[mt][3], bf[nt][0], bf[nt][1]);
        }
    }

#pragma unroll
    for (int mt = 0; mt < 4; mt++)
#pragma unroll
        for (int nt = 0; nt < 4; nt++) {
            int r = bm + wm * 64 + mt * 16 + g;
            int c = bn + wn * 32 + nt * 8 + 2 * tg;
            if constexpr (sizeof(TO) == 2) {
                *(__half2*)&C[(size_t)r * N + c] =
                    __floats2half2_rn(acc[mt][nt][0], acc[mt][nt][1]);
                *(__half2*)&C[(size_t)(r + 8) * N + c] =
                    __floats2half2_rn(acc[mt][nt][2], acc[mt][nt][3]);
            } else {
                *(float2*)&C[(size_t)r * N + c] = make_float2(acc[mt][nt][0], acc[mt][nt][1]);
                *(float2*)&C[(size_t)(r + 8) * N + c] = make_float2(acc[mt][nt][2], acc[mt][nt][3]);
            }
        }
}

// ---------------- prep kernels ----------------
__global__ void round_h(const float4* __restrict__ in, __half* __restrict__ out, int n4) {
    int i = blockIdx.x * blockDim.x + threadIdx.x;
    if (i < n4) {
        float4 v = in[i];
        __half2 lo = __floats2half2_rn(v.x, v.y);
        __half2 hi = __floats2half2_rn(v.z, v.w);
        *(uint2*)&out[i * 4] = make_uint2(*(uint32_t*)&lo, *(uint32_t*)&hi);
    }
}

__device__ __forceinline__ void do_transpose(const float* W, __half* Wt, int K, int N,
                                             int kb, int nb, int tx, int ty) {
    __shared__ float t[32][33];
#pragma unroll
    for (int i = 0; i < 32; i += 8)
        t[ty + i][tx] = W[(size_t)(kb + ty + i) * N + nb + tx];
    __syncthreads();
#pragma unroll
    for (int i = 0; i < 32; i += 8)
        Wt[(size_t)(nb + ty + i) * K + kb + tx] = __float2half_rn(t[tx][ty + i]);
}

// all 4 weight transposes in one launch: 10240 blocks of (32,8)
__global__ void transpose_all(const float* __restrict__ Wq, const float* __restrict__ Wk,
                              const float* __restrict__ Wv, const float* __restrict__ Wo,
                              __half* __restrict__ wct, __half* __restrict__ wot) {
    int bid = blockIdx.x;
    int tx = threadIdx.x, ty = threadIdx.y;
    if (bid < 4096) {                                    // Wq: 64x64 blocks
        do_transpose(Wq, wct, D_MODEL, QDIM, (bid & 63) * 32, (bid >> 6) * 32, tx, ty);
    } else if (bid < 5120) {                             // Wk: 64x16
        int l = bid - 4096;
        do_transpose(Wk, wct + (size_t)QDIM * D_MODEL, D_MODEL, KVDIM,
                     (l & 63) * 32, (l >> 6) * 32, tx, ty);
    } else if (bid < 6144) {                             // Wv: 64x16
        int l = bid - 5120;
        do_transpose(Wv, wct + (size_t)2560 * D_MODEL, D_MODEL, KVDIM,
                     (l & 63) * 32, (l >> 6) * 32, tx, ty);
    } else {                                             // Wo: 64x64
        int l = bid - 6144;
        do_transpose(Wo, wot, QDIM, D_MODEL, (l & 63) * 32, (l >> 6) * 32, tx, ty);
    }
}

__global__ void build_tab() {
    int gid = blockIdx.x * blockDim.x + threadIdx.x;
    if (gid >= T_SEQ * 64) return;
    int i = gid & 63;
    int t = gid >> 6;
    float inv = powf(10000.0f, -((float)(2 * i)) / 128.0f);
    float ang = (float)t * inv;
    float s, c;
    sincosf(ang, &s, &c);
    g_tab[gid] = make_float2(c, s);
}

__global__ void rope_h(__half* __restrict__ X, int total) {
    int gid = blockIdx.x * blockDim.x + threadIdx.x;
    if (gid >= total) return;
    int i = gid & 63;
    int hh = (gid >> 6) % 20;
    int bt = gid / (64 * 20);
    int t = bt % T_SEQ;

    float2 cs = g_tab[t * 64 + i];

    size_t base = (size_t)bt * QKVD + (size_t)hh * 128 + i;
    float x1 = __half2float(X[base]);
    float x2 = __half2float(X[base + 64]);
    X[base] = __float2half_rn(x1 * cs.x - x2 * cs.y);
    X[base + 64] = __float2half_rn(x2 * cs.x + x1 * cs.y);
}

// ---------------- flash attention fp16: Br=128, Bc=64, P kept in registers ----------------
#define BQ 128
#define BKV 64
#define QSTH 136
#define KSTH 136
#define VSTH 136
#define KBUFH (BKV * KSTH)

__global__ __launch_bounds__(256, 2) void attn_h(const __half* __restrict__ QKV,
                                                 __half* __restrict__ O) {
    extern __shared__ __half smh[];
    __half* Qs = smh;                    // 128*136
    __half* Ks = Qs + BQ * QSTH;         // 2 * 64*136
    __half* Vs = Ks + 2 * KBUFH;         // 64*136
    const uint32_t qsb = s2u(Qs), ksb = s2u(Ks), vsb = s2u(Vs);

    const int qt = blockIdx.x, h = blockIdx.y, b = blockIdx.z;
    const int kvh = h >> 2;
    const int tid = threadIdx.x, lane = tid & 31, warp = tid >> 5;
    const int g = lane >> 2, tg = lane & 3;
    const int wr0 = warp * 16;
    const int qrow0 = b * T_SEQ + qt * BQ;
    const float scale = 0.08838834764831845f;
    const float c2 = scale * 1.4426950408889634f;

    const __half* Qg = QKV + (size_t)h * 128;
    const __half* Kg = QKV + QDIM + (size_t)kvh * 128;
    const __half* Vg = QKV + 2560 + (size_t)kvh * 128;

    const uint32_t q_lo = (uint32_t)(((wr0 + (lane & 15)) * QSTH + ((lane >> 4) << 3)) * 2);
    const uint32_t k_lo = (uint32_t)((((lane & 7) + ((lane >> 4) << 3)) * KSTH +
                                      (((lane >> 3) & 1) << 3)) * 2);
    const uint32_t v_lo = (uint32_t)(((((lane >> 3) & 1) * 8 + (lane & 7)) * VSTH +
                                      ((lane >> 4) << 3)) * 2);

    auto fill_k = [&](int kt) {
        const int s = kt & 1;
        const int kr0 = b * T_SEQ + kt * BKV;
#pragma unroll
        for (int i = 0; i < 4; i++) {        // 64 rows x 16 chunks
            int ch = tid + i * 256;
            int r = ch >> 4, j = ch & 15;
            cpa16(ksb + (uint32_t)((s * KBUFH + r * KSTH) * 2 + j * 16),
                  Kg + (size_t)(kr0 + r) * QKVD + 8 * j);
        }
    };
    auto fill_v = [&](int kt) {
        const int kr0 = b * T_SEQ + kt * BKV;
#pragma unroll
        for (int i = 0; i < 4; i++) {
            int ch = tid + i * 256;
            int r = ch >> 4, j = ch & 15;
            cpa16(vsb + (uint32_t)((r * VSTH) * 2 + j * 16),
                  Vg + (size_t)(kr0 + r) * QKVD + 8 * j);
        }
    };

#pragma unroll
    for (int i = 0; i < 8; i++) {            // Q: 128 rows x 16 chunks
        int ch = tid + i * 256;
        int r = ch >> 4, j = ch & 15;
        cpa16(qsb + (uint32_t)((r * QSTH) * 2 + j * 16), Qg + (size_t)(qrow0 + r) * QKVD + 8 * j);
    }
    fill_k(0);
    cpa_commit();

    float m_lo = -INFINITY, m_hi = -INFINITY, l_lo = 0.f, l_hi = 0.f;
    float o[16][4];
#pragma unroll
    for (int nt = 0; nt < 16; nt++)
#pragma unroll
        for (int r = 0; r < 4; r++) o[nt][r] = 0.f;

    const int kmax = 2 * qt + 1;
    for (int kt = 0; kt <= kmax; kt++) {
        cpa_wait<0>();                       // K(kt) (and Q on kt=0) resident
        __syncthreads();                     // V reusable, K visible
        fill_v(kt); cpa_commit();
        if (kt < kmax) { fill_k(kt + 1); cpa_commit(); }

        const uint32_t kb = ksb + (uint32_t)((kt & 1) * KBUFH * 2);

        // S = Q K^T : warp tile 16x64
        float sc[8][4];
#pragma unroll
        for (int nt = 0; nt < 8; nt++)
#pragma unroll
            for (int r = 0; r < 4; r++) sc[nt][r] = 0.f;
#pragma unroll
        for (int kss = 0; kss < 8; kss++) {
            uint32_t a0, a1, a2, a3;
            ldsm4(a0, a1, a2, a3, qsb + q_lo + kss * 32);
#pragma unroll
            for (int ntp = 0; ntp < 4; ntp++) {
                uint32_t b0, b1, b2, b3;
                ldsm4(b0, b1, b2, b3,
                      kb + k_lo + (uint32_t)(ntp * 16 * KSTH * 2) + kss * 32);
                mma16(sc[2 * ntp],     a0, a1, a2, a3, b0, b1);
                mma16(sc[2 * ntp + 1], a0, a1, a2, a3, b2, b3);
            }
        }

        // causal mask (last two kt tiles are partial)
        if (kt >= 2 * qt) {
            int lim_lo = qt * BQ + wr0 + g - kt * BKV;
            int lim_hi = lim_lo + 8;
#pragma unroll
            for (int nt = 0; nt < 8; nt++) {
                int cc = nt * 8 + 2 * tg;
                if (cc     > lim_lo) sc[nt][0] = -INFINITY;
                if (cc + 1 > lim_lo) sc[nt][1] = -INFINITY;
                if (cc     > lim_hi) sc[nt][2] = -INFINITY;
                if (cc + 1 > lim_hi) sc[nt][3] = -INFINITY;
            }
        }

        // register softmax; packed exp outputs double as PV A-fragments
        float mx_lo = -INFINITY, mx_hi = -INFINITY;
#pragma unroll
        for (int nt = 0; nt < 8; nt++) {
            mx_lo = fmaxf(mx_lo, fmaxf(sc[nt][0], sc[nt][1]));
            mx_hi = fmaxf(mx_hi, fmaxf(sc[nt][2], sc[nt][3]));
        }
        mx_lo = fmaxf(mx_lo, __shfl_xor_sync(0xffffffffu, mx_lo, 1));
        mx_lo = fmaxf(mx_lo, __shfl_xor_sync(0xffffffffu, mx_lo, 2));
        mx_hi = fmaxf(mx_hi, __shfl_xor_sync(0xffffffffu, mx_hi, 1));
        mx_hi = fmaxf(mx_hi, __shfl_xor_sync(0xffffffffu, mx_hi, 2));

        float mn_lo = fmaxf(m_lo, mx_lo), mn_hi = fmaxf(m_hi, mx_hi);
        float al_lo = __expf((m_lo - mn_lo) * scale);
        float al_hi = __expf((m_hi - mn_hi) * scale);
        float ls_lo = 0.f, ls_hi = 0.f;
        uint32_t plo[8], phi[8];
#pragma unroll
        for (int nt = 0; nt < 8; nt++) {
            plo[nt] = ex2h2((sc[nt][0] - mn_lo) * c2, (sc[nt][1] - mn_lo) * c2);
            phi[nt] = ex2h2((sc[nt][2] - mn_hi) * c2, (sc[nt][3] - mn_hi) * c2);
            float2 flo = __half22float2(*(__half2*)&plo[nt]);
            float2 fhi = __half22float2(*(__half2*)&phi[nt]);
            ls_lo += flo.x + flo.y;
            ls_hi += fhi.x + fhi.y;
        }
        ls_lo += __shfl_xor_sync(0xffffffffu, ls_lo, 1);
        ls_lo += __shfl_xor_sync(0xffffffffu, ls_lo, 2);
        ls_hi += __shfl_xor_sync(0xffffffffu, ls_hi, 1);
        ls_hi += __shfl_xor_sync(0xffffffffu, ls_hi, 2);
        l_lo = l_lo * al_lo + ls_lo;
        l_hi = l_hi * al_hi + ls_hi;
        m_lo = mn_lo; m_hi = mn_hi;

        if (kt < kmax) cpa_wait<1>(); else cpa_wait<0>();   // V(kt) resident
        __syncthreads();

        // O = O*alpha + P @ V : P A-fragments straight from registers
#pragma unroll
        for (int nt = 0; nt < 16; nt++) {
            o[nt][0] *= al_lo; o[nt][1] *= al_lo;
            o[nt][2] *= al_hi; o[nt][3] *= al_hi;
        }
#pragma unroll
        for (int kss = 0; kss < 4; kss++) {     // 4 x 16 k-rows = 64
            uint32_t a0 = plo[2 * kss],     a1 = phi[2 * kss];
            uint32_t a2 = plo[2 * kss + 1], a3 = phi[2 * kss + 1];
            const uint32_t vslab = vsb + v_lo + (uint32_t)(kss * 16 * VSTH * 2);
#pragma unroll
            for (int ntp = 0; ntp < 8; ntp++) {
                uint32_t b0, b1, b2, b3;
                ldsm4t(b0, b1, b2, b3, vslab + ntp * 32);
                mma16(o[2 * ntp],     a0, a1, a2, a3, b0, b1);
                mma16(o[2 * ntp + 1], a0, a1, a2, a3, b2, b3);
            }
        }
    }

    // epilogue
    float li = 1.f / l_lo, lh = 1.f / l_hi;
#pragma unroll
    for (int nt = 0; nt < 16; nt++) {
        int c = h * HEAD_DIM + nt * 8 + 2 * tg;
        *(__half2*)&O[(size_t)(qrow0 + wr0 + g) * QDIM + c] =
            __floats2half2_rn(o[nt][0] * li, o[nt][1] * li);
        *(__half2*)&O[(size_t)(qrow0 + wr0 + 8 + g) * QDIM + c] =
            __floats2half2_rn(o[nt][2] * lh, o[nt][3] * lh);
    }
}

// ---------------- launch ----------------
extern "C" void kernel_launch(void* const* d_in, const int* in_sizes, int n_in,
                              void* d_out, int out_size) {
    const float* x  = (const float*)d_in[0];
    const float* Wq = (const float*)d_in[1];
    const float* Wk = (const float*)d_in[2];
    const float* Wv = (const float*)d_in[3];
    const float* Wo = (const float*)d_in[4];
    float* out = (float*)d_out;

    __half *qkv, *att, *xh, *wct, *wot;
    cudaGetSymbolAddress((void**)&qkv, g_qkv);
    cudaGetSymbolAddress((void**)&att, g_att);
    cudaGetSymbolAddress((void**)&xh, g_xh);
    cudaGetSymbolAddress((void**)&wct, g_wct);
    cudaGetSymbolAddress((void**)&wot, g_wot);

    {
        int n4x = M_ROWS * D_MODEL / 4;
        round_h<<<(n4x + 255) / 256, 256>>>((const float4*)x, xh, n4x);
        build_tab<<<(T_SEQ * 64 + 255) / 256, 256>>>();
        transpose_all<<<10240, dim3(32, 8)>>>(Wq, Wk, Wv, Wo, wct, wot);
    }

    const int GSM = 3 * (ASTGH + BSTGH) * 2;   // 110592
    cudaFuncSetAttribute(gemm_h<__half>, cudaFuncAttributeMaxDynamicSharedMemorySize, GSM);
    cudaFuncSetAttribute(gemm_h<float>, cudaFuncAttributeMaxDynamicSharedMemorySize, GSM);

    gemm_h<__half><<<dim3(QKVD / GBN, M_ROWS / GBM), 256, GSM>>>(xh, wct, qkv, M_ROWS, QKVD, D_MODEL);

    {
        int tot = B_SZ * T_SEQ * 20 * 64;
        rope_h<<<(tot + 255) / 256, 256>>>(qkv, tot);
    }

    {
        const int ASM_ = (BQ * QSTH + 2 * KBUFH + BKV * VSTH) * 2;   // 87040
        cudaFuncSetAttribute(attn_h, cudaFuncAttributeMaxDynamicSharedMemorySize, ASM_);
        attn_h<<<dim3(T_SEQ / BQ, N_HEADS, B_SZ), 256, ASM_>>>(qkv, att);
    }

    gemm_h<float><<<dim3(D_MODEL / GBN, M_ROWS / GBM), 256, GSM>>>(att, wot, out, M_ROWS, D_MODEL, QDIM);
}

// round 12
// speedup vs baseline: 10.2453x; 1.0183x over previous
#include <cuda_runtime.h>
#include <cuda_fp16.h>
#include <math.h>
#include <stdint.h>

#define D_MODEL 2048
#define N_HEADS 16
#define N_KV 4
#define HEAD_DIM 128
#define B_SZ 2
#define T_SEQ 2048
#define M_ROWS (B_SZ * T_SEQ)          // 4096
#define QDIM (N_HEADS * HEAD_DIM)      // 2048
#define KVDIM (N_KV * HEAD_DIM)        // 512
#define QKVD (QDIM + 2 * KVDIM)        // 3072

// ---------------- scratch ----------------
__device__ __half g_qkv[M_ROWS * QKVD];
__device__ __half g_att[M_ROWS * QDIM];
__device__ __half g_xh[M_ROWS * D_MODEL];
__device__ __half g_wct[(size_t)QKVD * D_MODEL];   // concat weights [n][k], fp16
__device__ __half g_wot[(size_t)D_MODEL * QDIM];   // Wo [n][k], fp16
__device__ float2 g_tab[T_SEQ * 64];               // rope cos/sin table

// ---------------- helpers ----------------
__device__ __forceinline__ uint32_t s2u(const void* p) {
    uint32_t a;
    asm("{ .reg .u64 t; cvta.to.shared.u64 t, %1; cvt.u32.u64 %0, t; }" : "=r"(a) : "l"(p));
    return a;
}
__device__ __forceinline__ void cpa16(uint32_t dst, const void* src) {
    asm volatile("cp.async.cg.shared.global [%0], [%1], 16;" :: "r"(dst), "l"(src));
}
__device__ __forceinline__ void cpa_commit() { asm volatile("cp.async.commit_group;" ::: "memory"); }
template <int N> __device__ __forceinline__ void cpa_wait() {
    asm volatile("cp.async.wait_group %0;" :: "n"(N) : "memory");
}
__device__ __forceinline__ void ldsm4(uint32_t& r0, uint32_t& r1, uint32_t& r2, uint32_t& r3,
                                      uint32_t addr) {
    asm volatile("ldmatrix.sync.aligned.m8n8.x4.shared.b16 {%0,%1,%2,%3}, [%4];"
                 : "=r"(r0), "=r"(r1), "=r"(r2), "=r"(r3) : "r"(addr));
}
__device__ __forceinline__ void ldsm4t(uint32_t& r0, uint32_t& r1, uint32_t& r2, uint32_t& r3,
                                       uint32_t addr) {
    asm volatile("ldmatrix.sync.aligned.m8n8.x4.trans.shared.b16 {%0,%1,%2,%3}, [%4];"
                 : "=r"(r0), "=r"(r1), "=r"(r2), "=r"(r3) : "r"(addr));
}
__device__ __forceinline__ void mma16(float* c, uint32_t a0, uint32_t a1, uint32_t a2, uint32_t a3,
                                      uint32_t b0, uint32_t b1) {
    asm volatile(
        "mma.sync.aligned.m16n8k16.row.col.f32.f16.f16.f32 "
        "{%0,%1,%2,%3},{%4,%5,%6,%7},{%8,%9},{%0,%1,%2,%3};"
        : "+f"(c[0]), "+f"(c[1]), "+f"(c[2]), "+f"(c[3])
        : "r"(a0), "r"(a1), "r"(a2), "r"(a3), "r"(b0), "r"(b1));
}
__device__ __forceinline__ uint32_t ex2h2(float a, float b) {
    __half2 h = __floats2half2_rn(a, b);
    uint32_t r;
    asm("ex2.approx.f16x2 %0, %1;" : "=r"(r) : "r"(*(uint32_t*)&h));
    return r;
}

// ---------------- GEMM: 128x128 CTA tile, 64x32 warp tile, 3-stage, 2 CTAs/SM ----------------
#define GBM 128
#define GBN 128
#define GBK 64
#define GSTH 72
#define ASTGH (128 * GSTH)
#define BSTGH (128 * GSTH)

template <typename TO>
__global__ __launch_bounds__(256, 2) void gemm_h(const __half* __restrict__ A,
                                                 const __half* __restrict__ Bt,
                                                 TO* __restrict__ C,
                                                 int M, int N, int K) {
    extern __shared__ __half smh[];
    const uint32_t asb = s2u(smh);
    const uint32_t bsb = asb + 3 * ASTGH * 2;

    const int tid = threadIdx.x;
    const int lane = tid & 31, warp = tid >> 5;
    const int wm = warp >> 2, wn = warp & 3;
    const int g = lane >> 2, tg = lane & 3;
    const int bm = blockIdx.y * GBM, bn = blockIdx.x * GBN;
    const int NK = K / GBK;

    uint32_t aoff[4], boff[2];
#pragma unroll
    for (int mt = 0; mt < 4; mt++)
        aoff[mt] = (uint32_t)(((wm * 64 + mt * 16 + (lane & 15)) * GSTH + ((lane >> 4) << 3)) * 2);
#pragma unroll
    for (int ntp = 0; ntp < 2; ntp++)
        boff[ntp] = (uint32_t)(((wn * 32 + ntp * 16 + (lane & 7) + ((lane >> 4) << 3)) * GSTH +
                                (((lane >> 3) & 1) << 3)) * 2);

    float acc[4][4][4];
#pragma unroll
    for (int mt = 0; mt < 4; mt++)
#pragma unroll
        for (int nt = 0; nt < 4; nt++)
#pragma unroll
            for (int r = 0; r < 4; r++) acc[mt][nt][r] = 0.f;

    auto fill = [&](int kt) {
        const int s = kt - (kt / 3) * 3;
        const int k0 = kt * GBK;
#pragma unroll
        for (int i = 0; i < 4; i++) {
            int ch = tid + i * 256;
            int r = ch >> 3, j = ch & 7;
            cpa16(asb + (uint32_t)((s * ASTGH + r * GSTH) * 2 + j * 16),
                  A + (size_t)(bm + r) * K + k0 + 8 * j);
        }
#pragma unroll
        for (int i = 0; i < 4; i++) {
            int ch = tid + i * 256;
            int r = ch >> 3, j = ch & 7;
            cpa16(bsb + (uint32_t)((s * BSTGH + r * GSTH) * 2 + j * 16),
                  Bt + (size_t)(bn + r) * K + k0 + 8 * j);
        }
    };

    fill(0); cpa_commit();
    fill(1); cpa_commit();

    for (int kt = 0; kt < NK; kt++) {
        cpa_wait<1>();
        __syncthreads();
        if (kt + 2 < NK) fill(kt + 2);
        cpa_commit();

        const int s = kt - (kt / 3) * 3;
        const uint32_t ab = asb + (uint32_t)(s * ASTGH * 2);
        const uint32_t bb = bsb + (uint32_t)(s * BSTGH * 2);
#pragma unroll
        for (int ks = 0; ks < 4; ks++) {
            uint32_t af[4][4], bf[4][2];
#pragma unroll
            for (int mt = 0; mt < 4; mt++)
                ldsm4(af[mt][0], af[mt][1], af[mt][2], af[mt][3], ab + aoff[mt] + ks * 32);
#pragma unroll
            for (int ntp = 0; ntp < 2; ntp++)
                ldsm4(bf[2 * ntp][0], bf[2 * ntp][1], bf[2 * ntp + 1][0], bf[2 * ntp + 1][1],
                      bb + boff[ntp] + ks * 32);
#pragma unroll
            for (int mt = 0; mt < 4; mt++)
#pragma unroll
                for (int nt = 0; nt < 4; nt++)
                    mma16(acc[mt][nt], af[mt][0], af[mt][1], af[mt][2], af[mt][3], bf[nt][0], bf[nt][1]);
        }
    }

#pragma unroll
    for (int mt = 0; mt < 4; mt++)
#pragma unroll
        for (int nt = 0; nt < 4; nt++) {
            int r = bm + wm * 64 + mt * 16 + g;
            int c = bn + wn * 32 + nt * 8 + 2 * tg;
            if constexpr (sizeof(TO) == 2) {
                *(__half2*)&C[(size_t)r * N + c] =
                    __floats2half2_rn(acc[mt][nt][0], acc[mt][nt][1]);
                *(__half2*)&C[(size_t)(r + 8) * N + c] =
                    __floats2half2_rn(acc[mt][nt][2], acc[mt][nt][3]);
            } else {
                *(float2*)&C[(size_t)r * N + c] = make_float2(acc[mt][nt][0], acc[mt][nt][1]);
                *(float2*)&C[(size_t)(r + 8) * N + c] = make_float2(acc[mt][nt][2], acc[mt][nt][3]);
            }
        }
}

// ---------------- fused prep: transposes + x rounding + rope table, one launch ----------------
__device__ __forceinline__ void do_transpose(const float* W, __half* Wt, int K, int N,
                                             int kb, int nb, int tx, int ty, float (*t)[33]) {
#pragma unroll
    for (int i = 0; i < 32; i += 8)
        t[ty + i][tx] = W[(size_t)(kb + ty + i) * N + nb + tx];
    __syncthreads();
#pragma unroll
    for (int i = 0; i < 32; i += 8)
        Wt[(size_t)(nb + ty + i) * K + kb + tx] = __float2half_rn(t[tx][ty + i]);
}

__global__ void prep_all(const float* __restrict__ x, const float* __restrict__ Wq,
                         const float* __restrict__ Wk, const float* __restrict__ Wv,
                         const float* __restrict__ Wo, __half* __restrict__ xh,
                         __half* __restrict__ wct, __half* __restrict__ wot) {
    __shared__ float t[32][33];
    int bid = blockIdx.x;
    int tid = threadIdx.x;
    if (bid < 10240) {                       // weight transposes
        int tx = tid & 31, ty = tid >> 5;
        if (bid < 4096) {
            do_transpose(Wq, wct, D_MODEL, QDIM, (bid & 63) * 32, (bid >> 6) * 32, tx, ty, t);
        } else if (bid < 5120) {
            int l = bid - 4096;
            do_transpose(Wk, wct + (size_t)QDIM * D_MODEL, D_MODEL, KVDIM,
                         (l & 63) * 32, (l >> 6) * 32, tx, ty, t);
        } else if (bid < 6144) {
            int l = bid - 5120;
            do_transpose(Wv, wct + (size_t)2560 * D_MODEL, D_MODEL, KVDIM,
                         (l & 63) * 32, (l >> 6) * 32, tx, ty, t);
        } else {
            int l = bid - 6144;
            do_transpose(Wo, wot, QDIM, D_MODEL, (l & 63) * 32, (l >> 6) * 32, tx, ty, t);
        }
    } else if (bid < 18432) {                // x -> fp16 (8192 blocks)
        int i = (bid - 10240) * 256 + tid;   // per float4
        float4 v = ((const float4*)x)[i];
        __half2 lo = __floats2half2_rn(v.x, v.y);
        __half2 hi = __floats2half2_rn(v.z, v.w);
        *(uint2*)&xh[i * 4] = make_uint2(*(uint32_t*)&lo, *(uint32_t*)&hi);
    } else {                                 // rope table (512 blocks)
        int gid = (bid - 18432) * 256 + tid;
        int i = gid & 63;
        int tt = gid >> 6;
        float inv = powf(10000.0f, -((float)(2 * i)) / 128.0f);
        float ang = (float)tt * inv;
        float s, c;
        sincosf(ang, &s, &c);
        g_tab[gid] = make_float2(c, s);
    }
}

__global__ void rope_h(__half* __restrict__ X, int total) {
    int gid = blockIdx.x * blockDim.x + threadIdx.x;
    if (gid >= total) return;
    int i = gid & 63;
    int hh = (gid >> 6) % 20;
    int bt = gid / (64 * 20);
    int t = bt % T_SEQ;

    float2 cs = g_tab[t * 64 + i];

    size_t base = (size_t)bt * QKVD + (size_t)hh * 128 + i;
    float x1 = __half2float(X[base]);
    float x2 = __half2float(X[base + 64]);
    X[base] = __float2half_rn(x1 * cs.x - x2 * cs.y);
    X[base + 64] = __float2half_rn(x2 * cs.x + x1 * cs.y);
}

// ---------------- flash attention fp16: Br=128, Bc=64, K+V double buffered ----------------
#define BQ 128
#define BKV 64
#define QSTH 136
#define KSTH 136
#define VSTH 136
#define KBUFH (BKV * KSTH)
#define VBUFH (BKV * VSTH)

__global__ __launch_bounds__(256, 2) void attn_h(const __half* __restrict__ QKV,
                                                 __half* __restrict__ O) {
    extern __shared__ __half smh[];
    __half* Qs = smh;                    // 128*136
    __half* Ks = Qs + BQ * QSTH;         // 2 * 64*136
    __half* Vs = Ks + 2 * KBUFH;         // 2 * 64*136
    const uint32_t qsb = s2u(Qs), ksb = s2u(Ks), vsb = s2u(Vs);

    const int qt = (T_SEQ / BQ - 1) - blockIdx.x;   // heavy tiles first
    const int h = blockIdx.y, b = blockIdx.z;
    const int kvh = h >> 2;
    const int tid = threadIdx.x, lane = tid & 31, warp = tid >> 5;
    const int g = lane >> 2, tg = lane & 3;
    const int wr0 = warp * 16;
    const int qrow0 = b * T_SEQ + qt * BQ;
    const float scale = 0.08838834764831845f;
    const float c2 = scale * 1.4426950408889634f;

    const __half* Qg = QKV + (size_t)h * 128;
    const __half* Kg = QKV + QDIM + (size_t)kvh * 128;
    const __half* Vg = QKV + 2560 + (size_t)kvh * 128;

    const uint32_t q_lo = (uint32_t)(((wr0 + (lane & 15)) * QSTH + ((lane >> 4) << 3)) * 2);
    const uint32_t k_lo = (uint32_t)((((lane & 7) + ((lane >> 4) << 3)) * KSTH +
                                      (((lane >> 3) & 1) << 3)) * 2);
    const uint32_t v_lo = (uint32_t)(((((lane >> 3) & 1) * 8 + (lane & 7)) * VSTH +
                                      ((lane >> 4) << 3)) * 2);

    // K + V tile for step kt as ONE cp.async group
    auto fill_kv = [&](int kt) {
        const int s = kt & 1;
        const int kr0 = b * T_SEQ + kt * BKV;
#pragma unroll
        for (int i = 0; i < 4; i++) {
            int ch = tid + i * 256;
            int r = ch >> 4, j = ch & 15;
            cpa16(ksb + (uint32_t)((s * KBUFH + r * KSTH) * 2 + j * 16),
                  Kg + (size_t)(kr0 + r) * QKVD + 8 * j);
            cpa16(vsb + (uint32_t)((s * VBUFH + r * VSTH) * 2 + j * 16),
                  Vg + (size_t)(kr0 + r) * QKVD + 8 * j);
        }
    };

#pragma unroll
    for (int i = 0; i < 8; i++) {            // Q: 128 rows x 16 chunks
        int ch = tid + i * 256;
        int r = ch >> 4, j = ch & 15;
        cpa16(qsb + (uint32_t)((r * QSTH) * 2 + j * 16), Qg + (size_t)(qrow0 + r) * QKVD + 8 * j);
    }
    fill_kv(0);
    cpa_commit();

    float m_lo = -INFINITY, m_hi = -INFINITY, l_lo = 0.f, l_hi = 0.f;
    float o[16][4];
#pragma unroll
    for (int nt = 0; nt < 16; nt++)
#pragma unroll
        for (int r = 0; r < 4; r++) o[nt][r] = 0.f;

    const int kmax = 2 * qt + 1;
    for (int kt = 0; kt <= kmax; kt++) {
        cpa_wait<0>();                       // K(kt)+V(kt) (and Q on kt=0) resident
        __syncthreads();                     // all warps done with stage (kt+1)&1 from kt-1
        if (kt < kmax) { fill_kv(kt + 1); cpa_commit(); }

        const uint32_t kb = ksb + (uint32_t)((kt & 1) * KBUFH * 2);
        const uint32_t vb = vsb + (uint32_t)((kt & 1) * VBUFH * 2);

        // S = Q K^T : warp tile 16x64
        float sc[8][4];
#pragma unroll
        for (int nt = 0; nt < 8; nt++)
#pragma unroll
            for (int r = 0; r < 4; r++) sc[nt][r] = 0.f;
#pragma unroll
        for (int kss = 0; kss < 8; kss++) {
            uint32_t a0, a1, a2, a3;
            ldsm4(a0, a1, a2, a3, qsb + q_lo + kss * 32);
#pragma unroll
            for (int ntp = 0; ntp < 4; ntp++) {
                uint32_t b0, b1, b2, b3;
                ldsm4(b0, b1, b2, b3,
                      kb + k_lo + (uint32_t)(ntp * 16 * KSTH * 2) + kss * 32);
                mma16(sc[2 * ntp],     a0, a1, a2, a3, b0, b1);
                mma16(sc[2 * ntp + 1], a0, a1, a2, a3, b2, b3);
            }
        }

        // causal mask (last two kt tiles are partial)
        if (kt >= 2 * qt) {
            int lim_lo = qt * BQ + wr0 + g - kt * BKV;
            int lim_hi = lim_lo + 8;
#pragma unroll
            for (int nt = 0; nt < 8; nt++) {
                int cc = nt * 8 + 2 * tg;
                if (cc     > lim_lo) sc[nt][0] = -INFINITY;
                if (cc + 1 > lim_lo) sc[nt][1] = -INFINITY;
                if (cc     > lim_hi) sc[nt][2] = -INFINITY;
                if (cc + 1 > lim_hi) sc[nt][3] = -INFINITY;
            }
        }

        // register softmax; packed exp outputs double as PV A-fragments
        float mx_lo = -INFINITY, mx_hi = -INFINITY;
#pragma unroll
        for (int nt = 0; nt < 8; nt++) {
            mx_lo = fmaxf(mx_lo, fmaxf(sc[nt][0], sc[nt][1]));
            mx_hi = fmaxf(mx_hi, fmaxf(sc[nt][2], sc[nt][3]));
        }
        mx_lo = fmaxf(mx_lo, __shfl_xor_sync(0xffffffffu, mx_lo, 1));
        mx_lo = fmaxf(mx_lo, __shfl_xor_sync(0xffffffffu, mx_lo, 2));
        mx_hi = fmaxf(mx_hi, __shfl_xor_sync(0xffffffffu, mx_hi, 1));
        mx_hi = fmaxf(mx_hi, __shfl_xor_sync(0xffffffffu, mx_hi, 2));

        float mn_lo = fmaxf(m_lo, mx_lo), mn_hi = fmaxf(m_hi, mx_hi);
        float al_lo = __expf((m_lo - mn_lo) * scale);
        float al_hi = __expf((m_hi - mn_hi) * scale);
        float ls_lo = 0.f, ls_hi = 0.f;
        uint32_t plo[8], phi[8];
#pragma unroll
        for (int nt = 0; nt < 8; nt++) {
            plo[nt] = ex2h2((sc[nt][0] - mn_lo) * c2, (sc[nt][1] - mn_lo) * c2);
            phi[nt] = ex2h2((sc[nt][2] - mn_hi) * c2, (sc[nt][3] - mn_hi) * c2);
            float2 flo = __half22float2(*(__half2*)&plo[nt]);
            float2 fhi = __half22float2(*(__half2*)&phi[nt]);
            ls_lo += flo.x + flo.y;
            ls_hi += fhi.x + fhi.y;
        }
        ls_lo += __shfl_xor_sync(0xffffffffu, ls_lo, 1);
        ls_lo += __shfl_xor_sync(0xffffffffu, ls_lo, 2);
        ls_hi += __shfl_xor_sync(0xffffffffu, ls_hi, 1);
        ls_hi += __shfl_xor_sync(0xffffffffu, ls_hi, 2);
        l_lo = l_lo * al_lo + ls_lo;
        l_hi = l_hi * al_hi + ls_hi;
        m_lo = mn_lo; m_hi = mn_hi;

        // O = O*alpha + P @ V : P A-fragments straight from registers
#pragma unroll
        for (int nt = 0; nt < 16; nt++) {
            o[nt][0] *= al_lo; o[nt][1] *= al_lo;
            o[nt][2] *= al_hi; o[nt][3] *= al_hi;
        }
#pragma unroll
        for (int kss = 0; kss < 4; kss++) {
            uint32_t a0 = plo[2 * kss],     a1 = phi[2 * kss];
            uint32_t a2 = plo[2 * kss + 1], a3 = phi[2 * kss + 1];
            const uint32_t vslab = vb + v_lo + (uint32_t)(kss * 16 * VSTH * 2);
#pragma unroll
            for (int ntp = 0; ntp < 8; ntp++) {
                uint32_t b0, b1, b2, b3;
                ldsm4t(b0, b1, b2, b3, vslab + ntp * 32);
                mma16(o[2 * ntp],     a0, a1, a2, a3, b0, b1);
                mma16(o[2 * ntp + 1], a0, a1, a2, a3, b2, b3);
            }
        }
    }

    // epilogue
    float li = 1.f / l_lo, lh = 1.f / l_hi;
#pragma unroll
    for (int nt = 0; nt < 16; nt++) {
        int c = h * HEAD_DIM + nt * 8 + 2 * tg;
        *(__half2*)&O[(size_t)(qrow0 + wr0 + g) * QDIM + c] =
            __floats2half2_rn(o[nt][0] * li, o[nt][1] * li);
        *(__half2*)&O[(size_t)(qrow0 + wr0 + 8 + g) * QDIM + c] =
            __floats2half2_rn(o[nt][2] * lh, o[nt][3] * lh);
    }
}

// ---------------- launch ----------------
extern "C" void kernel_launch(void* const* d_in, const int* in_sizes, int n_in,
                              void* d_out, int out_size) {
    const float* x  = (const float*)d_in[0];
    const float* Wq = (const float*)d_in[1];
    const float* Wk = (const float*)d_in[2];
    const float* Wv = (const float*)d_in[3];
    const float* Wo = (const float*)d_in[4];
    float* out = (float*)d_out;

    __half *qkv, *att, *xh, *wct, *wot;
    cudaGetSymbolAddress((void**)&qkv, g_qkv);
    cudaGetSymbolAddress((void**)&att, g_att);
    cudaGetSymbolAddress((void**)&xh, g_xh);
    cudaGetSymbolAddress((void**)&wct, g_wct);
    cudaGetSymbolAddress((void**)&wot, g_wot);

    // fused prep: 10240 transpose blocks + 8192 round blocks + 512 table blocks
    prep_all<<<18944, 256>>>(x, Wq, Wk, Wv, Wo, xh, wct, wot);

    const int GSM = 3 * (ASTGH + BSTGH) * 2;   // 110592
    cudaFuncSetAttribute(gemm_h<__half>, cudaFuncAttributeMaxDynamicSharedMemorySize, GSM);
    cudaFuncSetAttribute(gemm_h<float>, cudaFuncAttributeMaxDynamicSharedMemorySize, GSM);

    gemm_h<__half><<<dim3(QKVD / GBN, M_ROWS / GBM), 256, GSM>>>(xh, wct, qkv, M_ROWS, QKVD, D_MODEL);

    {
        int tot = B_SZ * T_SEQ * 20 * 64;
        rope_h<<<(tot + 255) / 256, 256>>>(qkv, tot);
    }

    {
        const int ASM_ = (BQ * QSTH + 2 * KBUFH + 2 * VBUFH) * 2;   // 104448
        cudaFuncSetAttribute(attn_h, cudaFuncAttributeMaxDynamicSharedMemorySize, ASM_);
        attn_h<<<dim3(T_SEQ / BQ, N_HEADS, B_SZ), 256, ASM_>>>(qkv, att);
    }

    gemm_h<float><<<dim3(D_MODEL / GBN, M_ROWS / GBM), 256, GSM>>>(att, wot, out, M_ROWS, D_MODEL, QDIM);
}

// round 13
// speedup vs baseline: 10.6241x; 1.0370x over previous
#include <cuda_runtime.h>
#include <cuda_fp16.h>
#include <math.h>
#include <stdint.h>

#define D_MODEL 2048
#define N_HEADS 16
#define N_KV 4
#define HEAD_DIM 128
#define B_SZ 2
#define T_SEQ 2048
#define M_ROWS (B_SZ * T_SEQ)          // 4096
#define QDIM (N_HEADS * HEAD_DIM)      // 2048
#define KVDIM (N_KV * HEAD_DIM)        // 512
#define QKVD (QDIM + 2 * KVDIM)        // 3072

// ---------------- scratch ----------------
__device__ __half g_qkv[M_ROWS * QKVD];
__device__ __half g_att[M_ROWS * QDIM];
__device__ __half g_xh[M_ROWS * D_MODEL];
__device__ __half g_wc[(size_t)D_MODEL * QKVD];    // concat weights [k][n] fp16
__device__ __half g_wo[(size_t)QDIM * D_MODEL];    // Wo [k][n] fp16
__device__ float2 g_tab[T_SEQ * 64];               // rope cos/sin table

// ---------------- helpers ----------------
__device__ __forceinline__ uint32_t s2u(const void* p) {
    uint32_t a;
    asm("{ .reg .u64 t; cvta.to.shared.u64 t, %1; cvt.u32.u64 %0, t; }" : "=r"(a) : "l"(p));
    return a;
}
__device__ __forceinline__ void cpa16(uint32_t dst, const void* src) {
    asm volatile("cp.async.cg.shared.global [%0], [%1], 16;" :: "r"(dst), "l"(src));
}
__device__ __forceinline__ void cpa_commit() { asm volatile("cp.async.commit_group;" ::: "memory"); }
template <int N> __device__ __forceinline__ void cpa_wait() {
    asm volatile("cp.async.wait_group %0;" :: "n"(N) : "memory");
}
__device__ __forceinline__ void ldsm4(uint32_t& r0, uint32_t& r1, uint32_t& r2, uint32_t& r3,
                                      uint32_t addr) {
    asm volatile("ldmatrix.sync.aligned.m8n8.x4.shared.b16 {%0,%1,%2,%3}, [%4];"
                 : "=r"(r0), "=r"(r1), "=r"(r2), "=r"(r3) : "r"(addr));
}
__device__ __forceinline__ void ldsm4t(uint32_t& r0, uint32_t& r1, uint32_t& r2, uint32_t& r3,
                                       uint32_t addr) {
    asm volatile("ldmatrix.sync.aligned.m8n8.x4.trans.shared.b16 {%0,%1,%2,%3}, [%4];"
                 : "=r"(r0), "=r"(r1), "=r"(r2), "=r"(r3) : "r"(addr));
}
__device__ __forceinline__ void mma16(float* c, uint32_t a0, uint32_t a1, uint32_t a2, uint32_t a3,
                                      uint32_t b0, uint32_t b1) {
    asm volatile(
        "mma.sync.aligned.m16n8k16.row.col.f32.f16.f16.f32 "
        "{%0,%1,%2,%3},{%4,%5,%6,%7},{%8,%9},{%0,%1,%2,%3};"
        : "+f"(c[0]), "+f"(c[1]), "+f"(c[2]), "+f"(c[3])
        : "r"(a0), "r"(a1), "r"(a2), "r"(a3), "r"(b0), "r"(b1));
}
__device__ __forceinline__ uint32_t ex2h2(float a, float b) {
    __half2 h = __floats2half2_rn(a, b);
    uint32_t r;
    asm("ex2.approx.f16x2 %0, %1;" : "=r"(r) : "r"(*(uint32_t*)&h));
    return r;
}

// ---------------- GEMM: A[m][k]h @ B[k][n]h, B frags via ldmatrix.trans ----------------
#define GBM 128
#define GBN 128
#define GBK 64
#define ASTH 72                         // A smem stride (halves)
#define BSTH 136                        // B smem stride (halves)
#define ASTGH (128 * ASTH)
#define BSTGH (64 * BSTH)

// ROPE: apply rotary to columns of head-aligned tiles (qkv projection only)
template <typename TO, bool ROPE>
__global__ __launch_bounds__(256, 2) void gemm_h(const __half* __restrict__ A,
                                                 const __half* __restrict__ B,
                                                 TO* __restrict__ C,
                                                 int M, int N, int K) {
    extern __shared__ __half smh[];
    const uint32_t asb = s2u(smh);
    const uint32_t bsb = asb + 3 * ASTGH * 2;

    const int tid = threadIdx.x;
    const int lane = tid & 31, warp = tid >> 5;
    const int wm = warp >> 2, wn = warp & 3;    // 2 x 4 warps, warp tile 64x32
    const int g = lane >> 2, tg = lane & 3;
    const int bm = blockIdx.y * GBM, bn = blockIdx.x * GBN;
    const int NK = K / GBK;

    uint32_t aoff[4];
#pragma unroll
    for (int mt = 0; mt < 4; mt++)
        aoff[mt] = (uint32_t)(((wm * 64 + mt * 16 + (lane & 15)) * ASTH + ((lane >> 4) << 3)) * 2);
    // B [k][n] trans-ldmatrix lane offset (same pattern as attention V path)
    const uint32_t b_lo = (uint32_t)(((((lane >> 3) & 1) * 8 + (lane & 7)) * BSTH +
                                      ((lane >> 4) << 3)) * 2);

    float acc[4][4][4];
#pragma unroll
    for (int mt = 0; mt < 4; mt++)
#pragma unroll
        for (int nt = 0; nt < 4; nt++)
#pragma unroll
            for (int r = 0; r < 4; r++) acc[mt][nt][r] = 0.f;

    auto fill = [&](int kt) {
        const int s = kt - (kt / 3) * 3;
        const int k0 = kt * GBK;
#pragma unroll
        for (int i = 0; i < 4; i++) {           // A: 128 rows x 8 chunks
            int ch = tid + i * 256;
            int r = ch >> 3, j = ch & 7;
            cpa16(asb + (uint32_t)((s * ASTGH + r * ASTH) * 2 + j * 16),
                  A + (size_t)(bm + r) * K + k0 + 8 * j);
        }
#pragma unroll
        for (int i = 0; i < 4; i++) {           // B: 64 k-rows x 16 chunks
            int ch = tid + i * 256;
            int r = ch >> 4, j = ch & 15;
            cpa16(bsb + (uint32_t)((s * BSTGH + r * BSTH) * 2 + j * 16),
                  B + (size_t)(k0 + r) * N + bn + 8 * j);
        }
    };

    fill(0); cpa_commit();
    fill(1); cpa_commit();

    for (int kt = 0; kt < NK; kt++) {
        cpa_wait<1>();
        __syncthreads();
        if (kt + 2 < NK) fill(kt + 2);
        cpa_commit();

        const int s = kt - (kt / 3) * 3;
        const uint32_t ab = asb + (uint32_t)(s * ASTGH * 2);
        const uint32_t bb = bsb + (uint32_t)(s * BSTGH * 2);
#pragma unroll
        for (int ks = 0; ks < 4; ks++) {
            uint32_t af[4][4], bf[4][2];
#pragma unroll
            for (int mt = 0; mt < 4; mt++)
                ldsm4(af[mt][0], af[mt][1], af[mt][2], af[mt][3], ab + aoff[mt] + ks * 32);
            const uint32_t bslab = bb + b_lo + (uint32_t)(ks * 16 * BSTH * 2);
#pragma unroll
            for (int nl = 0; nl < 2; nl++) {
                int ntp = wn * 2 + nl;          // 16-col group within the 128-col tile
                ldsm4t(bf[2 * nl][0], bf[2 * nl][1], bf[2 * nl + 1][0], bf[2 * nl + 1][1],
                       bslab + ntp * 32);
            }
#pragma unroll
            for (int mt = 0; mt < 4; mt++)
#pragma unroll
                for (int nt = 0; nt < 4; nt++)
                    mma16(acc[mt][nt], af[mt][0], af[mt][1], af[mt][2], af[mt][3], bf[nt][0], bf[nt][1]);
        }
    }

    if constexpr (ROPE) {
        // stage fp16 tile in (now free) pipeline smem, rotate head-aligned column pairs
        cpa_wait<0>();
        __syncthreads();
        __half* Cs = smh;                       // 128 x 136
#pragma unroll
        for (int mt = 0; mt < 4; mt++)
#pragma unroll
            for (int nt = 0; nt < 4; nt++) {
                int r = wm * 64 + mt * 16 + g;
                int c = wn * 32 + nt * 8 + 2 * tg;
                *(__half2*)&Cs[r * 136 + c] = __floats2half2_rn(acc[mt][nt][0], acc[mt][nt][1]);
                *(__half2*)&Cs[(r + 8) * 136 + c] = __floats2half2_rn(acc[mt][nt][2], acc[mt][nt][3]);
            }
        __syncthreads();
        if (bn < 2560) {                        // q/k panels: rotate
            for (int it = tid; it < 128 * 32; it += 256) {
                int r = it >> 5;
                int i2 = (it & 31) * 2;
                int t = (bm + r) & (T_SEQ - 1);
                float2 cs0 = g_tab[t * 64 + i2];
                float2 cs1 = g_tab[t * 64 + i2 + 1];
                float2 f1 = __half22float2(*(__half2*)&Cs[r * 136 + i2]);
                float2 f2 = __half22float2(*(__half2*)&Cs[r * 136 + 64 + i2]);
                *(__half2*)&C[(size_t)(bm + r) * N + bn + i2] =
                    __floats2half2_rn(f1.x * cs0.x - f2.x * cs0.y, f1.y * cs1.x - f2.y * cs1.y);
                *(__half2*)&C[(size_t)(bm + r) * N + bn + 64 + i2] =
                    __floats2half2_rn(f2.x * cs0.x + f1.x * cs0.y, f2.y * cs1.x + f1.y * cs1.y);
            }
        } else {                                // v panel: plain copy
            for (int it = tid; it < 128 * 64; it += 256) {
                int r = it >> 6;
                int c2 = (it & 63) * 2;
                *(__half2*)&C[(size_t)(bm + r) * N + bn + c2] = *(__half2*)&Cs[r * 136 + c2];
            }
        }
    } else {
#pragma unroll
        for (int mt = 0; mt < 4; mt++)
#pragma unroll
            for (int nt = 0; nt < 4; nt++) {
                int r = bm + wm * 64 + mt * 16 + g;
                int c = bn + wn * 32 + nt * 8 + 2 * tg;
                if constexpr (sizeof(TO) == 2) {
                    *(__half2*)&C[(size_t)r * N + c] =
                        __floats2half2_rn(acc[mt][nt][0], acc[mt][nt][1]);
                    *(__half2*)&C[(size_t)(r + 8) * N + c] =
                        __floats2half2_rn(acc[mt][nt][2], acc[mt][nt][3]);
                } else {
                    *(float2*)&C[(size_t)r * N + c] = make_float2(acc[mt][nt][0], acc[mt][nt][1]);
                    *(float2*)&C[(size_t)(r + 8) * N + c] = make_float2(acc[mt][nt][2], acc[mt][nt][3]);
                }
            }
    }
}

// ---------------- fused prep: converts + rope table (all coalesced) ----------------
__global__ void prep_all(const float* __restrict__ x, const float* __restrict__ Wq,
                         const float* __restrict__ Wk, const float* __restrict__ Wv,
                         const float* __restrict__ Wo, __half* __restrict__ xh,
                         __half* __restrict__ wc, __half* __restrict__ wo) {
    int bid = blockIdx.x;
    int tid = threadIdx.x;
    if (bid < 8192) {                            // x -> fp16
        int i = bid * 256 + tid;
        float4 v = ((const float4*)x)[i];
        __half2 lo = __floats2half2_rn(v.x, v.y);
        __half2 hi = __floats2half2_rn(v.z, v.w);
        *(uint2*)&xh[i * 4] = make_uint2(*(uint32_t*)&lo, *(uint32_t*)&hi);
    } else if (bid < 14336) {                    // concat Wq|Wk|Wv -> wc [k][3072]
        int idx = (bid - 8192) * 256 + tid;      // per float4
        const int n4row = QKVD / 4;
        int k = idx / n4row;
        int n = (idx - k * n4row) * 4;
        const float* src;
        int c;
        if (n < QDIM)      { src = Wq + (size_t)k * QDIM;  c = n; }
        else if (n < 2560) { src = Wk + (size_t)k * KVDIM; c = n - QDIM; }
        else               { src = Wv + (size_t)k * KVDIM; c = n - 2560; }
        float4 v = *(const float4*)(src + c);
        __half2 lo = __floats2half2_rn(v.x, v.y);
        __half2 hi = __floats2half2_rn(v.z, v.w);
        *(uint2*)&wc[(size_t)k * QKVD + n] = make_uint2(*(uint32_t*)&lo, *(uint32_t*)&hi);
    } else if (bid < 18432) {                    // Wo -> fp16
        int i = (bid - 14336) * 256 + tid;
        float4 v = ((const float4*)Wo)[i];
        __half2 lo = __floats2half2_rn(v.x, v.y);
        __half2 hi = __floats2half2_rn(v.z, v.w);
        *(uint2*)&wo[i * 4] = make_uint2(*(uint32_t*)&lo, *(uint32_t*)&hi);
    } else {                                     // rope table (512 blocks)
        int gid = (bid - 18432) * 256 + tid;
        int i = gid & 63;
        int tt = gid >> 6;
        float inv = powf(10000.0f, -((float)(2 * i)) / 128.0f);
        float ang = (float)tt * inv;
        float s, c;
        sincosf(ang, &s, &c);
        g_tab[gid] = make_float2(c, s);
    }
}

// ---------------- flash attention fp16: Br=128, Bc=64, K+V double buffered ----------------
#define BQ 128
#define BKV 64
#define QSTH 136
#define KSTH 136
#define VSTH 136
#define KBUFH (BKV * KSTH)
#define VBUFH (BKV * VSTH)

__global__ __launch_bounds__(256, 2) void attn_h(const __half* __restrict__ QKV,
                                                 __half* __restrict__ O) {
    extern __shared__ __half smh[];
    __half* Qs = smh;
    __half* Ks = Qs + BQ * QSTH;
    __half* Vs = Ks + 2 * KBUFH;
    const uint32_t qsb = s2u(Qs), ksb = s2u(Ks), vsb = s2u(Vs);

    const int qt = (T_SEQ / BQ - 1) - blockIdx.x;
    const int h = blockIdx.y, b = blockIdx.z;
    const int kvh = h >> 2;
    const int tid = threadIdx.x, lane = tid & 31, warp = tid >> 5;
    const int g = lane >> 2, tg = lane & 3;
    const int wr0 = warp * 16;
    const int qrow0 = b * T_SEQ + qt * BQ;
    const float scale = 0.08838834764831845f;
    const float c2 = scale * 1.4426950408889634f;

    const __half* Qg = QKV + (size_t)h * 128;
    const __half* Kg = QKV + QDIM + (size_t)kvh * 128;
    const __half* Vg = QKV + 2560 + (size_t)kvh * 128;

    const uint32_t q_lo = (uint32_t)(((wr0 + (lane & 15)) * QSTH + ((lane >> 4) << 3)) * 2);
    const uint32_t k_lo = (uint32_t)((((lane & 7) + ((lane >> 4) << 3)) * KSTH +
                                      (((lane >> 3) & 1) << 3)) * 2);
    const uint32_t v_lo = (uint32_t)(((((lane >> 3) & 1) * 8 + (lane & 7)) * VSTH +
                                      ((lane >> 4) << 3)) * 2);

    auto fill_kv = [&](int kt) {
        const int s = kt & 1;
        const int kr0 = b * T_SEQ + kt * BKV;
#pragma unroll
        for (int i = 0; i < 4; i++) {
            int ch = tid + i * 256;
            int r = ch >> 4, j = ch & 15;
            cpa16(ksb + (uint32_t)((s * KBUFH + r * KSTH) * 2 + j * 16),
                  Kg + (size_t)(kr0 + r) * QKVD + 8 * j);
            cpa16(vsb + (uint32_t)((s * VBUFH + r * VSTH) * 2 + j * 16),
                  Vg + (size_t)(kr0 + r) * QKVD + 8 * j);
        }
    };

#pragma unroll
    for (int i = 0; i < 8; i++) {
        int ch = tid + i * 256;
        int r = ch >> 4, j = ch & 15;
        cpa16(qsb + (uint32_t)((r * QSTH) * 2 + j * 16), Qg + (size_t)(qrow0 + r) * QKVD + 8 * j);
    }
    fill_kv(0);
    cpa_commit();

    float m_lo = -INFINITY, m_hi = -INFINITY, l_lo = 0.f, l_hi = 0.f;
    float o[16][4];
#pragma unroll
    for (int nt = 0; nt < 16; nt++)
#pragma unroll
        for (int r = 0; r < 4; r++) o[nt][r] = 0.f;

    const int kmax = 2 * qt + 1;
    for (int kt = 0; kt <= kmax; kt++) {
        cpa_wait<0>();
        __syncthreads();
        if (kt < kmax) { fill_kv(kt + 1); cpa_commit(); }

        const uint32_t kb = ksb + (uint32_t)((kt & 1) * KBUFH * 2);
        const uint32_t vb = vsb + (uint32_t)((kt & 1) * VBUFH * 2);

        float sc[8][4];
#pragma unroll
        for (int nt = 0; nt < 8; nt++)
#pragma unroll
            for (int r = 0; r < 4; r++) sc[nt][r] = 0.f;
#pragma unroll
        for (int kss = 0; kss < 8; kss++) {
            uint32_t a0, a1, a2, a3;
            ldsm4(a0, a1, a2, a3, qsb + q_lo + kss * 32);
#pragma unroll
            for (int ntp = 0; ntp < 4; ntp++) {
                uint32_t b0, b1, b2, b3;
                ldsm4(b0, b1, b2, b3,
                      kb + k_lo + (uint32_t)(ntp * 16 * KSTH * 2) + kss * 32);
                mma16(sc[2 * ntp],     a0, a1, a2, a3, b0, b1);
                mma16(sc[2 * ntp + 1], a0, a1, a2, a3, b2, b3);
            }
        }

        if (kt >= 2 * qt) {
            int lim_lo = qt * BQ + wr0 + g - kt * BKV;
            int lim_hi = lim_lo + 8;
#pragma unroll
            for (int nt = 0; nt < 8; nt++) {
                int cc = nt * 8 + 2 * tg;
                if (cc     > lim_lo) sc[nt][0] = -INFINITY;
                if (cc + 1 > lim_lo) sc[nt][1] = -INFINITY;
                if (cc     > lim_hi) sc[nt][2] = -INFINITY;
                if (cc + 1 > lim_hi) sc[nt][3] = -INFINITY;
            }
        }

        float mx_lo = -INFINITY, mx_hi = -INFINITY;
#pragma unroll
        for (int nt = 0; nt < 8; nt++) {
            mx_lo = fmaxf(mx_lo, fmaxf(sc[nt][0], sc[nt][1]));
            mx_hi = fmaxf(mx_hi, fmaxf(sc[nt][2], sc[nt][3]));
        }
        mx_lo = fmaxf(mx_lo, __shfl_xor_sync(0xffffffffu, mx_lo, 1));
        mx_lo = fmaxf(mx_lo, __shfl_xor_sync(0xffffffffu, mx_lo, 2));
        mx_hi = fmaxf(mx_hi, __shfl_xor_sync(0xffffffffu, mx_hi, 1));
        mx_hi = fmaxf(mx_hi, __shfl_xor_sync(0xffffffffu, mx_hi, 2));

        float mn_lo = fmaxf(m_lo, mx_lo), mn_hi = fmaxf(m_hi, mx_hi);
        float al_lo = __expf((m_lo - mn_lo) * scale);
        float al_hi = __expf((m_hi - mn_hi) * scale);
        float ls_lo = 0.f, ls_hi = 0.f;
        uint32_t plo[8], phi[8];
#pragma unroll
        for (int nt = 0; nt < 8; nt++) {
            plo[nt] = ex2h2((sc[nt][0] - mn_lo) * c2, (sc[nt][1] - mn_lo) * c2);
            phi[nt] = ex2h2((sc[nt][2] - mn_hi) * c2, (sc[nt][3] - mn_hi) * c2);
            float2 flo = __half22float2(*(__half2*)&plo[nt]);
            float2 fhi = __half22float2(*(__half2*)&phi[nt]);
            ls_lo += flo.x + flo.y;
            ls_hi += fhi.x + fhi.y;
        }
        ls_lo += __shfl_xor_sync(0xffffffffu, ls_lo, 1);
        ls_lo += __shfl_xor_sync(0xffffffffu, ls_lo, 2);
        ls_hi += __shfl_xor_sync(0xffffffffu, ls_hi, 1);
        ls_hi += __shfl_xor_sync(0xffffffffu, ls_hi, 2);
        l_lo = l_lo * al_lo + ls_lo;
        l_hi = l_hi * al_hi + ls_hi;
        m_lo = mn_lo; m_hi = mn_hi;

#pragma unroll
        for (int nt = 0; nt < 16; nt++) {
            o[nt][0] *= al_lo; o[nt][1] *= al_lo;
            o[nt][2] *= al_hi; o[nt][3] *= al_hi;
        }
#pragma unroll
        for (int kss = 0; kss < 4; kss++) {
            uint32_t a0 = plo[2 * kss],     a1 = phi[2 * kss];
            uint32_t a2 = plo[2 * kss + 1], a3 = phi[2 * kss + 1];
            const uint32_t vslab = vb + v_lo + (uint32_t)(kss * 16 * VSTH * 2);
#pragma unroll
            for (int ntp = 0; ntp < 8; ntp++) {
                uint32_t b0, b1, b2, b3;
                ldsm4t(b0, b1, b2, b3, vslab + ntp * 32);
                mma16(o[2 * ntp],     a0, a1, a2, a3, b0, b1);
                mma16(o[2 * ntp + 1], a0, a1, a2, a3, b2, b3);
            }
        }
    }

    float li = 1.f / l_lo, lh = 1.f / l_hi;
#pragma unroll
    for (int nt = 0; nt < 16; nt++) {
        int c = h * HEAD_DIM + nt * 8 + 2 * tg;
        *(__half2*)&O[(size_t)(qrow0 + wr0 + g) * QDIM + c] =
            __floats2half2_rn(o[nt][0] * li, o[nt][1] * li);
        *(__half2*)&O[(size_t)(qrow0 + wr0 + 8 + g) * QDIM + c] =
            __floats2half2_rn(o[nt][2] * lh, o[nt][3] * lh);
    }
}

// ---------------- launch ----------------
extern "C" void kernel_launch(void* const* d_in, const int* in_sizes, int n_in,
                              void* d_out, int out_size) {
    const float* x  = (const float*)d_in[0];
    const float* Wq = (const float*)d_in[1];
    const float* Wk = (const float*)d_in[2];
    const float* Wv = (const float*)d_in[3];
    const float* Wo = (const float*)d_in[4];
    float* out = (float*)d_out;

    __half *qkv, *att, *xh, *wc, *wo;
    cudaGetSymbolAddress((void**)&qkv, g_qkv);
    cudaGetSymbolAddress((void**)&att, g_att);
    cudaGetSymbolAddress((void**)&xh, g_xh);
    cudaGetSymbolAddress((void**)&wc, g_wc);
    cudaGetSymbolAddress((void**)&wo, g_wo);

    // fused prep: 8192 x-convert + 6144 concat + 4096 Wo + 512 table blocks
    prep_all<<<18944, 256>>>(x, Wq, Wk, Wv, Wo, xh, wc, wo);

    const int GSM = 3 * (ASTGH + BSTGH) * 2;   // 107520
    cudaFuncSetAttribute((const void*)gemm_h<__half, true>,
                         cudaFuncAttributeMaxDynamicSharedMemorySize, GSM);
    cudaFuncSetAttribute((const void*)gemm_h<float, false>,
                         cudaFuncAttributeMaxDynamicSharedMemorySize, GSM);

    // fused QKV projection with rope epilogue
    gemm_h<__half, true><<<dim3(QKVD / GBN, M_ROWS / GBM), 256, GSM>>>(xh, wc, qkv,
                                                                       M_ROWS, QKVD, D_MODEL);

    // attention
    {
        const int ASM_ = (BQ * QSTH + 2 * KBUFH + 2 * VBUFH) * 2;   // 104448
        cudaFuncSetAttribute(attn_h, cudaFuncAttributeMaxDynamicSharedMemorySize, ASM_);
        attn_h<<<dim3(T_SEQ / BQ, N_HEADS, B_SZ), 256, ASM_>>>(qkv, att);
    }

    // output projection
    gemm_h<float, false><<<dim3(D_MODEL / GBN, M_ROWS / GBM), 256, GSM>>>(att, wo, out,
                                                                          M_ROWS, D_MODEL, QDIM);
}

// round 14
// speedup vs baseline: 11.0263x; 1.0379x over previous
#include <cuda_runtime.h>
#include <cuda_fp16.h>
#include <math.h>
#include <stdint.h>

#define D_MODEL 2048
#define N_HEADS 16
#define N_KV 4
#define HEAD_DIM 128
#define B_SZ 2
#define T_SEQ 2048
#define M_ROWS (B_SZ * T_SEQ)          // 4096
#define QDIM (N_HEADS * HEAD_DIM)      // 2048
#define KVDIM (N_KV * HEAD_DIM)        // 512
#define QKVD (QDIM + 2 * KVDIM)        // 3072

// ---------------- scratch ----------------
__device__ __half g_qkv[M_ROWS * QKVD];
__device__ __half g_att[M_ROWS * QDIM];
__device__ __half g_xh[M_ROWS * D_MODEL];
__device__ __half g_wc[(size_t)D_MODEL * QKVD];    // concat weights [k][n] fp16
__device__ __half g_wo[(size_t)QDIM * D_MODEL];    // Wo [k][n] fp16
__device__ float2 g_tab[T_SEQ * 64];               // rope cos/sin table

// ---------------- helpers ----------------
__device__ __forceinline__ uint32_t s2u(const void* p) {
    uint32_t a;
    asm("{ .reg .u64 t; cvta.to.shared.u64 t, %1; cvt.u32.u64 %0, t; }" : "=r"(a) : "l"(p));
    return a;
}
__device__ __forceinline__ void cpa16(uint32_t dst, const void* src) {
    asm volatile("cp.async.cg.shared.global [%0], [%1], 16;" :: "r"(dst), "l"(src));
}
__device__ __forceinline__ void cpa_commit() { asm volatile("cp.async.commit_group;" ::: "memory"); }
template <int N> __device__ __forceinline__ void cpa_wait() {
    asm volatile("cp.async.wait_group %0;" :: "n"(N) : "memory");
}
__device__ __forceinline__ void ldsm4(uint32_t& r0, uint32_t& r1, uint32_t& r2, uint32_t& r3,
                                      uint32_t addr) {
    asm volatile("ldmatrix.sync.aligned.m8n8.x4.shared.b16 {%0,%1,%2,%3}, [%4];"
                 : "=r"(r0), "=r"(r1), "=r"(r2), "=r"(r3) : "r"(addr));
}
__device__ __forceinline__ void ldsm4t(uint32_t& r0, uint32_t& r1, uint32_t& r2, uint32_t& r3,
                                       uint32_t addr) {
    asm volatile("ldmatrix.sync.aligned.m8n8.x4.trans.shared.b16 {%0,%1,%2,%3}, [%4];"
                 : "=r"(r0), "=r"(r1), "=r"(r2), "=r"(r3) : "r"(addr));
}
__device__ __forceinline__ void mma16(float* c, uint32_t a0, uint32_t a1, uint32_t a2, uint32_t a3,
                                      uint32_t b0, uint32_t b1) {
    asm volatile(
        "mma.sync.aligned.m16n8k16.row.col.f32.f16.f16.f32 "
        "{%0,%1,%2,%3},{%4,%5,%6,%7},{%8,%9},{%0,%1,%2,%3};"
        : "+f"(c[0]), "+f"(c[1]), "+f"(c[2]), "+f"(c[3])
        : "r"(a0), "r"(a1), "r"(a2), "r"(a3), "r"(b0), "r"(b1));
}
__device__ __forceinline__ uint32_t ex2h2(float a, float b) {
    __half2 h = __floats2half2_rn(a, b);
    uint32_t r;
    asm("ex2.approx.f16x2 %0, %1;" : "=r"(r) : "r"(*(uint32_t*)&h));
    return r;
}

// ---------------- GEMM: A[m][k]h @ B[k][n]h, B frags via ldmatrix.trans ----------------
#define GBM 128
#define GBN 128
#define GBK 64
#define ASTH 72
#define BSTH 136
#define ASTGH (128 * ASTH)
#define BSTGH (64 * BSTH)

template <typename TO, bool ROPE>
__global__ __launch_bounds__(256, 2) void gemm_h(const __half* __restrict__ A,
                                                 const __half* __restrict__ B,
                                                 TO* __restrict__ C,
                                                 int M, int N, int K) {
    extern __shared__ __half smh[];
    const uint32_t asb = s2u(smh);
    const uint32_t bsb = asb + 3 * ASTGH * 2;

    const int tid = threadIdx.x;
    const int lane = tid & 31, warp = tid >> 5;
    const int wm = warp >> 2, wn = warp & 3;
    const int g = lane >> 2, tg = lane & 3;
    const int bm = blockIdx.y * GBM, bn = blockIdx.x * GBN;
    const int NK = K / GBK;

    uint32_t aoff[4];
#pragma unroll
    for (int mt = 0; mt < 4; mt++)
        aoff[mt] = (uint32_t)(((wm * 64 + mt * 16 + (lane & 15)) * ASTH + ((lane >> 4) << 3)) * 2);
    const uint32_t b_lo = (uint32_t)(((((lane >> 3) & 1) * 8 + (lane & 7)) * BSTH +
                                      ((lane >> 4) << 3)) * 2);

    float acc[4][4][4];
#pragma unroll
    for (int mt = 0; mt < 4; mt++)
#pragma unroll
        for (int nt = 0; nt < 4; nt++)
#pragma unroll
            for (int r = 0; r < 4; r++) acc[mt][nt][r] = 0.f;

    auto fill = [&](int kt) {
        const int s = kt - (kt / 3) * 3;
        const int k0 = kt * GBK;
#pragma unroll
        for (int i = 0; i < 4; i++) {
            int ch = tid + i * 256;
            int r = ch >> 3, j = ch & 7;
            cpa16(asb + (uint32_t)((s * ASTGH + r * ASTH) * 2 + j * 16),
                  A + (size_t)(bm + r) * K + k0 + 8 * j);
        }
#pragma unroll
        for (int i = 0; i < 4; i++) {
            int ch = tid + i * 256;
            int r = ch >> 4, j = ch & 15;
            cpa16(bsb + (uint32_t)((s * BSTGH + r * BSTH) * 2 + j * 16),
                  B + (size_t)(k0 + r) * N + bn + 8 * j);
        }
    };

    fill(0); cpa_commit();
    fill(1); cpa_commit();

    for (int kt = 0; kt < NK; kt++) {
        cpa_wait<1>();
        __syncthreads();
        if (kt + 2 < NK) fill(kt + 2);
        cpa_commit();

        const int s = kt - (kt / 3) * 3;
        const uint32_t ab = asb + (uint32_t)(s * ASTGH * 2);
        const uint32_t bb = bsb + (uint32_t)(s * BSTGH * 2);
#pragma unroll
        for (int ks = 0; ks < 4; ks++) {
            uint32_t af[4][4], bf[4][2];
#pragma unroll
            for (int mt = 0; mt < 4; mt++)
                ldsm4(af[mt][0], af[mt][1], af[mt][2], af[mt][3], ab + aoff[mt] + ks * 32);
            const uint32_t bslab = bb + b_lo + (uint32_t)(ks * 16 * BSTH * 2);
#pragma unroll
            for (int nl = 0; nl < 2; nl++) {
                int ntp = wn * 2 + nl;
                ldsm4t(bf[2 * nl][0], bf[2 * nl][1], bf[2 * nl + 1][0], bf[2 * nl + 1][1],
                       bslab + ntp * 32);
            }
#pragma unroll
            for (int mt = 0; mt < 4; mt++)
#pragma unroll
                for (int nt = 0; nt < 4; nt++)
                    mma16(acc[mt][nt], af[mt][0], af[mt][1], af[mt][2], af[mt][3], bf[nt][0], bf[nt][1]);
        }
    }

    if constexpr (ROPE) {
        cpa_wait<0>();
        __syncthreads();
        __half* Cs = smh;                       // 128 x 136
#pragma unroll
        for (int mt = 0; mt < 4; mt++)
#pragma unroll
            for (int nt = 0; nt < 4; nt++) {
                int r = wm * 64 + mt * 16 + g;
                int c = wn * 32 + nt * 8 + 2 * tg;
                *(__half2*)&Cs[r * 136 + c] = __floats2half2_rn(acc[mt][nt][0], acc[mt][nt][1]);
                *(__half2*)&Cs[(r + 8) * 136 + c] = __floats2half2_rn(acc[mt][nt][2], acc[mt][nt][3]);
            }
        __syncthreads();
        if (bn < 2560) {
            for (int it = tid; it < 128 * 32; it += 256) {
                int r = it >> 5;
                int i2 = (it & 31) * 2;
                int t = (bm + r) & (T_SEQ - 1);
                float2 cs0 = g_tab[t * 64 + i2];
                float2 cs1 = g_tab[t * 64 + i2 + 1];
                float2 f1 = __half22float2(*(__half2*)&Cs[r * 136 + i2]);
                float2 f2 = __half22float2(*(__half2*)&Cs[r * 136 + 64 + i2]);
                *(__half2*)&C[(size_t)(bm + r) * N + bn + i2] =
                    __floats2half2_rn(f1.x * cs0.x - f2.x * cs0.y, f1.y * cs1.x - f2.y * cs1.y);
                *(__half2*)&C[(size_t)(bm + r) * N + bn + 64 + i2] =
                    __floats2half2_rn(f2.x * cs0.x + f1.x * cs0.y, f2.y * cs1.x + f1.y * cs1.y);
            }
        } else {
            for (int it = tid; it < 128 * 64; it += 256) {
                int r = it >> 6;
                int c2 = (it & 63) * 2;
                *(__half2*)&C[(size_t)(bm + r) * N + bn + c2] = *(__half2*)&Cs[r * 136 + c2];
            }
        }
    } else {
#pragma unroll
        for (int mt = 0; mt < 4; mt++)
#pragma unroll
            for (int nt = 0; nt < 4; nt++) {
                int r = bm + wm * 64 + mt * 16 + g;
                int c = bn + wn * 32 + nt * 8 + 2 * tg;
                if constexpr (sizeof(TO) == 2) {
                    *(__half2*)&C[(size_t)r * N + c] =
                        __floats2half2_rn(acc[mt][nt][0], acc[mt][nt][1]);
                    *(__half2*)&C[(size_t)(r + 8) * N + c] =
                        __floats2half2_rn(acc[mt][nt][2], acc[mt][nt][3]);
                } else {
                    *(float2*)&C[(size_t)r * N + c] = make_float2(acc[mt][nt][0], acc[mt][nt][1]);
                    *(float2*)&C[(size_t)(r + 8) * N + c] = make_float2(acc[mt][nt][2], acc[mt][nt][3]);
                }
            }
    }
}

// ---------------- fused prep ----------------
__global__ void prep_all(const float* __restrict__ x, const float* __restrict__ Wq,
                         const float* __restrict__ Wk, const float* __restrict__ Wv,
                         const float* __restrict__ Wo, __half* __restrict__ xh,
                         __half* __restrict__ wc, __half* __restrict__ wo) {
    int bid = blockIdx.x;
    int tid = threadIdx.x;
    if (bid < 8192) {
        int i = bid * 256 + tid;
        float4 v = ((const float4*)x)[i];
        __half2 lo = __floats2half2_rn(v.x, v.y);
        __half2 hi = __floats2half2_rn(v.z, v.w);
        *(uint2*)&xh[i * 4] = make_uint2(*(uint32_t*)&lo, *(uint32_t*)&hi);
    } else if (bid < 14336) {
        int idx = (bid - 8192) * 256 + tid;
        const int n4row = QKVD / 4;
        int k = idx / n4row;
        int n = (idx - k * n4row) * 4;
        const float* src;
        int c;
        if (n < QDIM)      { src = Wq + (size_t)k * QDIM;  c = n; }
        else if (n < 2560) { src = Wk + (size_t)k * KVDIM; c = n - QDIM; }
        else               { src = Wv + (size_t)k * KVDIM; c = n - 2560; }
        float4 v = *(const float4*)(src + c);
        __half2 lo = __floats2half2_rn(v.x, v.y);
        __half2 hi = __floats2half2_rn(v.z, v.w);
        *(uint2*)&wc[(size_t)k * QKVD + n] = make_uint2(*(uint32_t*)&lo, *(uint32_t*)&hi);
    } else if (bid < 18432) {
        int i = (bid - 14336) * 256 + tid;
        float4 v = ((const float4*)Wo)[i];
        __half2 lo = __floats2half2_rn(v.x, v.y);
        __half2 hi = __floats2half2_rn(v.z, v.w);
        *(uint2*)&wo[i * 4] = make_uint2(*(uint32_t*)&lo, *(uint32_t*)&hi);
    } else {
        int gid = (bid - 18432) * 256 + tid;
        int i = gid & 63;
        int tt = gid >> 6;
        float inv = powf(10000.0f, -((float)(2 * i)) / 128.0f);
        float ang = (float)tt * inv;
        float s, c;
        sincosf(ang, &s, &c);
        g_tab[gid] = make_float2(c, s);
    }
}

// ---------------- flash attention: 4 warps x 32 rows, Bc=64, K+V double buffered ----------------
#define BQ 128
#define BKV 64
#define QSTH 136
#define KSTH 136
#define VSTH 136
#define KBUFH (BKV * KSTH)
#define VBUFH (BKV * VSTH)
#define ATHREADS 128

__global__ __launch_bounds__(ATHREADS, 2) void attn_h(const __half* __restrict__ QKV,
                                                      __half* __restrict__ O) {
    extern __shared__ __half smh[];
    __half* Qs = smh;
    __half* Ks = Qs + BQ * QSTH;
    __half* Vs = Ks + 2 * KBUFH;
    const uint32_t qsb = s2u(Qs), ksb = s2u(Ks), vsb = s2u(Vs);

    const int qt = (T_SEQ / BQ - 1) - blockIdx.x;
    const int h = blockIdx.y, b = blockIdx.z;
    const int kvh = h >> 2;
    const int tid = threadIdx.x, lane = tid & 31, warp = tid >> 5;
    const int g = lane >> 2, tg = lane & 3;
    const int wr0 = warp * 32;                      // warp owns 32 rows
    const int qrow0 = b * T_SEQ + qt * BQ;
    const float scale = 0.08838834764831845f;
    const float c2 = scale * 1.4426950408889634f;

    const __half* Qg = QKV + (size_t)h * 128;
    const __half* Kg = QKV + QDIM + (size_t)kvh * 128;
    const __half* Vg = QKV + 2560 + (size_t)kvh * 128;

    uint32_t q_lo[2];
#pragma unroll
    for (int mt = 0; mt < 2; mt++)
        q_lo[mt] = (uint32_t)(((wr0 + mt * 16 + (lane & 15)) * QSTH + ((lane >> 4) << 3)) * 2);
    const uint32_t k_lo = (uint32_t)((((lane & 7) + ((lane >> 4) << 3)) * KSTH +
                                      (((lane >> 3) & 1) << 3)) * 2);
    const uint32_t v_lo = (uint32_t)(((((lane >> 3) & 1) * 8 + (lane & 7)) * VSTH +
                                      ((lane >> 4) << 3)) * 2);

    auto fill_kv = [&](int kt) {
        const int s = kt & 1;
        const int kr0 = b * T_SEQ + kt * BKV;
#pragma unroll
        for (int i = 0; i < 8; i++) {               // 64 rows x 16 chunks, 128 threads
            int ch = tid + i * ATHREADS;
            int r = ch >> 4, j = ch & 15;
            cpa16(ksb + (uint32_t)((s * KBUFH + r * KSTH) * 2 + j * 16),
                  Kg + (size_t)(kr0 + r) * QKVD + 8 * j);
            cpa16(vsb + (uint32_t)((s * VBUFH + r * VSTH) * 2 + j * 16),
                  Vg + (size_t)(kr0 + r) * QKVD + 8 * j);
        }
    };

#pragma unroll
    for (int i = 0; i < 16; i++) {                  // Q: 128 rows x 16 chunks
        int ch = tid + i * ATHREADS;
        int r = ch >> 4, j = ch & 15;
        cpa16(qsb + (uint32_t)((r * QSTH) * 2 + j * 16), Qg + (size_t)(qrow0 + r) * QKVD + 8 * j);
    }
    fill_kv(0);
    cpa_commit();

    float m_[2][2], l_[2][2];
#pragma unroll
    for (int mt = 0; mt < 2; mt++) {
        m_[mt][0] = -INFINITY; m_[mt][1] = -INFINITY;
        l_[mt][0] = 0.f; l_[mt][1] = 0.f;
    }
    float o[2][16][4];
#pragma unroll
    for (int mt = 0; mt < 2; mt++)
#pragma unroll
        for (int nt = 0; nt < 16; nt++)
#pragma unroll
            for (int r = 0; r < 4; r++) o[mt][nt][r] = 0.f;

    const int kmax = 2 * qt + 1;
    for (int kt = 0; kt <= kmax; kt++) {
        cpa_wait<0>();
        __syncthreads();
        if (kt < kmax) { fill_kv(kt + 1); cpa_commit(); }

        const uint32_t kb = ksb + (uint32_t)((kt & 1) * KBUFH * 2);
        const uint32_t vb = vsb + (uint32_t)((kt & 1) * VBUFH * 2);

        // S = Q K^T : warp tile 32x64
        float sc[2][8][4];
#pragma unroll
        for (int mt = 0; mt < 2; mt++)
#pragma unroll
            for (int nt = 0; nt < 8; nt++)
#pragma unroll
                for (int r = 0; r < 4; r++) sc[mt][nt][r] = 0.f;
#pragma unroll
        for (int kss = 0; kss < 8; kss++) {
            uint32_t a[2][4];
#pragma unroll
            for (int mt = 0; mt < 2; mt++)
                ldsm4(a[mt][0], a[mt][1], a[mt][2], a[mt][3], qsb + q_lo[mt] + kss * 32);
#pragma unroll
            for (int ntp = 0; ntp < 4; ntp++) {
                uint32_t b0, b1, b2, b3;
                ldsm4(b0, b1, b2, b3,
                      kb + k_lo + (uint32_t)(ntp * 16 * KSTH * 2) + kss * 32);
#pragma unroll
                for (int mt = 0; mt < 2; mt++) {
                    mma16(sc[mt][2 * ntp],     a[mt][0], a[mt][1], a[mt][2], a[mt][3], b0, b1);
                    mma16(sc[mt][2 * ntp + 1], a[mt][0], a[mt][1], a[mt][2], a[mt][3], b2, b3);
                }
            }
        }

        // causal mask (last two kt tiles are partial)
        if (kt >= 2 * qt) {
#pragma unroll
            for (int mt = 0; mt < 2; mt++) {
                int lim_lo = qt * BQ + wr0 + mt * 16 + g - kt * BKV;
                int lim_hi = lim_lo + 8;
#pragma unroll
                for (int nt = 0; nt < 8; nt++) {
                    int cc = nt * 8 + 2 * tg;
                    if (cc     > lim_lo) sc[mt][nt][0] = -INFINITY;
                    if (cc + 1 > lim_lo) sc[mt][nt][1] = -INFINITY;
                    if (cc     > lim_hi) sc[mt][nt][2] = -INFINITY;
                    if (cc + 1 > lim_hi) sc[mt][nt][3] = -INFINITY;
                }
            }
        }

        // register softmax per 16-row sub-tile
        uint32_t plo[2][8], phi[2][8];
        float al[2][2];
#pragma unroll
        for (int mt = 0; mt < 2; mt++) {
            float mx_lo = -INFINITY, mx_hi = -INFINITY;
#pragma unroll
            for (int nt = 0; nt < 8; nt++) {
                mx_lo = fmaxf(mx_lo, fmaxf(sc[mt][nt][0], sc[mt][nt][1]));
                mx_hi = fmaxf(mx_hi, fmaxf(sc[mt][nt][2], sc[mt][nt][3]));
            }
            mx_lo = fmaxf(mx_lo, __shfl_xor_sync(0xffffffffu, mx_lo, 1));
            mx_lo = fmaxf(mx_lo, __shfl_xor_sync(0xffffffffu, mx_lo, 2));
            mx_hi = fmaxf(mx_hi, __shfl_xor_sync(0xffffffffu, mx_hi, 1));
            mx_hi = fmaxf(mx_hi, __shfl_xor_sync(0xffffffffu, mx_hi, 2));

            float mn_lo = fmaxf(m_[mt][0], mx_lo), mn_hi = fmaxf(m_[mt][1], mx_hi);
            al[mt][0] = __expf((m_[mt][0] - mn_lo) * scale);
            al[mt][1] = __expf((m_[mt][1] - mn_hi) * scale);
            float ls_lo = 0.f, ls_hi = 0.f;
#pragma unroll
            for (int nt = 0; nt < 8; nt++) {
                plo[mt][nt] = ex2h2((sc[mt][nt][0] - mn_lo) * c2, (sc[mt][nt][1] - mn_lo) * c2);
                phi[mt][nt] = ex2h2((sc[mt][nt][2] - mn_hi) * c2, (sc[mt][nt][3] - mn_hi) * c2);
                float2 flo = __half22float2(*(__half2*)&plo[mt][nt]);
                float2 fhi = __half22float2(*(__half2*)&phi[mt][nt]);
                ls_lo += flo.x + flo.y;
                ls_hi += fhi.x + fhi.y;
            }
            ls_lo += __shfl_xor_sync(0xffffffffu, ls_lo, 1);
            ls_lo += __shfl_xor_sync(0xffffffffu, ls_lo, 2);
            ls_hi += __shfl_xor_sync(0xffffffffu, ls_hi, 1);
            ls_hi += __shfl_xor_sync(0xffffffffu, ls_hi, 2);
            l_[mt][0] = l_[mt][0] * al[mt][0] + ls_lo;
            l_[mt][1] = l_[mt][1] * al[mt][1] + ls_hi;
            m_[mt][0] = mn_lo; m_[mt][1] = mn_hi;
        }

        // O = O*alpha + P @ V : V fragments shared across both sub-tiles
#pragma unroll
        for (int mt = 0; mt < 2; mt++)
#pragma unroll
            for (int nt = 0; nt < 16; nt++) {
                o[mt][nt][0] *= al[mt][0]; o[mt][nt][1] *= al[mt][0];
                o[mt][nt][2] *= al[mt][1]; o[mt][nt][3] *= al[mt][1];
            }
#pragma unroll
        for (int kss = 0; kss < 4; kss++) {
            const uint32_t vslab = vb + v_lo + (uint32_t)(kss * 16 * VSTH * 2);
#pragma unroll
            for (int ntp = 0; ntp < 8; ntp++) {
                uint32_t b0, b1, b2, b3;
                ldsm4t(b0, b1, b2, b3, vslab + ntp * 32);
#pragma unroll
                for (int mt = 0; mt < 2; mt++) {
                    uint32_t a0 = plo[mt][2 * kss],     a1 = phi[mt][2 * kss];
                    uint32_t a2 = plo[mt][2 * kss + 1], a3 = phi[mt][2 * kss + 1];
                    mma16(o[mt][2 * ntp],     a0, a1, a2, a3, b0, b1);
                    mma16(o[mt][2 * ntp + 1], a0, a1, a2, a3, b2, b3);
                }
            }
        }
    }

    // epilogue
#pragma unroll
    for (int mt = 0; mt < 2; mt++) {
        float li = 1.f / l_[mt][0], lh = 1.f / l_[mt][1];
#pragma unroll
        for (int nt = 0; nt < 16; nt++) {
            int c = h * HEAD_DIM + nt * 8 + 2 * tg;
            int r = qrow0 + wr0 + mt * 16 + g;
            *(__half2*)&O[(size_t)r * QDIM + c] =
                __floats2half2_rn(o[mt][nt][0] * li, o[mt][nt][1] * li);
            *(__half2*)&O[(size_t)(r + 8) * QDIM + c] =
                __floats2half2_rn(o[mt][nt][2] * lh, o[mt][nt][3] * lh);
        }
    }
}

// ---------------- launch ----------------
extern "C" void kernel_launch(void* const* d_in, const int* in_sizes, int n_in,
                              void* d_out, int out_size) {
    const float* x  = (const float*)d_in[0];
    const float* Wq = (const float*)d_in[1];
    const float* Wk = (const float*)d_in[2];
    const float* Wv = (const float*)d_in[3];
    const float* Wo = (const float*)d_in[4];
    float* out = (float*)d_out;

    __half *qkv, *att, *xh, *wc, *wo;
    cudaGetSymbolAddress((void**)&qkv, g_qkv);
    cudaGetSymbolAddress((void**)&att, g_att);
    cudaGetSymbolAddress((void**)&xh, g_xh);
    cudaGetSymbolAddress((void**)&wc, g_wc);
    cudaGetSymbolAddress((void**)&wo, g_wo);

    prep_all<<<18944, 256>>>(x, Wq, Wk, Wv, Wo, xh, wc, wo);

    const int GSM = 3 * (ASTGH + BSTGH) * 2;   // 107520
    cudaFuncSetAttribute((const void*)gemm_h<__half, true>,
                         cudaFuncAttributeMaxDynamicSharedMemorySize, GSM);
    cudaFuncSetAttribute((const void*)gemm_h<float, false>,
                         cudaFuncAttributeMaxDynamicSharedMemorySize, GSM);

    gemm_h<__half, true><<<dim3(QKVD / GBN, M_ROWS / GBM), 256, GSM>>>(xh, wc, qkv,
                                                                       M_ROWS, QKVD, D_MODEL);

    {
        const int ASM_ = (BQ * QSTH + 2 * KBUFH + 2 * VBUFH) * 2;   // 104448
        cudaFuncSetAttribute(attn_h, cudaFuncAttributeMaxDynamicSharedMemorySize, ASM_);
        attn_h<<<dim3(T_SEQ / BQ, N_HEADS, B_SZ), ATHREADS, ASM_>>>(qkv, att);
    }

    gemm_h<float, false><<<dim3(D_MODEL / GBN, M_ROWS / GBM), 256, GSM>>>(att, wo, out,
                                                                          M_ROWS, D_MODEL, QDIM);
}